// round 2
// baseline (speedup 1.0000x reference)
#include <cuda_runtime.h>
#include <cuda_bf16.h>
#include <cstdint>

// Problem constants
#define L_   12
#define NH_  16
#define H_   1024
#define FF_  4096
#define V_   32000
#define S_   1024
#define E_   128
#define B_   4
#define HEAD_ 64
#define M4   (B_ * S_)   // 4096 rows total

// ---------------------------------------------------------------------------
// Scratch (device globals — allocation-free per harness rules)
// ---------------------------------------------------------------------------
__device__ float g_Aemb   [M4 * E_];        // gathered embeddings
__device__ float g_xemb   [M4 * H_];        // x_dec_embed
__device__ float g_layerin[M4 * H_];        // layer_in (m = 11)
__device__ float g_q      [M4 * H_];
__device__ float g_k      [M4 * H_];
__device__ float g_v      [M4 * H_];
__device__ float g_conc   [M4 * H_];
__device__ float g_xmulti [M4 * H_];
__device__ float g_xself  [M4 * H_];
__device__ float g_ffw1   [M4 * FF_];
__device__ float g_ffw2   [M4 * H_];
__device__ float g_xffw   [M4 * H_];
__device__ float g_decout [M4 * H_];

// ---------------------------------------------------------------------------
// SGEMM: C[M,N] = alpha * (A[M,K] @ B[K,N]) + bias[N] (opt), relu (opt)
// All row-major fp32. M%128==0, N%128==0, K%8==0 (true for all calls here).
// 128x128 block tile, 8x8 per-thread micro-tile, 256 threads.
// ---------------------------------------------------------------------------
#define BM 128
#define BN 128
#define BKT 8
#define TM 8
#define TN 8

__global__ __launch_bounds__(256) void sgemm_kernel(
    const float* __restrict__ A, const float* __restrict__ Bm,
    const float* __restrict__ bias, float* __restrict__ C,
    int M, int N, int K, float alpha, int do_relu)
{
    __shared__ float As[BKT][BM];
    __shared__ float Bs[BKT][BN];

    const int tid = threadIdx.x;
    const int bx = blockIdx.x;   // N tile
    const int by = blockIdx.y;   // M tile

    const float* Ab = A + (size_t)by * BM * K;
    const float* Bb = Bm + (size_t)bx * BN;

    const int aRow = tid >> 1;            // 0..127
    const int aCol = (tid & 1) * 4;       // 0 or 4
    const int bRow = tid >> 5;            // 0..7
    const int bCol = (tid & 31) * 4;      // 0..124

    const int tx = tid & 15;              // col group
    const int ty = tid >> 4;              // row group

    float acc[TM][TN];
    #pragma unroll
    for (int i = 0; i < TM; i++)
        #pragma unroll
        for (int j = 0; j < TN; j++) acc[i][j] = 0.f;

    for (int k0 = 0; k0 < K; k0 += BKT) {
        float4 a4 = *reinterpret_cast<const float4*>(Ab + (size_t)aRow * K + k0 + aCol);
        As[aCol + 0][aRow] = a4.x;
        As[aCol + 1][aRow] = a4.y;
        As[aCol + 2][aRow] = a4.z;
        As[aCol + 3][aRow] = a4.w;
        *reinterpret_cast<float4*>(&Bs[bRow][bCol]) =
            *reinterpret_cast<const float4*>(Bb + (size_t)(k0 + bRow) * N + bCol);
        __syncthreads();

        #pragma unroll
        for (int k = 0; k < BKT; k++) {
            float ra[TM], rb[TN];
            #pragma unroll
            for (int i = 0; i < TM; i++) ra[i] = As[k][ty * TM + i];
            #pragma unroll
            for (int j = 0; j < TN; j++) rb[j] = Bs[k][tx * TN + j];
            #pragma unroll
            for (int i = 0; i < TM; i++)
                #pragma unroll
                for (int j = 0; j < TN; j++)
                    acc[i][j] += ra[i] * rb[j];
        }
        __syncthreads();
    }

    float* Cb = C + (size_t)(by * BM) * N + (size_t)bx * BN;
    #pragma unroll
    for (int i = 0; i < TM; i++) {
        const int row = ty * TM + i;
        #pragma unroll
        for (int j = 0; j < TN; j += 4) {
            float4 o;
            float* op = &o.x;
            #pragma unroll
            for (int q = 0; q < 4; q++) {
                const int col = tx * TN + j + q;
                float v = acc[i][j + q] * alpha;
                if (bias) v += bias[(size_t)bx * BN + col];
                if (do_relu) v = fmaxf(v, 0.f);
                op[q] = v;
            }
            *reinterpret_cast<float4*>(Cb + (size_t)row * N + tx * TN + j) = o;
        }
    }
}

// ---------------------------------------------------------------------------
// Embedding gather: A_emb[i, e] = emb_decode[x[i], e]
// ---------------------------------------------------------------------------
__global__ void gather_kernel(const int* __restrict__ x,
                              const float* __restrict__ emb,
                              float* __restrict__ out)
{
    int idx = blockIdx.x * blockDim.x + threadIdx.x;   // over M4*E_
    if (idx >= M4 * E_) return;
    int i = idx / E_;
    int e = idx - i * E_;
    out[idx] = emb[(size_t)x[i] * E_ + e];
}

// ---------------------------------------------------------------------------
// layer_in[b*S+s, h] = x_emb_pos_dec[11, s, h] + x_dec_embed[b*S+s, h]
// ---------------------------------------------------------------------------
__global__ void addpos_kernel(const float* __restrict__ xemb,
                              const float* __restrict__ pos11,
                              float* __restrict__ out)
{
    int idx = blockIdx.x * blockDim.x + threadIdx.x;   // over M4*H_
    if (idx >= M4 * H_) return;
    int i = idx / H_;
    int h = idx - i * H_;
    int s = i & (S_ - 1);
    out[idx] = xemb[idx] + pos11[(size_t)s * H_ + h];
}

// ---------------------------------------------------------------------------
// out = res + layer_norm(x) * scale + bias    (one block per row, H=1024)
// ---------------------------------------------------------------------------
__global__ __launch_bounds__(256) void ln_res_kernel(
    const float* __restrict__ res, const float* __restrict__ x,
    const float* __restrict__ bias, const float* __restrict__ scale,
    float* __restrict__ out)
{
    __shared__ float red[256];
    const int row = blockIdx.x;
    const int t = threadIdx.x;
    const float* xr = x + (size_t)row * H_;

    float lsum = 0.f;
    for (int i = t; i < H_; i += 256) lsum += xr[i];
    red[t] = lsum; __syncthreads();
    for (int s = 128; s > 0; s >>= 1) { if (t < s) red[t] += red[t + s]; __syncthreads(); }
    const float mean = red[0] * (1.0f / H_);
    __syncthreads();

    float lvar = 0.f;
    for (int i = t; i < H_; i += 256) { float d = xr[i] - mean; lvar += d * d; }
    red[t] = lvar; __syncthreads();
    for (int s = 128; s > 0; s >>= 1) { if (t < s) red[t] += red[t + s]; __syncthreads(); }
    const float rstd = rsqrtf(red[0] * (1.0f / H_) + 1e-6f);

    for (int i = t; i < H_; i += 256) {
        out[(size_t)row * H_ + i] =
            res[(size_t)row * H_ + i] + (xr[i] - mean) * rstd * scale[i] + bias[i];
    }
}

// ---------------------------------------------------------------------------
// Causal flash attention, fp32. Heads interleaved in [B*S, H] layout.
// Block: 64 threads; each thread owns one q row of a 64-row tile.
// grid = (S/64, B*NH). K/V smem reads are warp-broadcast (same j,d per step).
// Scores staged in padded smem for a numerically-stable two-pass softmax.
// Output includes the heads-combined layout directly (conc).
// ---------------------------------------------------------------------------
__global__ __launch_bounds__(64) void attn_kernel(
    const float* __restrict__ Q, const float* __restrict__ Kb,
    const float* __restrict__ Vb, float* __restrict__ O)
{
    __shared__ float Ks[64 * 64];
    __shared__ float Vs[64 * 64];
    __shared__ float Ss[64 * 65];   // padded: bank-conflict-free score rows

    const int qt = blockIdx.x;           // q tile 0..15
    const int bh = blockIdx.y;           // 0..63
    const int b  = bh >> 4;
    const int n  = bh & 15;
    const int t  = threadIdx.x;          // q row within tile
    const int qrow = qt * 64 + t;

    const float* qptr = Q + ((size_t)(b * S_ + qrow)) * H_ + n * HEAD_;
    float qreg[HEAD_];
    #pragma unroll
    for (int d = 0; d < HEAD_; d++) qreg[d] = qptr[d];

    float accv[HEAD_];
    #pragma unroll
    for (int d = 0; d < HEAD_; d++) accv[d] = 0.f;
    float mval = -1e30f, lval = 0.f;

    for (int kt = 0; kt <= qt; kt++) {
        const float* kptr = Kb + ((size_t)(b * S_ + kt * 64 + t)) * H_ + n * HEAD_;
        const float* vptr = Vb + ((size_t)(b * S_ + kt * 64 + t)) * H_ + n * HEAD_;
        #pragma unroll
        for (int d = 0; d < HEAD_; d += 4) {
            *reinterpret_cast<float4*>(&Ks[t * 64 + d]) =
                *reinterpret_cast<const float4*>(kptr + d);
            *reinterpret_cast<float4*>(&Vs[t * 64 + d]) =
                *reinterpret_cast<const float4*>(vptr + d);
        }
        __syncthreads();

        const int jmax = (kt == qt) ? (t + 1) : 64;

        // pass 1: scores + tile max
        float tmax = -1e30f;
        for (int j = 0; j < jmax; j++) {
            float s = 0.f;
            #pragma unroll
            for (int d = 0; d < HEAD_; d++) s += qreg[d] * Ks[j * 64 + d];
            Ss[t * 65 + j] = s;
            tmax = fmaxf(tmax, s);
        }

        const float mnew = fmaxf(mval, tmax);
        const float corr = __expf(mval - mnew);
        lval *= corr;
        #pragma unroll
        for (int d = 0; d < HEAD_; d++) accv[d] *= corr;

        // pass 2: exp + P@V
        for (int j = 0; j < jmax; j++) {
            const float p = __expf(Ss[t * 65 + j] - mnew);
            lval += p;
            #pragma unroll
            for (int d = 0; d < HEAD_; d++) accv[d] += p * Vs[j * 64 + d];
        }
        mval = mnew;
        __syncthreads();
    }

    const float inv = 1.f / lval;
    float* optr = O + ((size_t)(b * S_ + qrow)) * H_ + n * HEAD_;
    #pragma unroll
    for (int d = 0; d < HEAD_; d += 4) {
        float4 o;
        o.x = accv[d + 0] * inv;
        o.y = accv[d + 1] * inv;
        o.z = accv[d + 2] * inv;
        o.w = accv[d + 3] * inv;
        *reinterpret_cast<float4*>(optr + d) = o;
    }
}

// ---------------------------------------------------------------------------
// Launch
// ---------------------------------------------------------------------------
static inline void run_sgemm(const float* A, const float* B, const float* bias,
                             float* C, int M, int N, int K, float alpha, int relu)
{
    dim3 grid(N / BN, M / BM);
    sgemm_kernel<<<grid, 256>>>(A, B, bias, C, M, N, K, alpha, relu);
}

extern "C" void kernel_launch(void* const* d_in, const int* in_sizes, int n_in,
                              void* d_out, int out_size)
{
    const int*   x            = (const int*)  d_in[0];
    const float* emb_decode   = (const float*)d_in[1];
    const float* W_dec_lin    = (const float*)d_in[2];
    const float* p_decoder    = (const float*)d_in[3];
    const float* x_emb_pos    = (const float*)d_in[4];
    const float* p_d_q        = (const float*)d_in[5];
    const float* p_d_k        = (const float*)d_in[6];
    const float* p_d_v        = (const float*)d_in[7];
    const float* p_d_c        = (const float*)d_in[8];
    const float* p_d_ff1      = (const float*)d_in[9];
    const float* p_d_ff2      = (const float*)d_in[10];
    const float* b_d_ff1      = (const float*)d_in[11];
    const float* b_d_ff2      = (const float*)d_in[12];
    const float* d_o_bias     = (const float*)d_in[13];
    const float* d_o_scale    = (const float*)d_in[14];
    const float* b_d_bias_1   = (const float*)d_in[15];
    const float* b_d_bias_2   = (const float*)d_in[16];
    const float* b_d_scale_1  = (const float*)d_in[17];
    const float* b_d_scale_2  = (const float*)d_in[18];
    float* out = (float*)d_out;

    const int m = L_ - 1;   // only the last layer's result is observable

    float *Aemb, *xemb, *layerin, *q, *k, *v, *conc, *xmulti, *xself,
          *ffw1, *ffw2, *xffw, *decout;
    cudaGetSymbolAddress((void**)&Aemb,    g_Aemb);
    cudaGetSymbolAddress((void**)&xemb,    g_xemb);
    cudaGetSymbolAddress((void**)&layerin, g_layerin);
    cudaGetSymbolAddress((void**)&q,       g_q);
    cudaGetSymbolAddress((void**)&k,       g_k);
    cudaGetSymbolAddress((void**)&v,       g_v);
    cudaGetSymbolAddress((void**)&conc,    g_conc);
    cudaGetSymbolAddress((void**)&xmulti,  g_xmulti);
    cudaGetSymbolAddress((void**)&xself,   g_xself);
    cudaGetSymbolAddress((void**)&ffw1,    g_ffw1);
    cudaGetSymbolAddress((void**)&ffw2,    g_ffw2);
    cudaGetSymbolAddress((void**)&xffw,    g_xffw);
    cudaGetSymbolAddress((void**)&decout,  g_decout);

    const float inv_sqrt_head = 0.125f;   // 1/sqrt(64)

    // 1. gather embeddings
    gather_kernel<<<(M4 * E_ + 255) / 256, 256>>>(x, emb_decode, Aemb);

    // 2. x_dec_embed = A_emb @ W_dec_lin
    run_sgemm(Aemb, W_dec_lin, nullptr, xemb, M4, H_, E_, 1.f, 0);

    // 3. layer_in = pos[11] + x_dec_embed
    addpos_kernel<<<(M4 * H_ + 255) / 256, 256>>>(
        xemb, x_emb_pos + (size_t)m * S_ * H_, layerin);

    // 4. Q/K/V projections (Q pre-scaled by 1/sqrt(head))
    run_sgemm(layerin, p_d_q + (size_t)m * H_ * H_, nullptr, q, M4, H_, H_, inv_sqrt_head, 0);
    run_sgemm(layerin, p_d_k + (size_t)m * H_ * H_, nullptr, k, M4, H_, H_, 1.f, 0);
    run_sgemm(layerin, p_d_v + (size_t)m * H_ * H_, nullptr, v, M4, H_, H_, 1.f, 0);

    // 5. causal attention -> conc (heads combined in-layout)
    attn_kernel<<<dim3(S_ / 64, B_ * NH_), 64>>>(q, k, v, conc);

    // 6. x_multi = conc @ p_d_c
    run_sgemm(conc, p_d_c + (size_t)m * H_ * H_, nullptr, xmulti, M4, H_, H_, 1.f, 0);

    // 7. x_self = layer_in + LN(x_multi)
    ln_res_kernel<<<M4, 256>>>(layerin, xmulti,
                               b_d_bias_1 + (size_t)m * H_,
                               b_d_scale_1 + (size_t)m * H_, xself);

    // 8. FFN
    run_sgemm(xself, p_d_ff1 + (size_t)m * H_ * FF_,
              b_d_ff1 + (size_t)m * FF_, ffw1, M4, FF_, H_, 1.f, 1);
    run_sgemm(ffw1, p_d_ff2 + (size_t)m * FF_ * H_,
              b_d_ff2 + (size_t)m * H_, ffw2, M4, H_, FF_, 1.f, 0);

    // 9. x_ffw = x_self + LN(ffw2)
    ln_res_kernel<<<M4, 256>>>(xself, ffw2,
                               b_d_bias_2 + (size_t)m * H_,
                               b_d_scale_2 + (size_t)m * H_, xffw);

    // 10. dec_outputs = x_dec_embed + LN(x_ffw)
    ln_res_kernel<<<M4, 256>>>(xemb, xffw, d_o_bias, d_o_scale, decout);

    // 11. logits = dec_outputs @ p_decoder   (dominant GEMM: 268 GFLOP)
    run_sgemm(decout, p_decoder, nullptr, out, M4, V_, H_, 1.f, 0);
}

// round 5
// speedup vs baseline: 1.6116x; 1.6116x over previous
#include <cuda_runtime.h>
#include <cuda_bf16.h>
#include <cstdint>

// Problem constants
#define L_   12
#define NH_  16
#define H_   1024
#define FF_  4096
#define V_   32000
#define S_   1024
#define E_   128
#define B_   4
#define HEAD_ 64
#define M4   (B_ * S_)   // 4096 rows total

// ---------------------------------------------------------------------------
// Scratch (device globals — allocation-free per harness rules)
// ---------------------------------------------------------------------------
__device__ float g_Aemb   [M4 * E_];
__device__ float g_xemb   [M4 * H_];
__device__ float g_layerin[M4 * H_];
__device__ float g_q      [M4 * H_];
__device__ float g_k      [M4 * H_];
__device__ float g_v      [M4 * H_];
__device__ float g_conc   [M4 * H_];
__device__ float g_xmulti [M4 * H_];
__device__ float g_xself  [M4 * H_];
__device__ float g_ffw1   [M4 * FF_];
__device__ float g_ffw2   [M4 * H_];
__device__ float g_xffw   [M4 * H_];
__device__ float g_decout [M4 * H_];

// bf16 split-K3 operand buffers.  A' = [hi | lo | hi] (row-major, 3K cols),
// B' = [hi | hi | lo] as [N, 3K] (k-contiguous, i.e. transposed weight).
__device__ __align__(128) __nv_bfloat16 g_a3_emb [M4 * 3 * E_];
__device__ __align__(128) __nv_bfloat16 g_a3_li  [M4 * 3 * H_];
__device__ __align__(128) __nv_bfloat16 g_a3_conc[M4 * 3 * H_];
__device__ __align__(128) __nv_bfloat16 g_a3_self[M4 * 3 * H_];
__device__ __align__(128) __nv_bfloat16 g_a3_ffw1[(size_t)M4 * 3 * FF_];
__device__ __align__(128) __nv_bfloat16 g_a3_dec [M4 * 3 * H_];

__device__ __align__(128) __nv_bfloat16 g_w3_dec [H_ * 3 * E_];
__device__ __align__(128) __nv_bfloat16 g_w3_q   [H_ * 3 * H_];
__device__ __align__(128) __nv_bfloat16 g_w3_k   [H_ * 3 * H_];
__device__ __align__(128) __nv_bfloat16 g_w3_v   [H_ * 3 * H_];
__device__ __align__(128) __nv_bfloat16 g_w3_c   [H_ * 3 * H_];
__device__ __align__(128) __nv_bfloat16 g_w3_ff1 [(size_t)FF_ * 3 * H_];
__device__ __align__(128) __nv_bfloat16 g_w3_ff2 [(size_t)H_ * 3 * FF_];
__device__ __align__(128) __nv_bfloat16 g_w3_pdec[(size_t)V_ * 3 * H_];

// ---------------------------------------------------------------------------
// PTX helpers (all legal on baseline sm_103 / compute_103 target)
// ---------------------------------------------------------------------------
__device__ __forceinline__ uint32_t smem_u32(const void* p) {
    uint32_t a;
    asm("{ .reg .u64 t; cvta.to.shared.u64 t, %1; cvt.u32.u64 %0, t; }"
        : "=r"(a) : "l"(p));
    return a;
}
__device__ __forceinline__ void cp16(uint32_t dst, const void* src) {
    asm volatile("cp.async.cg.shared.global [%0], [%1], 16;"
                 :: "r"(dst), "l"(src) : "memory");
}
__device__ __forceinline__ void cp_commit() {
    asm volatile("cp.async.commit_group;" ::: "memory");
}
template <int N>
__device__ __forceinline__ void cp_wait() {
    asm volatile("cp.async.wait_group %0;" :: "n"(N) : "memory");
}

// m16n8k16 bf16 MMA, fp32 accumulate (sm_80+)
__device__ __forceinline__ void mma16(float* d, const uint32_t* a, const uint32_t* b) {
    asm volatile(
        "mma.sync.aligned.m16n8k16.row.col.f32.bf16.bf16.f32 "
        "{%0,%1,%2,%3}, {%4,%5,%6,%7}, {%8,%9}, {%0,%1,%2,%3};"
        : "+f"(d[0]), "+f"(d[1]), "+f"(d[2]), "+f"(d[3])
        : "r"(a[0]), "r"(a[1]), "r"(a[2]), "r"(a[3]),
          "r"(b[0]), "r"(b[1]));
}

// ---------------------------------------------------------------------------
// bf16 GEMM over expanded K3: C[M,N] = alpha*(A3[M,K3] @ B3[N,K3]^T) + bias + relu
// CTA 128x128, 8 warps of 64x32, BK=64 bf16, cp.async double buffer.
// smem rows padded to 36 words (72 bf16) for conflict-free fragment loads.
// ---------------------------------------------------------------------------
#define GBM 128
#define GBN 128
#define GBK 64
#define RSTRIDE 36                        // uint32 words per smem row
#define ABUF (128 * RSTRIDE)              // words
#define BBUF (128 * RSTRIDE)
#define GEMM_SMEM_BYTES (2 * (ABUF + BBUF) * 4)   // 73728 B

__global__ __launch_bounds__(256, 2) void gemm_bf16_kernel(
    const __nv_bfloat16* __restrict__ A3, const __nv_bfloat16* __restrict__ B3,
    const float* __restrict__ bias, float* __restrict__ C,
    int M, int N, int K3, float alpha, int do_relu)
{
    extern __shared__ uint32_t sm[];
    const uint32_t smb = smem_u32(sm);
    const int tid = threadIdx.x;
    const int wid = tid >> 5, lane = tid & 31;
    const int g = lane >> 2, c4 = lane & 3;
    const int warp_m = wid >> 2;   // 0..1
    const int warp_n = wid & 3;    // 0..3
    const int m0 = blockIdx.x * GBM;
    const int n0 = blockIdx.y * GBN;

    // staging: 256 threads; each handles half of one 128-bf16 (256B) row chunk
    const int srow = tid >> 1, spart = tid & 1;
    const __nv_bfloat16* aptr = A3 + (size_t)(m0 + srow) * K3 + spart * 32;
    const __nv_bfloat16* bptr = B3 + (size_t)(n0 + srow) * K3 + spart * 32;
    const uint32_t as_base = smb + (srow * RSTRIDE + spart * 16) * 4;
    const uint32_t bs_base = smb + (2 * ABUF + srow * RSTRIDE + spart * 16) * 4;

    const int NC = K3 / GBK;

    float acc[4][4][4];
    #pragma unroll
    for (int i = 0; i < 4; i++)
        #pragma unroll
        for (int j = 0; j < 4; j++)
            #pragma unroll
            for (int q = 0; q < 4; q++) acc[i][j][q] = 0.f;

    // prologue: stage chunk 0
    #pragma unroll
    for (int q = 0; q < 4; q++) cp16(as_base + q * 16, aptr + q * 8);
    #pragma unroll
    for (int q = 0; q < 4; q++) cp16(bs_base + q * 16, bptr + q * 8);
    cp_commit();

    for (int c = 0; c < NC; c++) {
        if (c + 1 < NC) {
            const int nb = (c + 1) & 1;
            const __nv_bfloat16* ap = aptr + (c + 1) * GBK;
            const __nv_bfloat16* bp = bptr + (c + 1) * GBK;
            #pragma unroll
            for (int q = 0; q < 4; q++)
                cp16(as_base + nb * ABUF * 4 + q * 16, ap + q * 8);
            #pragma unroll
            for (int q = 0; q < 4; q++)
                cp16(bs_base + nb * BBUF * 4 + q * 16, bp + q * 8);
            cp_commit();
            cp_wait<1>();
        } else {
            cp_wait<0>();
        }
        __syncthreads();

        const uint32_t* ab = sm + (c & 1) * ABUF;
        const uint32_t* bb = sm + 2 * ABUF + (c & 1) * BBUF;

        #pragma unroll
        for (int ks = 0; ks < 4; ks++) {
            const int kb = ks * 8;          // word offset of this k16 step
            uint32_t af[4][4], bf[4][2];
            #pragma unroll
            for (int i = 0; i < 4; i++) {
                const uint32_t* p = ab + (warp_m * 64 + i * 16 + g) * RSTRIDE + kb + c4;
                af[i][0] = p[0];
                af[i][1] = p[8 * RSTRIDE];
                af[i][2] = p[4];
                af[i][3] = p[8 * RSTRIDE + 4];
            }
            #pragma unroll
            for (int j = 0; j < 4; j++) {
                const uint32_t* p = bb + (warp_n * 32 + j * 8 + g) * RSTRIDE + kb + c4;
                bf[j][0] = p[0];
                bf[j][1] = p[4];
            }
            #pragma unroll
            for (int i = 0; i < 4; i++)
                #pragma unroll
                for (int j = 0; j < 4; j++)
                    mma16(acc[i][j], af[i], bf[j]);
        }
        __syncthreads();
    }

    // epilogue
    #pragma unroll
    for (int i = 0; i < 4; i++) {
        const int r0 = m0 + warp_m * 64 + i * 16 + g;
        #pragma unroll
        for (int j = 0; j < 4; j++) {
            const int col = n0 + warp_n * 32 + j * 8 + c4 * 2;
            float b0v = 0.f, b1v = 0.f;
            if (bias) { b0v = bias[col]; b1v = bias[col + 1]; }
            float v0 = acc[i][j][0] * alpha + b0v;
            float v1 = acc[i][j][1] * alpha + b1v;
            float v2 = acc[i][j][2] * alpha + b0v;
            float v3 = acc[i][j][3] * alpha + b1v;
            if (do_relu) {
                v0 = fmaxf(v0, 0.f); v1 = fmaxf(v1, 0.f);
                v2 = fmaxf(v2, 0.f); v3 = fmaxf(v3, 0.f);
            }
            float2 lo = {v0, v1}, hi = {v2, v3};
            *reinterpret_cast<float2*>(C + (size_t)r0 * N + col) = lo;
            *reinterpret_cast<float2*>(C + (size_t)(r0 + 8) * N + col) = hi;
        }
    }
}

// ---------------------------------------------------------------------------
// Split conversion: act[M,K] f32 -> A3[M,3K] bf16 = [hi | lo | hi]
// ---------------------------------------------------------------------------
__global__ void conv_act_kernel(const float* __restrict__ in,
                                __nv_bfloat16* __restrict__ out,
                                int M, int K)
{
    int idx = blockIdx.x * blockDim.x + threadIdx.x;
    if (idx >= M * K) return;
    int row = idx / K;
    int k = idx - row * K;
    float x = in[idx];
    __nv_bfloat16 hi = __float2bfloat16_rn(x);
    __nv_bfloat16 lo = __float2bfloat16_rn(x - __bfloat162float(hi));
    size_t base = (size_t)row * 3 * K;
    out[base + k] = hi;
    out[base + K + k] = lo;
    out[base + 2 * K + k] = hi;
}

// ---------------------------------------------------------------------------
// Split + transpose: W[K,N] f32 -> B3[N,3K] bf16 = [hi | hi | lo]
// ---------------------------------------------------------------------------
__global__ __launch_bounds__(256) void conv_wT_kernel(
    const float* __restrict__ W, __nv_bfloat16* __restrict__ out, int K, int N)
{
    __shared__ float tile[32][33];
    const int tx = threadIdx.x & 31;
    const int ty = threadIdx.x >> 5;       // 0..7
    const int n0 = blockIdx.x * 32;
    const int k0 = blockIdx.y * 32;
    #pragma unroll
    for (int i = 0; i < 4; i++)
        tile[ty + i * 8][tx] = W[(size_t)(k0 + ty + i * 8) * N + n0 + tx];
    __syncthreads();
    #pragma unroll
    for (int i = 0; i < 4; i++) {
        const int n = n0 + ty + i * 8;
        const int k = k0 + tx;
        float x = tile[tx][ty + i * 8];
        __nv_bfloat16 hi = __float2bfloat16_rn(x);
        __nv_bfloat16 lo = __float2bfloat16_rn(x - __bfloat162float(hi));
        size_t base = (size_t)n * 3 * K;
        out[base + k] = hi;
        out[base + K + k] = hi;
        out[base + 2 * K + k] = lo;
    }
}

// ---------------------------------------------------------------------------
// Elementwise / LN / gather kernels
// ---------------------------------------------------------------------------
__global__ void gather_kernel(const int* __restrict__ x,
                              const float* __restrict__ emb,
                              float* __restrict__ out)
{
    int idx = blockIdx.x * blockDim.x + threadIdx.x;
    if (idx >= M4 * E_) return;
    int i = idx / E_;
    int e = idx - i * E_;
    out[idx] = emb[(size_t)x[i] * E_ + e];
}

__global__ void addpos_kernel(const float* __restrict__ xemb,
                              const float* __restrict__ pos11,
                              float* __restrict__ out)
{
    int idx = blockIdx.x * blockDim.x + threadIdx.x;
    if (idx >= M4 * H_) return;
    int i = idx / H_;
    int h = idx - i * H_;
    int s = i & (S_ - 1);
    out[idx] = xemb[idx] + pos11[(size_t)s * H_ + h];
}

__global__ __launch_bounds__(256) void ln_res_kernel(
    const float* __restrict__ res, const float* __restrict__ x,
    const float* __restrict__ bias, const float* __restrict__ scale,
    float* __restrict__ out)
{
    __shared__ float red[256];
    const int row = blockIdx.x;
    const int t = threadIdx.x;
    const float* xr = x + (size_t)row * H_;

    float lsum = 0.f;
    for (int i = t; i < H_; i += 256) lsum += xr[i];
    red[t] = lsum; __syncthreads();
    for (int s = 128; s > 0; s >>= 1) { if (t < s) red[t] += red[t + s]; __syncthreads(); }
    const float mean = red[0] * (1.0f / H_);
    __syncthreads();

    float lvar = 0.f;
    for (int i = t; i < H_; i += 256) { float d = xr[i] - mean; lvar += d * d; }
    red[t] = lvar; __syncthreads();
    for (int s = 128; s > 0; s >>= 1) { if (t < s) red[t] += red[t + s]; __syncthreads(); }
    const float rstd = rsqrtf(red[0] * (1.0f / H_) + 1e-6f);

    for (int i = t; i < H_; i += 256) {
        out[(size_t)row * H_ + i] =
            res[(size_t)row * H_ + i] + (xr[i] - mean) * rstd * scale[i] + bias[i];
    }
}

// ---------------------------------------------------------------------------
// Causal flash attention (fp32)
// ---------------------------------------------------------------------------
__global__ __launch_bounds__(64) void attn_kernel(
    const float* __restrict__ Q, const float* __restrict__ Kb,
    const float* __restrict__ Vb, float* __restrict__ O)
{
    __shared__ float Ks[64 * 64];
    __shared__ float Vs[64 * 64];
    __shared__ float Ss[64 * 65];

    const int qt = blockIdx.x;
    const int bh = blockIdx.y;
    const int b  = bh >> 4;
    const int n  = bh & 15;
    const int t  = threadIdx.x;
    const int qrow = qt * 64 + t;

    const float* qptr = Q + ((size_t)(b * S_ + qrow)) * H_ + n * HEAD_;
    float qreg[HEAD_];
    #pragma unroll
    for (int d = 0; d < HEAD_; d++) qreg[d] = qptr[d];

    float accv[HEAD_];
    #pragma unroll
    for (int d = 0; d < HEAD_; d++) accv[d] = 0.f;
    float mval = -1e30f, lval = 0.f;

    for (int kt = 0; kt <= qt; kt++) {
        const float* kptr = Kb + ((size_t)(b * S_ + kt * 64 + t)) * H_ + n * HEAD_;
        const float* vptr = Vb + ((size_t)(b * S_ + kt * 64 + t)) * H_ + n * HEAD_;
        #pragma unroll
        for (int d = 0; d < HEAD_; d += 4) {
            *reinterpret_cast<float4*>(&Ks[t * 64 + d]) =
                *reinterpret_cast<const float4*>(kptr + d);
            *reinterpret_cast<float4*>(&Vs[t * 64 + d]) =
                *reinterpret_cast<const float4*>(vptr + d);
        }
        __syncthreads();

        const int jmax = (kt == qt) ? (t + 1) : 64;

        float tmax = -1e30f;
        for (int j = 0; j < jmax; j++) {
            float s = 0.f;
            #pragma unroll
            for (int d = 0; d < HEAD_; d++) s += qreg[d] * Ks[j * 64 + d];
            Ss[t * 65 + j] = s;
            tmax = fmaxf(tmax, s);
        }

        const float mnew = fmaxf(mval, tmax);
        const float corr = __expf(mval - mnew);
        lval *= corr;
        #pragma unroll
        for (int d = 0; d < HEAD_; d++) accv[d] *= corr;

        for (int j = 0; j < jmax; j++) {
            const float p = __expf(Ss[t * 65 + j] - mnew);
            lval += p;
            #pragma unroll
            for (int d = 0; d < HEAD_; d++) accv[d] += p * Vs[j * 64 + d];
        }
        mval = mnew;
        __syncthreads();
    }

    const float inv = 1.f / lval;
    float* optr = O + ((size_t)(b * S_ + qrow)) * H_ + n * HEAD_;
    #pragma unroll
    for (int d = 0; d < HEAD_; d += 4) {
        float4 o;
        o.x = accv[d + 0] * inv;
        o.y = accv[d + 1] * inv;
        o.z = accv[d + 2] * inv;
        o.w = accv[d + 3] * inv;
        *reinterpret_cast<float4*>(optr + d) = o;
    }
}

// ---------------------------------------------------------------------------
// Launch helpers
// ---------------------------------------------------------------------------
static inline void run_gemm(const __nv_bfloat16* A3, const __nv_bfloat16* B3,
                            const float* bias, float* C,
                            int M, int N, int K3, float alpha, int relu)
{
    dim3 grid(M / GBM, N / GBN);
    gemm_bf16_kernel<<<grid, 256, GEMM_SMEM_BYTES>>>(A3, B3, bias, C, M, N, K3, alpha, relu);
}
static inline void run_conv_act(const float* in, __nv_bfloat16* out, int M, int K)
{
    conv_act_kernel<<<(M * K + 255) / 256, 256>>>(in, out, M, K);
}
static inline void run_conv_wT(const float* W, __nv_bfloat16* out, int K, int N)
{
    dim3 grid(N / 32, K / 32);
    conv_wT_kernel<<<grid, 256>>>(W, out, K, N);
}

extern "C" void kernel_launch(void* const* d_in, const int* in_sizes, int n_in,
                              void* d_out, int out_size)
{
    const int*   x            = (const int*)  d_in[0];
    const float* emb_decode   = (const float*)d_in[1];
    const float* W_dec_lin    = (const float*)d_in[2];
    const float* p_decoder    = (const float*)d_in[3];
    const float* x_emb_pos    = (const float*)d_in[4];
    const float* p_d_q        = (const float*)d_in[5];
    const float* p_d_k        = (const float*)d_in[6];
    const float* p_d_v        = (const float*)d_in[7];
    const float* p_d_c        = (const float*)d_in[8];
    const float* p_d_ff1      = (const float*)d_in[9];
    const float* p_d_ff2      = (const float*)d_in[10];
    const float* b_d_ff1      = (const float*)d_in[11];
    const float* b_d_ff2      = (const float*)d_in[12];
    const float* d_o_bias     = (const float*)d_in[13];
    const float* d_o_scale    = (const float*)d_in[14];
    const float* b_d_bias_1   = (const float*)d_in[15];
    const float* b_d_bias_2   = (const float*)d_in[16];
    const float* b_d_scale_1  = (const float*)d_in[17];
    const float* b_d_scale_2  = (const float*)d_in[18];
    float* out = (float*)d_out;

    const int m = L_ - 1;   // only the last layer's result is observable

    cudaFuncSetAttribute(gemm_bf16_kernel,
                         cudaFuncAttributeMaxDynamicSharedMemorySize, GEMM_SMEM_BYTES);

    float *Aemb, *xemb, *layerin, *q, *k, *v, *conc, *xmulti, *xself,
          *ffw1, *ffw2, *xffw, *decout;
    __nv_bfloat16 *a3_emb, *a3_li, *a3_conc, *a3_self, *a3_ffw1, *a3_dec;
    __nv_bfloat16 *w3_dec, *w3_q, *w3_k, *w3_v, *w3_c, *w3_ff1, *w3_ff2, *w3_pdec;
    cudaGetSymbolAddress((void**)&Aemb,    g_Aemb);
    cudaGetSymbolAddress((void**)&xemb,    g_xemb);
    cudaGetSymbolAddress((void**)&layerin, g_layerin);
    cudaGetSymbolAddress((void**)&q,       g_q);
    cudaGetSymbolAddress((void**)&k,       g_k);
    cudaGetSymbolAddress((void**)&v,       g_v);
    cudaGetSymbolAddress((void**)&conc,    g_conc);
    cudaGetSymbolAddress((void**)&xmulti,  g_xmulti);
    cudaGetSymbolAddress((void**)&xself,   g_xself);
    cudaGetSymbolAddress((void**)&ffw1,    g_ffw1);
    cudaGetSymbolAddress((void**)&ffw2,    g_ffw2);
    cudaGetSymbolAddress((void**)&xffw,    g_xffw);
    cudaGetSymbolAddress((void**)&decout,  g_decout);
    cudaGetSymbolAddress((void**)&a3_emb,  g_a3_emb);
    cudaGetSymbolAddress((void**)&a3_li,   g_a3_li);
    cudaGetSymbolAddress((void**)&a3_conc, g_a3_conc);
    cudaGetSymbolAddress((void**)&a3_self, g_a3_self);
    cudaGetSymbolAddress((void**)&a3_ffw1, g_a3_ffw1);
    cudaGetSymbolAddress((void**)&a3_dec,  g_a3_dec);
    cudaGetSymbolAddress((void**)&w3_dec,  g_w3_dec);
    cudaGetSymbolAddress((void**)&w3_q,    g_w3_q);
    cudaGetSymbolAddress((void**)&w3_k,    g_w3_k);
    cudaGetSymbolAddress((void**)&w3_v,    g_w3_v);
    cudaGetSymbolAddress((void**)&w3_c,    g_w3_c);
    cudaGetSymbolAddress((void**)&w3_ff1,  g_w3_ff1);
    cudaGetSymbolAddress((void**)&w3_ff2,  g_w3_ff2);
    cudaGetSymbolAddress((void**)&w3_pdec, g_w3_pdec);

    const float inv_sqrt_head = 0.125f;

    // weight conversions (split + transpose)
    run_conv_wT(W_dec_lin, w3_dec, E_, H_);
    run_conv_wT(p_d_q + (size_t)m * H_ * H_, w3_q, H_, H_);
    run_conv_wT(p_d_k + (size_t)m * H_ * H_, w3_k, H_, H_);
    run_conv_wT(p_d_v + (size_t)m * H_ * H_, w3_v, H_, H_);
    run_conv_wT(p_d_c + (size_t)m * H_ * H_, w3_c, H_, H_);
    run_conv_wT(p_d_ff1 + (size_t)m * H_ * FF_, w3_ff1, H_, FF_);
    run_conv_wT(p_d_ff2 + (size_t)m * FF_ * H_, w3_ff2, FF_, H_);
    run_conv_wT(p_decoder, w3_pdec, H_, V_);

    // 1. gather embeddings
    gather_kernel<<<(M4 * E_ + 255) / 256, 256>>>(x, emb_decode, Aemb);
    run_conv_act(Aemb, a3_emb, M4, E_);

    // 2. x_dec_embed = A_emb @ W_dec_lin
    run_gemm(a3_emb, w3_dec, nullptr, xemb, M4, H_, 3 * E_, 1.f, 0);

    // 3. layer_in = pos[11] + x_dec_embed
    addpos_kernel<<<(M4 * H_ + 255) / 256, 256>>>(
        xemb, x_emb_pos + (size_t)m * S_ * H_, layerin);
    run_conv_act(layerin, a3_li, M4, H_);

    // 4. Q/K/V projections (Q pre-scaled)
    run_gemm(a3_li, w3_q, nullptr, q, M4, H_, 3 * H_, inv_sqrt_head, 0);
    run_gemm(a3_li, w3_k, nullptr, k, M4, H_, 3 * H_, 1.f, 0);
    run_gemm(a3_li, w3_v, nullptr, v, M4, H_, 3 * H_, 1.f, 0);

    // 5. causal attention -> conc
    attn_kernel<<<dim3(S_ / 64, B_ * NH_), 64>>>(q, k, v, conc);
    run_conv_act(conc, a3_conc, M4, H_);

    // 6. x_multi = conc @ p_d_c
    run_gemm(a3_conc, w3_c, nullptr, xmulti, M4, H_, 3 * H_, 1.f, 0);

    // 7. x_self = layer_in + LN(x_multi)
    ln_res_kernel<<<M4, 256>>>(layerin, xmulti,
                               b_d_bias_1 + (size_t)m * H_,
                               b_d_scale_1 + (size_t)m * H_, xself);
    run_conv_act(xself, a3_self, M4, H_);

    // 8. FFN
    run_gemm(a3_self, w3_ff1, b_d_ff1 + (size_t)m * FF_, ffw1, M4, FF_, 3 * H_, 1.f, 1);
    run_conv_act(ffw1, a3_ffw1, M4, FF_);
    run_gemm(a3_ffw1, w3_ff2, b_d_ff2 + (size_t)m * H_, ffw2, M4, H_, 3 * FF_, 1.f, 0);

    // 9. x_ffw = x_self + LN(ffw2)
    ln_res_kernel<<<M4, 256>>>(xself, ffw2,
                               b_d_bias_2 + (size_t)m * H_,
                               b_d_scale_2 + (size_t)m * H_, xffw);

    // 10. dec_outputs = x_dec_embed + LN(x_ffw)
    ln_res_kernel<<<M4, 256>>>(xemb, xffw, d_o_bias, d_o_scale, decout);
    run_conv_act(decout, a3_dec, M4, H_);

    // 11. logits = dec_outputs @ p_decoder
    run_gemm(a3_dec, w3_pdec, nullptr, out, M4, V_, 3 * H_, 1.f, 0);
}

// round 6
// speedup vs baseline: 4.3823x; 2.7192x over previous
#include <cuda_runtime.h>
#include <cuda_bf16.h>
#include <cstdint>

// Problem constants
#define L_   12
#define NH_  16
#define H_   1024
#define FF_  4096
#define V_   32000
#define S_   1024
#define E_   128
#define B_   4
#define HEAD_ 64
#define M4   (B_ * S_)   // 4096 rows total

// Arch-feature dispatch: tcgen05 only legal in the sm_103a pass.
#if defined(__CUDA_ARCH__) && defined(__CUDA_ARCH_FEAT_SM103_ALL)
#define TC_PATH 1
#else
#define TC_PATH 0
#endif

// ---------------------------------------------------------------------------
// Scratch (device globals — allocation-free per harness rules)
// ---------------------------------------------------------------------------
__device__ float g_Aemb   [M4 * E_];
__device__ float g_xemb   [M4 * H_];
__device__ float g_layerin[M4 * H_];
__device__ float g_q      [M4 * H_];
__device__ float g_k      [M4 * H_];
__device__ float g_v      [M4 * H_];
__device__ float g_conc   [M4 * H_];
__device__ float g_xmulti [M4 * H_];
__device__ float g_xself  [M4 * H_];
__device__ float g_ffw1   [M4 * FF_];
__device__ float g_ffw2   [M4 * H_];
__device__ float g_xffw   [M4 * H_];
__device__ float g_decout [M4 * H_];

// bf16 split-K3 operand buffers.  A' = [hi | lo | hi] (row-major, 3K cols),
// B' = [hi | hi | lo] as [N, 3K] (k-contiguous, i.e. transposed weight).
__device__ __align__(128) __nv_bfloat16 g_a3_emb [M4 * 3 * E_];
__device__ __align__(128) __nv_bfloat16 g_a3_li  [M4 * 3 * H_];
__device__ __align__(128) __nv_bfloat16 g_a3_conc[M4 * 3 * H_];
__device__ __align__(128) __nv_bfloat16 g_a3_self[M4 * 3 * H_];
__device__ __align__(128) __nv_bfloat16 g_a3_ffw1[(size_t)M4 * 3 * FF_];
__device__ __align__(128) __nv_bfloat16 g_a3_dec [M4 * 3 * H_];

__device__ __align__(128) __nv_bfloat16 g_w3_dec [H_ * 3 * E_];
__device__ __align__(128) __nv_bfloat16 g_w3_q   [H_ * 3 * H_];
__device__ __align__(128) __nv_bfloat16 g_w3_k   [H_ * 3 * H_];
__device__ __align__(128) __nv_bfloat16 g_w3_v   [H_ * 3 * H_];
__device__ __align__(128) __nv_bfloat16 g_w3_c   [H_ * 3 * H_];
__device__ __align__(128) __nv_bfloat16 g_w3_ff1 [(size_t)FF_ * 3 * H_];
__device__ __align__(128) __nv_bfloat16 g_w3_ff2 [(size_t)H_ * 3 * FF_];
__device__ __align__(128) __nv_bfloat16 g_w3_pdec[(size_t)V_ * 3 * H_];

// ---------------------------------------------------------------------------
// PTX helpers — baseline-legal ones first
// ---------------------------------------------------------------------------
__device__ __forceinline__ uint32_t smem_u32(const void* p) {
    uint32_t a;
    asm("{ .reg .u64 t; cvta.to.shared.u64 t, %1; cvt.u32.u64 %0, t; }"
        : "=r"(a) : "l"(p));
    return a;
}
__device__ __forceinline__ void cp16(uint32_t dst, const void* src) {
    asm volatile("cp.async.cg.shared.global [%0], [%1], 16;"
                 :: "r"(dst), "l"(src) : "memory");
}
__device__ __forceinline__ void cp_commit() {
    asm volatile("cp.async.commit_group;" ::: "memory");
}
template <int N>
__device__ __forceinline__ void cp_wait() {
    asm volatile("cp.async.wait_group %0;" :: "n"(N) : "memory");
}
__device__ __forceinline__ uint32_t elect_one_pred() {
    uint32_t pred;
    asm volatile(
        "{\n\t.reg .pred p;\n\telect.sync _|p, 0xFFFFFFFF;\n\t"
        "selp.b32 %0, 1, 0, p;\n\t}" : "=r"(pred));
    return pred;
}

// legacy m16n8k16 bf16 MMA, fp32 accumulate (sm_80+)
__device__ __forceinline__ void mma16(float* d, const uint32_t* a, const uint32_t* b) {
    asm volatile(
        "mma.sync.aligned.m16n8k16.row.col.f32.bf16.bf16.f32 "
        "{%0,%1,%2,%3}, {%4,%5,%6,%7}, {%8,%9}, {%0,%1,%2,%3};"
        : "+f"(d[0]), "+f"(d[1]), "+f"(d[2]), "+f"(d[3])
        : "r"(a[0]), "r"(a[1]), "r"(a[2]), "r"(a[3]),
          "r"(b[0]), "r"(b[1]));
}

#define SMEM_SWIZZLE_128B(o) ((o) ^ (((o) >> 3) & 0x70))

#if TC_PATH
// ---- tcgen05 helpers (only compiled in the sm_103a pass) ----
#define TCGEN05_ALLOC(smem_addr, nCols) \
    asm volatile("tcgen05.alloc.cta_group::1.sync.aligned.shared::cta.b32 [%0], %1;" \
                 :: "r"((uint32_t)(smem_addr)), "r"((uint32_t)(nCols)) : "memory")
#define TCGEN05_DEALLOC(tmem_addr, nCols) \
    asm volatile("tcgen05.dealloc.cta_group::1.sync.aligned.b32 %0, %1;" \
                 :: "r"(tmem_addr), "r"((uint32_t)(nCols)))
#define TCGEN05_RELINQUISH() \
    asm volatile("tcgen05.relinquish_alloc_permit.cta_group::1.sync.aligned;")
#define TCGEN05_COMMIT(mbar) \
    asm volatile("tcgen05.commit.cta_group::1.mbarrier::arrive::one.shared::cluster.b64 [%0];" \
                 :: "r"((uint32_t)(mbar)) : "memory")
#define TCGEN05_FENCE_AFTER() \
    asm volatile("tcgen05.fence::after_thread_sync;" ::: "memory")
#define TCGEN05_FENCE_BEFORE() \
    asm volatile("tcgen05.fence::before_thread_sync;" ::: "memory")
#define TCGEN05_WAIT_LD() \
    asm volatile("tcgen05.wait::ld.sync.aligned;" ::: "memory")
#define MBARRIER_INIT(mbar, cnt) \
    asm volatile("mbarrier.init.shared.b64 [%0], %1;" \
                 :: "r"((uint32_t)(mbar)), "r"((uint32_t)(cnt)) : "memory")
#define MBARRIER_INVAL(mbar) \
    asm volatile("mbarrier.inval.shared.b64 [%0];" :: "r"((uint32_t)(mbar)) : "memory")
#define FENCE_PROXY_ASYNC() \
    asm volatile("fence.proxy.async.shared::cta;" ::: "memory")

#define MBARRIER_WAIT_PARITY(mbar_smem_addr, phase_parity) do { \
    uint32_t _mbar = (uint32_t)(mbar_smem_addr); \
    uint32_t _parity = (uint32_t)(phase_parity); \
    uint32_t _done; \
    asm volatile("{\n\t.reg .pred p;\n\t" \
        "mbarrier.try_wait.parity.acquire.cta.shared::cta.b64 p, [%1], %2;\n\t" \
        "selp.b32 %0, 1, 0, p;\n\t}" \
        : "=r"(_done) : "r"(_mbar), "r"(_parity) : "memory"); \
    if (!_done) { \
        asm volatile("{\n\t.reg .pred P1;\n\t" \
            "WAIT_LOOP_%=:\n\t" \
            "mbarrier.try_wait.parity.acquire.cta.shared::cta.b64 P1, [%0], %1, 0x989680;\n\t" \
            "@P1 bra.uni WAIT_DONE_%=;\n\t" \
            "bra.uni WAIT_LOOP_%=;\n\t" \
            "WAIT_DONE_%=:\n\t}" \
            :: "r"(_mbar), "r"(_parity) : "memory"); \
    } \
} while(0)

#define TCGEN05_LD_32X32B_X32(r, tmem_addr) \
    asm volatile( \
        "tcgen05.ld.sync.aligned.32x32b.x32.b32 " \
        "{%0, %1, %2, %3, %4, %5, %6, %7, " \
        " %8, %9, %10, %11, %12, %13, %14, %15, " \
        " %16, %17, %18, %19, %20, %21, %22, %23, " \
        " %24, %25, %26, %27, %28, %29, %30, %31}, [%32];" \
        : "=r"((r)[0]),  "=r"((r)[1]),  "=r"((r)[2]),  "=r"((r)[3]), \
          "=r"((r)[4]),  "=r"((r)[5]),  "=r"((r)[6]),  "=r"((r)[7]), \
          "=r"((r)[8]),  "=r"((r)[9]),  "=r"((r)[10]), "=r"((r)[11]), \
          "=r"((r)[12]), "=r"((r)[13]), "=r"((r)[14]), "=r"((r)[15]), \
          "=r"((r)[16]), "=r"((r)[17]), "=r"((r)[18]), "=r"((r)[19]), \
          "=r"((r)[20]), "=r"((r)[21]), "=r"((r)[22]), "=r"((r)[23]), \
          "=r"((r)[24]), "=r"((r)[25]), "=r"((r)[26]), "=r"((r)[27]), \
          "=r"((r)[28]), "=r"((r)[29]), "=r"((r)[30]), "=r"((r)[31]) \
        : "r"(tmem_addr))

// SW128 smem descriptor: layout=SW128(2), version=1, SBO=64, LBO=1
static constexpr uint64_t SMEM_DESC_BASE_SW128 =
    (uint64_t(2) << 61) | (uint64_t(1) << 46) | (uint64_t(64) << 32) | (uint64_t(1) << 16);
#define MAKE_SMEM_DESC(addr) (SMEM_DESC_BASE_SW128 | ((uint64_t)((addr) >> 4) & 0x3FFF))

// bf16 SS MMA, cta_group::1, fp32 accumulate
__device__ __forceinline__ void mma_bf16_ss(uint32_t d_tmem, uint64_t a_desc,
                                            uint64_t b_desc, uint32_t idesc,
                                            uint32_t enable_d) {
    uint32_t z = 0;
    asm volatile(
        "{\n\t.reg .pred p;\n\tsetp.ne.u32 p, %5, 0;\n\t"
        "tcgen05.mma.cta_group::1.kind::f16 [%0], %1, %2, %3, {%4, %4, %4, %4}, p;\n\t}"
        :: "r"(d_tmem), "l"(a_desc), "l"(b_desc), "r"(idesc), "r"(z), "r"(enable_d)
        : "memory");
}
#endif // TC_PATH

// ---------------------------------------------------------------------------
// GEMM over expanded K3: C[M,N] = alpha*(A3[M,K3] @ B3[N,K3]^T) + bias + relu
// grid (M/128, N/128), 256 threads, dynamic smem GEMM_SMEM_BYTES (both paths).
// ---------------------------------------------------------------------------
#define GBM 128
#define GBN 128
#define GBK 64
#define RSTRIDE 36                        // legacy: uint32 words per smem row
#define ABUF (128 * RSTRIDE)
#define BBUF (128 * RSTRIDE)
#define GEMM_SMEM_BYTES (2 * (ABUF + BBUF) * 4)   // 73728 B (covers both paths)

__global__ __launch_bounds__(256, 2) void gemm_bf16_kernel(
    const __nv_bfloat16* __restrict__ A3, const __nv_bfloat16* __restrict__ B3,
    const float* __restrict__ bias, float* __restrict__ C,
    int M, int N, int K3, float alpha, int do_relu)
{
#if TC_PATH
    // =================== tcgen05 path (sm_103a SASS) ===================
    extern __shared__ char smc[];
    const uint32_t smb = smem_u32(smc);
    const int tid = threadIdx.x;
    const int wid = tid >> 5, lane = tid & 31;
    const int m0 = blockIdx.x * GBM;
    const int n0 = blockIdx.y * GBN;

    // smem map: [0..3] tmem ptr, [8],[16] mbarriers, tiles at 1024
    const uint32_t SA0 = 1024u, SA1 = 1024u + 16384u;
    const uint32_t SB0 = 1024u + 32768u, SB1 = 1024u + 49152u;
    const uint32_t MB0 = smb + 8u, MB1 = smb + 16u;

    if (wid == 0) TCGEN05_ALLOC(smb, 128);
    if (tid == 0) { MBARRIER_INIT(MB0, 1); MBARRIER_INIT(MB1, 1); }
    __syncthreads();
    uint32_t tmem;
    asm volatile("ld.shared.b32 %0, [%1];" : "=r"(tmem) : "r"(smb));
    if (wid == 0) TCGEN05_RELINQUISH();

    const uint32_t IDESC =
        (1u << 4) | (1u << 7) | (1u << 10) | ((GBN / 8) << 17) | ((GBM / 16) << 24);

    const int NC = K3 / GBK;
    const uint32_t saoff[2] = {SA0, SA1};
    const uint32_t sboff[2] = {SB0, SB1};

    // per-thread staging slots: 1024 16B chunks per tile, 4 per thread
    const int r0s = tid >> 3;             // rows handled: r0s, +32, +64, +96
    const int c8 = tid & 7;               // 16B column within 128B row
    const __nv_bfloat16* abase = A3 + (size_t)(m0 + r0s) * K3 + c8 * 8;
    const __nv_bfloat16* bbase = B3 + (size_t)(n0 + r0s) * K3 + c8 * 8;

    int ph0 = 0, ph1 = 0;

    // stage chunk 0 into buffer 0
    {
        #pragma unroll
        for (int it = 0; it < 4; it++) {
            const int row = r0s + it * 32;
            const uint32_t sw = SMEM_SWIZZLE_128B((uint32_t)(row * 128 + c8 * 16));
            cp16(smb + SA0 + sw, abase + (size_t)it * 32 * K3);
            cp16(smb + SB0 + sw, bbase + (size_t)it * 32 * K3);
        }
        cp_commit();
    }

    for (int c = 0; c < NC; c++) {
        const int b = c & 1;
        if (c + 1 < NC) {
            const int nb = (c + 1) & 1;
            if (c >= 1) {   // buffer nb was used by chunk c-1's MMAs
                if (nb == 0) { MBARRIER_WAIT_PARITY(MB0, ph0); ph0 ^= 1; }
                else         { MBARRIER_WAIT_PARITY(MB1, ph1); ph1 ^= 1; }
            }
            #pragma unroll
            for (int it = 0; it < 4; it++) {
                const int row = r0s + it * 32;
                const uint32_t sw = SMEM_SWIZZLE_128B((uint32_t)(row * 128 + c8 * 16));
                cp16(smb + saoff[nb] + sw, abase + (size_t)it * 32 * K3 + (c + 1) * GBK);
                cp16(smb + sboff[nb] + sw, bbase + (size_t)it * 32 * K3 + (c + 1) * GBK);
            }
            cp_commit();
            cp_wait<1>();       // chunk c's group has landed
        } else {
            cp_wait<0>();
        }
        __syncthreads();

        if (wid == 0 && elect_one_pred()) {
            FENCE_PROXY_ASYNC();
            const uint64_t ad = MAKE_SMEM_DESC(smb + saoff[b]);
            const uint64_t bd = MAKE_SMEM_DESC(smb + sboff[b]);
            #pragma unroll
            for (int ks = 0; ks < 4; ks++)
                mma_bf16_ss(tmem, ad + ks * 2, bd + ks * 2, IDESC,
                            (c > 0 || ks > 0) ? 1u : 0u);
            TCGEN05_COMMIT(b == 0 ? MB0 : MB1);
        }
    }

    // wait for final chunk's MMAs (commit tracks all prior MMAs)
    if (((NC - 1) & 1) == 0) MBARRIER_WAIT_PARITY(MB0, ph0);
    else                     MBARRIER_WAIT_PARITY(MB1, ph1);
    TCGEN05_FENCE_AFTER();

    if (wid < 4) {
        const uint32_t lofs = (uint32_t)wid << 21;
        const int row = m0 + wid * 32 + lane;
        #pragma unroll
        for (int j = 0; j < 4; j++) {
            uint32_t r[32];
            TCGEN05_LD_32X32B_X32(r, tmem + j * 32 + lofs);
            TCGEN05_WAIT_LD();
            float* cp = C + (size_t)row * N + n0 + j * 32;
            const float* bp = bias ? (bias + n0 + j * 32) : nullptr;
            #pragma unroll
            for (int q = 0; q < 32; q += 4) {
                float v0 = __uint_as_float(r[q + 0]) * alpha;
                float v1 = __uint_as_float(r[q + 1]) * alpha;
                float v2 = __uint_as_float(r[q + 2]) * alpha;
                float v3 = __uint_as_float(r[q + 3]) * alpha;
                if (bp) { v0 += bp[q]; v1 += bp[q + 1]; v2 += bp[q + 2]; v3 += bp[q + 3]; }
                if (do_relu) {
                    v0 = fmaxf(v0, 0.f); v1 = fmaxf(v1, 0.f);
                    v2 = fmaxf(v2, 0.f); v3 = fmaxf(v3, 0.f);
                }
                float4 o = {v0, v1, v2, v3};
                *reinterpret_cast<float4*>(cp + q) = o;
            }
        }
        TCGEN05_FENCE_BEFORE();
    }
    __syncthreads();
    if (tid == 0) { MBARRIER_INVAL(MB0); MBARRIER_INVAL(MB1); }
    __syncthreads();
    if (wid == 0) TCGEN05_DEALLOC(tmem, 128);

#else
    // =================== legacy HMMA path (compute_103 fallback) ===================
    extern __shared__ uint32_t sm[];
    const uint32_t smb = smem_u32(sm);
    const int tid = threadIdx.x;
    const int wid = tid >> 5, lane = tid & 31;
    const int g = lane >> 2, c4 = lane & 3;
    const int warp_m = wid >> 2;
    const int warp_n = wid & 3;
    const int m0 = blockIdx.x * GBM;
    const int n0 = blockIdx.y * GBN;

    const int srow = tid >> 1, spart = tid & 1;
    const __nv_bfloat16* aptr = A3 + (size_t)(m0 + srow) * K3 + spart * 32;
    const __nv_bfloat16* bptr = B3 + (size_t)(n0 + srow) * K3 + spart * 32;
    const uint32_t as_base = smb + (srow * RSTRIDE + spart * 16) * 4;
    const uint32_t bs_base = smb + (2 * ABUF + srow * RSTRIDE + spart * 16) * 4;

    const int NC = K3 / GBK;

    float acc[4][4][4];
    #pragma unroll
    for (int i = 0; i < 4; i++)
        #pragma unroll
        for (int j = 0; j < 4; j++)
            #pragma unroll
            for (int q = 0; q < 4; q++) acc[i][j][q] = 0.f;

    #pragma unroll
    for (int q = 0; q < 4; q++) cp16(as_base + q * 16, aptr + q * 8);
    #pragma unroll
    for (int q = 0; q < 4; q++) cp16(bs_base + q * 16, bptr + q * 8);
    cp_commit();

    for (int c = 0; c < NC; c++) {
        if (c + 1 < NC) {
            const int nb = (c + 1) & 1;
            const __nv_bfloat16* ap = aptr + (c + 1) * GBK;
            const __nv_bfloat16* bp = bptr + (c + 1) * GBK;
            #pragma unroll
            for (int q = 0; q < 4; q++)
                cp16(as_base + nb * ABUF * 4 + q * 16, ap + q * 8);
            #pragma unroll
            for (int q = 0; q < 4; q++)
                cp16(bs_base + nb * BBUF * 4 + q * 16, bp + q * 8);
            cp_commit();
            cp_wait<1>();
        } else {
            cp_wait<0>();
        }
        __syncthreads();

        const uint32_t* ab = sm + (c & 1) * ABUF;
        const uint32_t* bb = sm + 2 * ABUF + (c & 1) * BBUF;

        #pragma unroll
        for (int ks = 0; ks < 4; ks++) {
            const int kb = ks * 8;
            uint32_t af[4][4], bf[4][2];
            #pragma unroll
            for (int i = 0; i < 4; i++) {
                const uint32_t* p = ab + (warp_m * 64 + i * 16 + g) * RSTRIDE + kb + c4;
                af[i][0] = p[0];
                af[i][1] = p[8 * RSTRIDE];
                af[i][2] = p[4];
                af[i][3] = p[8 * RSTRIDE + 4];
            }
            #pragma unroll
            for (int j = 0; j < 4; j++) {
                const uint32_t* p = bb + (warp_n * 32 + j * 8 + g) * RSTRIDE + kb + c4;
                bf[j][0] = p[0];
                bf[j][1] = p[4];
            }
            #pragma unroll
            for (int i = 0; i < 4; i++)
                #pragma unroll
                for (int j = 0; j < 4; j++)
                    mma16(acc[i][j], af[i], bf[j]);
        }
        __syncthreads();
    }

    #pragma unroll
    for (int i = 0; i < 4; i++) {
        const int r0 = m0 + warp_m * 64 + i * 16 + g;
        #pragma unroll
        for (int j = 0; j < 4; j++) {
            const int col = n0 + warp_n * 32 + j * 8 + c4 * 2;
            float b0v = 0.f, b1v = 0.f;
            if (bias) { b0v = bias[col]; b1v = bias[col + 1]; }
            float v0 = acc[i][j][0] * alpha + b0v;
            float v1 = acc[i][j][1] * alpha + b1v;
            float v2 = acc[i][j][2] * alpha + b0v;
            float v3 = acc[i][j][3] * alpha + b1v;
            if (do_relu) {
                v0 = fmaxf(v0, 0.f); v1 = fmaxf(v1, 0.f);
                v2 = fmaxf(v2, 0.f); v3 = fmaxf(v3, 0.f);
            }
            float2 lo = {v0, v1}, hi = {v2, v3};
            *reinterpret_cast<float2*>(C + (size_t)r0 * N + col) = lo;
            *reinterpret_cast<float2*>(C + (size_t)(r0 + 8) * N + col) = hi;
        }
    }
#endif
}

// ---------------------------------------------------------------------------
// Split conversion: act[M,K] f32 -> A3[M,3K] bf16 = [hi | lo | hi]
// ---------------------------------------------------------------------------
__global__ void conv_act_kernel(const float* __restrict__ in,
                                __nv_bfloat16* __restrict__ out,
                                int M, int K)
{
    int idx = blockIdx.x * blockDim.x + threadIdx.x;
    if (idx >= M * K) return;
    int row = idx / K;
    int k = idx - row * K;
    float x = in[idx];
    __nv_bfloat16 hi = __float2bfloat16_rn(x);
    __nv_bfloat16 lo = __float2bfloat16_rn(x - __bfloat162float(hi));
    size_t base = (size_t)row * 3 * K;
    out[base + k] = hi;
    out[base + K + k] = lo;
    out[base + 2 * K + k] = hi;
}

// ---------------------------------------------------------------------------
// Split + transpose: W[K,N] f32 -> B3[N,3K] bf16 = [hi | hi | lo]
// ---------------------------------------------------------------------------
__global__ __launch_bounds__(256) void conv_wT_kernel(
    const float* __restrict__ W, __nv_bfloat16* __restrict__ out, int K, int N)
{
    __shared__ float tile[32][33];
    const int tx = threadIdx.x & 31;
    const int ty = threadIdx.x >> 5;
    const int n0 = blockIdx.x * 32;
    const int k0 = blockIdx.y * 32;
    #pragma unroll
    for (int i = 0; i < 4; i++)
        tile[ty + i * 8][tx] = W[(size_t)(k0 + ty + i * 8) * N + n0 + tx];
    __syncthreads();
    #pragma unroll
    for (int i = 0; i < 4; i++) {
        const int n = n0 + ty + i * 8;
        const int k = k0 + tx;
        float x = tile[tx][ty + i * 8];
        __nv_bfloat16 hi = __float2bfloat16_rn(x);
        __nv_bfloat16 lo = __float2bfloat16_rn(x - __bfloat162float(hi));
        size_t base = (size_t)n * 3 * K;
        out[base + k] = hi;
        out[base + K + k] = hi;
        out[base + 2 * K + k] = lo;
    }
}

// ---------------------------------------------------------------------------
// Elementwise / LN / gather kernels
// ---------------------------------------------------------------------------
__global__ void gather_kernel(const int* __restrict__ x,
                              const float* __restrict__ emb,
                              float* __restrict__ out)
{
    int idx = blockIdx.x * blockDim.x + threadIdx.x;
    if (idx >= M4 * E_) return;
    int i = idx / E_;
    int e = idx - i * E_;
    out[idx] = emb[(size_t)x[i] * E_ + e];
}

__global__ void addpos_kernel(const float* __restrict__ xemb,
                              const float* __restrict__ pos11,
                              float* __restrict__ out)
{
    int idx = blockIdx.x * blockDim.x + threadIdx.x;
    if (idx >= M4 * H_) return;
    int i = idx / H_;
    int h = idx - i * H_;
    int s = i & (S_ - 1);
    out[idx] = xemb[idx] + pos11[(size_t)s * H_ + h];
}

__global__ __launch_bounds__(256) void ln_res_kernel(
    const float* __restrict__ res, const float* __restrict__ x,
    const float* __restrict__ bias, const float* __restrict__ scale,
    float* __restrict__ out)
{
    __shared__ float red[256];
    const int row = blockIdx.x;
    const int t = threadIdx.x;
    const float* xr = x + (size_t)row * H_;

    float lsum = 0.f;
    for (int i = t; i < H_; i += 256) lsum += xr[i];
    red[t] = lsum; __syncthreads();
    for (int s = 128; s > 0; s >>= 1) { if (t < s) red[t] += red[t + s]; __syncthreads(); }
    const float mean = red[0] * (1.0f / H_);
    __syncthreads();

    float lvar = 0.f;
    for (int i = t; i < H_; i += 256) { float d = xr[i] - mean; lvar += d * d; }
    red[t] = lvar; __syncthreads();
    for (int s = 128; s > 0; s >>= 1) { if (t < s) red[t] += red[t + s]; __syncthreads(); }
    const float rstd = rsqrtf(red[0] * (1.0f / H_) + 1e-6f);

    for (int i = t; i < H_; i += 256) {
        out[(size_t)row * H_ + i] =
            res[(size_t)row * H_ + i] + (xr[i] - mean) * rstd * scale[i] + bias[i];
    }
}

// ---------------------------------------------------------------------------
// Causal flash attention (fp32)
// ---------------------------------------------------------------------------
__global__ __launch_bounds__(64) void attn_kernel(
    const float* __restrict__ Q, const float* __restrict__ Kb,
    const float* __restrict__ Vb, float* __restrict__ O)
{
    __shared__ float Ks[64 * 64];
    __shared__ float Vs[64 * 64];
    __shared__ float Ss[64 * 65];

    const int qt = blockIdx.x;
    const int bh = blockIdx.y;
    const int b  = bh >> 4;
    const int n  = bh & 15;
    const int t  = threadIdx.x;
    const int qrow = qt * 64 + t;

    const float* qptr = Q + ((size_t)(b * S_ + qrow)) * H_ + n * HEAD_;
    float qreg[HEAD_];
    #pragma unroll
    for (int d = 0; d < HEAD_; d++) qreg[d] = qptr[d];

    float accv[HEAD_];
    #pragma unroll
    for (int d = 0; d < HEAD_; d++) accv[d] = 0.f;
    float mval = -1e30f, lval = 0.f;

    for (int kt = 0; kt <= qt; kt++) {
        const float* kptr = Kb + ((size_t)(b * S_ + kt * 64 + t)) * H_ + n * HEAD_;
        const float* vptr = Vb + ((size_t)(b * S_ + kt * 64 + t)) * H_ + n * HEAD_;
        #pragma unroll
        for (int d = 0; d < HEAD_; d += 4) {
            *reinterpret_cast<float4*>(&Ks[t * 64 + d]) =
                *reinterpret_cast<const float4*>(kptr + d);
            *reinterpret_cast<float4*>(&Vs[t * 64 + d]) =
                *reinterpret_cast<const float4*>(vptr + d);
        }
        __syncthreads();

        const int jmax = (kt == qt) ? (t + 1) : 64;

        float tmax = -1e30f;
        for (int j = 0; j < jmax; j++) {
            float s = 0.f;
            #pragma unroll
            for (int d = 0; d < HEAD_; d++) s += qreg[d] * Ks[j * 64 + d];
            Ss[t * 65 + j] = s;
            tmax = fmaxf(tmax, s);
        }

        const float mnew = fmaxf(mval, tmax);
        const float corr = __expf(mval - mnew);
        lval *= corr;
        #pragma unroll
        for (int d = 0; d < HEAD_; d++) accv[d] *= corr;

        for (int j = 0; j < jmax; j++) {
            const float p = __expf(Ss[t * 65 + j] - mnew);
            lval += p;
            #pragma unroll
            for (int d = 0; d < HEAD_; d++) accv[d] += p * Vs[j * 64 + d];
        }
        mval = mnew;
        __syncthreads();
    }

    const float inv = 1.f / lval;
    float* optr = O + ((size_t)(b * S_ + qrow)) * H_ + n * HEAD_;
    #pragma unroll
    for (int d = 0; d < HEAD_; d += 4) {
        float4 o;
        o.x = accv[d + 0] * inv;
        o.y = accv[d + 1] * inv;
        o.z = accv[d + 2] * inv;
        o.w = accv[d + 3] * inv;
        *reinterpret_cast<float4*>(optr + d) = o;
    }
}

// ---------------------------------------------------------------------------
// Launch helpers
// ---------------------------------------------------------------------------
static inline void run_gemm(const __nv_bfloat16* A3, const __nv_bfloat16* B3,
                            const float* bias, float* C,
                            int M, int N, int K3, float alpha, int relu)
{
    dim3 grid(M / GBM, N / GBN);
    gemm_bf16_kernel<<<grid, 256, GEMM_SMEM_BYTES>>>(A3, B3, bias, C, M, N, K3, alpha, relu);
}
static inline void run_conv_act(const float* in, __nv_bfloat16* out, int M, int K)
{
    conv_act_kernel<<<(M * K + 255) / 256, 256>>>(in, out, M, K);
}
static inline void run_conv_wT(const float* W, __nv_bfloat16* out, int K, int N)
{
    dim3 grid(N / 32, K / 32);
    conv_wT_kernel<<<grid, 256>>>(W, out, K, N);
}

extern "C" void kernel_launch(void* const* d_in, const int* in_sizes, int n_in,
                              void* d_out, int out_size)
{
    const int*   x            = (const int*)  d_in[0];
    const float* emb_decode   = (const float*)d_in[1];
    const float* W_dec_lin    = (const float*)d_in[2];
    const float* p_decoder    = (const float*)d_in[3];
    const float* x_emb_pos    = (const float*)d_in[4];
    const float* p_d_q        = (const float*)d_in[5];
    const float* p_d_k        = (const float*)d_in[6];
    const float* p_d_v        = (const float*)d_in[7];
    const float* p_d_c        = (const float*)d_in[8];
    const float* p_d_ff1      = (const float*)d_in[9];
    const float* p_d_ff2      = (const float*)d_in[10];
    const float* b_d_ff1      = (const float*)d_in[11];
    const float* b_d_ff2      = (const float*)d_in[12];
    const float* d_o_bias     = (const float*)d_in[13];
    const float* d_o_scale    = (const float*)d_in[14];
    const float* b_d_bias_1   = (const float*)d_in[15];
    const float* b_d_bias_2   = (const float*)d_in[16];
    const float* b_d_scale_1  = (const float*)d_in[17];
    const float* b_d_scale_2  = (const float*)d_in[18];
    float* out = (float*)d_out;

    const int m = L_ - 1;   // only the last layer's result is observable

    cudaFuncSetAttribute(gemm_bf16_kernel,
                         cudaFuncAttributeMaxDynamicSharedMemorySize, GEMM_SMEM_BYTES);

    float *Aemb, *xemb, *layerin, *q, *k, *v, *conc, *xmulti, *xself,
          *ffw1, *ffw2, *xffw, *decout;
    __nv_bfloat16 *a3_emb, *a3_li, *a3_conc, *a3_self, *a3_ffw1, *a3_dec;
    __nv_bfloat16 *w3_dec, *w3_q, *w3_k, *w3_v, *w3_c, *w3_ff1, *w3_ff2, *w3_pdec;
    cudaGetSymbolAddress((void**)&Aemb,    g_Aemb);
    cudaGetSymbolAddress((void**)&xemb,    g_xemb);
    cudaGetSymbolAddress((void**)&layerin, g_layerin);
    cudaGetSymbolAddress((void**)&q,       g_q);
    cudaGetSymbolAddress((void**)&k,       g_k);
    cudaGetSymbolAddress((void**)&v,       g_v);
    cudaGetSymbolAddress((void**)&conc,    g_conc);
    cudaGetSymbolAddress((void**)&xmulti,  g_xmulti);
    cudaGetSymbolAddress((void**)&xself,   g_xself);
    cudaGetSymbolAddress((void**)&ffw1,    g_ffw1);
    cudaGetSymbolAddress((void**)&ffw2,    g_ffw2);
    cudaGetSymbolAddress((void**)&xffw,    g_xffw);
    cudaGetSymbolAddress((void**)&decout,  g_decout);
    cudaGetSymbolAddress((void**)&a3_emb,  g_a3_emb);
    cudaGetSymbolAddress((void**)&a3_li,   g_a3_li);
    cudaGetSymbolAddress((void**)&a3_conc, g_a3_conc);
    cudaGetSymbolAddress((void**)&a3_self, g_a3_self);
    cudaGetSymbolAddress((void**)&a3_ffw1, g_a3_ffw1);
    cudaGetSymbolAddress((void**)&a3_dec,  g_a3_dec);
    cudaGetSymbolAddress((void**)&w3_dec,  g_w3_dec);
    cudaGetSymbolAddress((void**)&w3_q,    g_w3_q);
    cudaGetSymbolAddress((void**)&w3_k,    g_w3_k);
    cudaGetSymbolAddress((void**)&w3_v,    g_w3_v);
    cudaGetSymbolAddress((void**)&w3_c,    g_w3_c);
    cudaGetSymbolAddress((void**)&w3_ff1,  g_w3_ff1);
    cudaGetSymbolAddress((void**)&w3_ff2,  g_w3_ff2);
    cudaGetSymbolAddress((void**)&w3_pdec, g_w3_pdec);

    const float inv_sqrt_head = 0.125f;

    // weight conversions (split + transpose)
    run_conv_wT(W_dec_lin, w3_dec, E_, H_);
    run_conv_wT(p_d_q + (size_t)m * H_ * H_, w3_q, H_, H_);
    run_conv_wT(p_d_k + (size_t)m * H_ * H_, w3_k, H_, H_);
    run_conv_wT(p_d_v + (size_t)m * H_ * H_, w3_v, H_, H_);
    run_conv_wT(p_d_c + (size_t)m * H_ * H_, w3_c, H_, H_);
    run_conv_wT(p_d_ff1 + (size_t)m * H_ * FF_, w3_ff1, H_, FF_);
    run_conv_wT(p_d_ff2 + (size_t)m * FF_ * H_, w3_ff2, FF_, H_);
    run_conv_wT(p_decoder, w3_pdec, H_, V_);

    // 1. gather embeddings
    gather_kernel<<<(M4 * E_ + 255) / 256, 256>>>(x, emb_decode, Aemb);
    run_conv_act(Aemb, a3_emb, M4, E_);

    // 2. x_dec_embed = A_emb @ W_dec_lin
    run_gemm(a3_emb, w3_dec, nullptr, xemb, M4, H_, 3 * E_, 1.f, 0);

    // 3. layer_in = pos[11] + x_dec_embed
    addpos_kernel<<<(M4 * H_ + 255) / 256, 256>>>(
        xemb, x_emb_pos + (size_t)m * S_ * H_, layerin);
    run_conv_act(layerin, a3_li, M4, H_);

    // 4. Q/K/V projections (Q pre-scaled)
    run_gemm(a3_li, w3_q, nullptr, q, M4, H_, 3 * H_, inv_sqrt_head, 0);
    run_gemm(a3_li, w3_k, nullptr, k, M4, H_, 3 * H_, 1.f, 0);
    run_gemm(a3_li, w3_v, nullptr, v, M4, H_, 3 * H_, 1.f, 0);

    // 5. causal attention -> conc
    attn_kernel<<<dim3(S_ / 64, B_ * NH_), 64>>>(q, k, v, conc);
    run_conv_act(conc, a3_conc, M4, H_);

    // 6. x_multi = conc @ p_d_c
    run_gemm(a3_conc, w3_c, nullptr, xmulti, M4, H_, 3 * H_, 1.f, 0);

    // 7. x_self = layer_in + LN(x_multi)
    ln_res_kernel<<<M4, 256>>>(layerin, xmulti,
                               b_d_bias_1 + (size_t)m * H_,
                               b_d_scale_1 + (size_t)m * H_, xself);
    run_conv_act(xself, a3_self, M4, H_);

    // 8. FFN
    run_gemm(a3_self, w3_ff1, b_d_ff1 + (size_t)m * FF_, ffw1, M4, FF_, 3 * H_, 1.f, 1);
    run_conv_act(ffw1, a3_ffw1, M4, FF_);
    run_gemm(a3_ffw1, w3_ff2, b_d_ff2 + (size_t)m * H_, ffw2, M4, H_, 3 * FF_, 1.f, 0);

    // 9. x_ffw = x_self + LN(ffw2)
    ln_res_kernel<<<M4, 256>>>(xself, ffw2,
                               b_d_bias_2 + (size_t)m * H_,
                               b_d_scale_2 + (size_t)m * H_, xffw);

    // 10. dec_outputs = x_dec_embed + LN(x_ffw)
    ln_res_kernel<<<M4, 256>>>(xemb, xffw, d_o_bias, d_o_scale, decout);
    run_conv_act(decout, a3_dec, M4, H_);

    // 11. logits = dec_outputs @ p_decoder
    run_gemm(a3_dec, w3_pdec, nullptr, out, M4, V_, 3 * H_, 1.f, 0);
}

// round 7
// speedup vs baseline: 4.9690x; 1.1339x over previous
#include <cuda_runtime.h>
#include <cuda_bf16.h>
#include <cstdint>

// Problem constants
#define L_   12
#define NH_  16
#define H_   1024
#define FF_  4096
#define V_   32000
#define S_   1024
#define E_   128
#define B_   4
#define HEAD_ 64
#define M4   (B_ * S_)   // 4096 rows total

// Arch-feature dispatch: tcgen05 only legal in the sm_103a pass.
#if defined(__CUDA_ARCH__) && defined(__CUDA_ARCH_FEAT_SM103_ALL)
#define TC_PATH 1
#else
#define TC_PATH 0
#endif

// ---------------------------------------------------------------------------
// Scratch (device globals — allocation-free per harness rules)
// ---------------------------------------------------------------------------
__device__ float g_Aemb   [M4 * E_];
__device__ float g_xemb   [M4 * H_];
__device__ float g_layerin[M4 * H_];
__device__ float g_q      [M4 * H_];
__device__ float g_k      [M4 * H_];
__device__ float g_v      [M4 * H_];
__device__ float g_xmulti [M4 * H_];
__device__ float g_xself  [M4 * H_];
__device__ float g_ffw1   [M4 * FF_];
__device__ float g_ffw2   [M4 * H_];
__device__ float g_xffw   [M4 * H_];
__device__ float g_decout [M4 * H_];

// bf16 split-K3 operand buffers.  A' = [hi | lo | hi] (row-major, 3K cols),
// B' = [hi | hi | lo] as [N, 3K] (k-contiguous, i.e. transposed weight).
__device__ __align__(128) __nv_bfloat16 g_a3_emb [M4 * 3 * E_];
__device__ __align__(128) __nv_bfloat16 g_a3_li  [M4 * 3 * H_];
__device__ __align__(128) __nv_bfloat16 g_a3_conc[M4 * 3 * H_];
__device__ __align__(128) __nv_bfloat16 g_a3_self[M4 * 3 * H_];
__device__ __align__(128) __nv_bfloat16 g_a3_ffw1[(size_t)M4 * 3 * FF_];
__device__ __align__(128) __nv_bfloat16 g_a3_dec [M4 * 3 * H_];

__device__ __align__(128) __nv_bfloat16 g_w3_dec [H_ * 3 * E_];
__device__ __align__(128) __nv_bfloat16 g_w3_q   [H_ * 3 * H_];
__device__ __align__(128) __nv_bfloat16 g_w3_k   [H_ * 3 * H_];
__device__ __align__(128) __nv_bfloat16 g_w3_v   [H_ * 3 * H_];
__device__ __align__(128) __nv_bfloat16 g_w3_c   [H_ * 3 * H_];
__device__ __align__(128) __nv_bfloat16 g_w3_ff1 [(size_t)FF_ * 3 * H_];
__device__ __align__(128) __nv_bfloat16 g_w3_ff2 [(size_t)H_ * 3 * FF_];
__device__ __align__(128) __nv_bfloat16 g_w3_pdec[(size_t)V_ * 3 * H_];

// ---------------------------------------------------------------------------
// PTX helpers — baseline-legal
// ---------------------------------------------------------------------------
__device__ __forceinline__ uint32_t smem_u32(const void* p) {
    uint32_t a;
    asm("{ .reg .u64 t; cvta.to.shared.u64 t, %1; cvt.u32.u64 %0, t; }"
        : "=r"(a) : "l"(p));
    return a;
}
__device__ __forceinline__ void cp16(uint32_t dst, const void* src) {
    asm volatile("cp.async.cg.shared.global [%0], [%1], 16;"
                 :: "r"(dst), "l"(src) : "memory");
}
__device__ __forceinline__ void cp_commit() {
    asm volatile("cp.async.commit_group;" ::: "memory");
}
template <int N>
__device__ __forceinline__ void cp_wait() {
    asm volatile("cp.async.wait_group %0;" :: "n"(N) : "memory");
}
__device__ __forceinline__ uint32_t elect_one_pred() {
    uint32_t pred;
    asm volatile(
        "{\n\t.reg .pred p;\n\telect.sync _|p, 0xFFFFFFFF;\n\t"
        "selp.b32 %0, 1, 0, p;\n\t}" : "=r"(pred));
    return pred;
}
// legacy m16n8k16 bf16 MMA, fp32 accumulate (sm_80+)
__device__ __forceinline__ void mma16(float* d, const uint32_t* a, const uint32_t* b) {
    asm volatile(
        "mma.sync.aligned.m16n8k16.row.col.f32.bf16.bf16.f32 "
        "{%0,%1,%2,%3}, {%4,%5,%6,%7}, {%8,%9}, {%0,%1,%2,%3};"
        : "+f"(d[0]), "+f"(d[1]), "+f"(d[2]), "+f"(d[3])
        : "r"(a[0]), "r"(a[1]), "r"(a[2]), "r"(a[3]),
          "r"(b[0]), "r"(b[1]));
}
// pack two f32 into bf16x2 (lo_elem -> low half)
__device__ __forceinline__ uint32_t pack_bf16x2(float lo_elem, float hi_elem) {
    uint32_t r;
    asm("cvt.rn.bf16x2.f32 %0, %1, %2;" : "=r"(r) : "f"(hi_elem), "f"(lo_elem));
    return r;
}
__device__ __forceinline__ uint32_t pack_raw(__nv_bfloat16 lo, __nv_bfloat16 hi) {
    return (uint32_t)__bfloat16_as_ushort(lo) | ((uint32_t)__bfloat16_as_ushort(hi) << 16);
}

#define SMEM_SWIZZLE_128B(o) ((o) ^ (((o) >> 3) & 0x70))

#if TC_PATH
// ---- tcgen05 helpers (only compiled in the sm_103a pass) ----
#define TCGEN05_ALLOC(smem_addr, nCols) \
    asm volatile("tcgen05.alloc.cta_group::1.sync.aligned.shared::cta.b32 [%0], %1;" \
                 :: "r"((uint32_t)(smem_addr)), "r"((uint32_t)(nCols)) : "memory")
#define TCGEN05_DEALLOC(tmem_addr, nCols) \
    asm volatile("tcgen05.dealloc.cta_group::1.sync.aligned.b32 %0, %1;" \
                 :: "r"(tmem_addr), "r"((uint32_t)(nCols)))
#define TCGEN05_RELINQUISH() \
    asm volatile("tcgen05.relinquish_alloc_permit.cta_group::1.sync.aligned;")
#define TCGEN05_COMMIT(mbar) \
    asm volatile("tcgen05.commit.cta_group::1.mbarrier::arrive::one.shared::cluster.b64 [%0];" \
                 :: "r"((uint32_t)(mbar)) : "memory")
#define TCGEN05_FENCE_AFTER() \
    asm volatile("tcgen05.fence::after_thread_sync;" ::: "memory")
#define TCGEN05_FENCE_BEFORE() \
    asm volatile("tcgen05.fence::before_thread_sync;" ::: "memory")
#define TCGEN05_WAIT_LD() \
    asm volatile("tcgen05.wait::ld.sync.aligned;" ::: "memory")
#define MBARRIER_INIT(mbar, cnt) \
    asm volatile("mbarrier.init.shared.b64 [%0], %1;" \
                 :: "r"((uint32_t)(mbar)), "r"((uint32_t)(cnt)) : "memory")
#define MBARRIER_INVAL(mbar) \
    asm volatile("mbarrier.inval.shared.b64 [%0];" :: "r"((uint32_t)(mbar)) : "memory")
#define FENCE_PROXY_ASYNC() \
    asm volatile("fence.proxy.async.shared::cta;" ::: "memory")

#define MBARRIER_WAIT_PARITY(mbar_smem_addr, phase_parity) do { \
    uint32_t _mbar = (uint32_t)(mbar_smem_addr); \
    uint32_t _parity = (uint32_t)(phase_parity); \
    uint32_t _done; \
    asm volatile("{\n\t.reg .pred p;\n\t" \
        "mbarrier.try_wait.parity.acquire.cta.shared::cta.b64 p, [%1], %2;\n\t" \
        "selp.b32 %0, 1, 0, p;\n\t}" \
        : "=r"(_done) : "r"(_mbar), "r"(_parity) : "memory"); \
    if (!_done) { \
        asm volatile("{\n\t.reg .pred P1;\n\t" \
            "WAIT_LOOP_%=:\n\t" \
            "mbarrier.try_wait.parity.acquire.cta.shared::cta.b64 P1, [%0], %1, 0x989680;\n\t" \
            "@P1 bra.uni WAIT_DONE_%=;\n\t" \
            "bra.uni WAIT_LOOP_%=;\n\t" \
            "WAIT_DONE_%=:\n\t}" \
            :: "r"(_mbar), "r"(_parity) : "memory"); \
    } \
} while(0)

#define TCGEN05_LD_32X32B_X32(r, tmem_addr) \
    asm volatile( \
        "tcgen05.ld.sync.aligned.32x32b.x32.b32 " \
        "{%0, %1, %2, %3, %4, %5, %6, %7, " \
        " %8, %9, %10, %11, %12, %13, %14, %15, " \
        " %16, %17, %18, %19, %20, %21, %22, %23, " \
        " %24, %25, %26, %27, %28, %29, %30, %31}, [%32];" \
        : "=r"((r)[0]),  "=r"((r)[1]),  "=r"((r)[2]),  "=r"((r)[3]), \
          "=r"((r)[4]),  "=r"((r)[5]),  "=r"((r)[6]),  "=r"((r)[7]), \
          "=r"((r)[8]),  "=r"((r)[9]),  "=r"((r)[10]), "=r"((r)[11]), \
          "=r"((r)[12]), "=r"((r)[13]), "=r"((r)[14]), "=r"((r)[15]), \
          "=r"((r)[16]), "=r"((r)[17]), "=r"((r)[18]), "=r"((r)[19]), \
          "=r"((r)[20]), "=r"((r)[21]), "=r"((r)[22]), "=r"((r)[23]), \
          "=r"((r)[24]), "=r"((r)[25]), "=r"((r)[26]), "=r"((r)[27]), \
          "=r"((r)[28]), "=r"((r)[29]), "=r"((r)[30]), "=r"((r)[31]) \
        : "r"(tmem_addr))

static constexpr uint64_t SMEM_DESC_BASE_SW128 =
    (uint64_t(2) << 61) | (uint64_t(1) << 46) | (uint64_t(64) << 32) | (uint64_t(1) << 16);
#define MAKE_SMEM_DESC(addr) (SMEM_DESC_BASE_SW128 | ((uint64_t)((addr) >> 4) & 0x3FFF))

__device__ __forceinline__ void mma_bf16_ss(uint32_t d_tmem, uint64_t a_desc,
                                            uint64_t b_desc, uint32_t idesc,
                                            uint32_t enable_d) {
    uint32_t z = 0;
    asm volatile(
        "{\n\t.reg .pred p;\n\tsetp.ne.u32 p, %5, 0;\n\t"
        "tcgen05.mma.cta_group::1.kind::f16 [%0], %1, %2, %3, {%4, %4, %4, %4}, p;\n\t}"
        :: "r"(d_tmem), "l"(a_desc), "l"(b_desc), "r"(idesc), "r"(z), "r"(enable_d)
        : "memory");
}
#endif // TC_PATH

// ---------------------------------------------------------------------------
// GEMM over expanded K3: C[M,N] = alpha*(A3[M,K3] @ B3[N,K3]^T) + bias + relu
// Optional out3: writes [hi|lo|hi] split bf16 (row stride 3N) INSTEAD of C.
// grid (M/128, N/128), 256 threads, dynamic smem GEMM_SMEM_BYTES (both paths).
// ---------------------------------------------------------------------------
#define GBM 128
#define GBN 128
#define GBK 64
#define RSTRIDE 36
#define ABUF (128 * RSTRIDE)
#define BBUF (128 * RSTRIDE)
#define GEMM_SMEM_BYTES 99328   // 1024 + 6*16384 (tc 3-stage); legacy needs 73728

__global__ __launch_bounds__(256, 2) void gemm_bf16_kernel(
    const __nv_bfloat16* __restrict__ A3, const __nv_bfloat16* __restrict__ B3,
    const float* __restrict__ bias, float* __restrict__ C,
    __nv_bfloat16* __restrict__ out3,
    int M, int N, int K3, float alpha, int do_relu)
{
#if TC_PATH
    // =================== tcgen05 path, 3-stage pipeline ===================
    extern __shared__ char smc[];
    const uint32_t smb = smem_u32(smc);
    const int tid = threadIdx.x;
    const int wid = tid >> 5, lane = tid & 31;
    const int m0 = blockIdx.x * GBM;
    const int n0 = blockIdx.y * GBN;

    const uint32_t sa[3] = {1024u, 1024u + 16384u, 1024u + 32768u};
    const uint32_t sb[3] = {1024u + 49152u, 1024u + 65536u, 1024u + 81920u};
    const uint32_t mb[3] = {smb + 8u, smb + 16u, smb + 24u};

    if (wid == 0) TCGEN05_ALLOC(smb, 128);
    if (tid == 0) { MBARRIER_INIT(mb[0], 1); MBARRIER_INIT(mb[1], 1); MBARRIER_INIT(mb[2], 1); }
    __syncthreads();
    uint32_t tmem;
    asm volatile("ld.shared.b32 %0, [%1];" : "=r"(tmem) : "r"(smb));
    if (wid == 0) TCGEN05_RELINQUISH();

    const uint32_t IDESC =
        (1u << 4) | (1u << 7) | (1u << 10) | ((GBN / 8) << 17) | ((GBM / 16) << 24);

    const int NC = K3 / GBK;
    const int r0s = tid >> 3;
    const int c8 = tid & 7;
    const __nv_bfloat16* abase = A3 + (size_t)(m0 + r0s) * K3 + c8 * 8;
    const __nv_bfloat16* bbase = B3 + (size_t)(n0 + r0s) * K3 + c8 * 8;
    const uint32_t swoff[4] = {
        SMEM_SWIZZLE_128B((uint32_t)((r0s +  0) * 128 + c8 * 16)),
        SMEM_SWIZZLE_128B((uint32_t)((r0s + 32) * 128 + c8 * 16)),
        SMEM_SWIZZLE_128B((uint32_t)((r0s + 64) * 128 + c8 * 16)),
        SMEM_SWIZZLE_128B((uint32_t)((r0s + 96) * 128 + c8 * 16))};

    auto stage_chunk = [&](int chunk, int buf) {
        #pragma unroll
        for (int it = 0; it < 4; it++) {
            cp16(smb + sa[buf] + swoff[it], abase + (size_t)it * 32 * K3 + chunk * GBK);
            cp16(smb + sb[buf] + swoff[it], bbase + (size_t)it * 32 * K3 + chunk * GBK);
        }
        cp_commit();
    };

    int ph[3] = {0, 0, 0};
    stage_chunk(0, 0);
    stage_chunk(1, 1);

    for (int c = 0; c < NC; c++) {
        const int b = c % 3;
        if (c + 2 < NC) {
            const int nb = (c + 2) % 3;
            if (c >= 1) { MBARRIER_WAIT_PARITY(mb[nb], ph[nb]); ph[nb] ^= 1; }
            stage_chunk(c + 2, nb);
            cp_wait<2>();
        } else if (c + 1 < NC) {
            cp_wait<1>();
        } else {
            cp_wait<0>();
        }
        __syncthreads();
        if (wid == 0 && elect_one_pred()) {
            FENCE_PROXY_ASYNC();
            const uint64_t ad = MAKE_SMEM_DESC(smb + sa[b]);
            const uint64_t bd = MAKE_SMEM_DESC(smb + sb[b]);
            #pragma unroll
            for (int ks = 0; ks < 4; ks++)
                mma_bf16_ss(tmem, ad + ks * 2, bd + ks * 2, IDESC,
                            (c > 0 || ks > 0) ? 1u : 0u);
            TCGEN05_COMMIT(mb[b]);
        }
    }
    MBARRIER_WAIT_PARITY(mb[(NC - 1) % 3], ph[(NC - 1) % 3]);
    TCGEN05_FENCE_AFTER();

    if (wid < 4) {
        const uint32_t lofs = (uint32_t)wid << 21;
        const int row = m0 + wid * 32 + lane;
        #pragma unroll
        for (int j = 0; j < 4; j++) {
            uint32_t r[32];
            TCGEN05_LD_32X32B_X32(r, tmem + j * 32 + lofs);
            TCGEN05_WAIT_LD();
            const float* bp = bias ? (bias + n0 + j * 32) : nullptr;
            if (out3) {
                __nv_bfloat16* op = out3 + (size_t)row * 3 * N + n0 + j * 32;
                #pragma unroll
                for (int q = 0; q < 32; q += 2) {
                    float v0 = __uint_as_float(r[q + 0]) * alpha;
                    float v1 = __uint_as_float(r[q + 1]) * alpha;
                    if (bp) { v0 += bp[q]; v1 += bp[q + 1]; }
                    if (do_relu) { v0 = fmaxf(v0, 0.f); v1 = fmaxf(v1, 0.f); }
                    __nv_bfloat16 h0 = __float2bfloat16_rn(v0);
                    __nv_bfloat16 h1 = __float2bfloat16_rn(v1);
                    float l0f = v0 - __bfloat162float(h0);
                    float l1f = v1 - __bfloat162float(h1);
                    uint32_t hp = pack_raw(h0, h1);
                    uint32_t lp = pack_bf16x2(l0f, l1f);
                    *reinterpret_cast<uint32_t*>(op + q) = hp;
                    *reinterpret_cast<uint32_t*>(op + N + q) = lp;
                    *reinterpret_cast<uint32_t*>(op + 2 * N + q) = hp;
                }
            } else {
                float* cp = C + (size_t)row * N + n0 + j * 32;
                #pragma unroll
                for (int q = 0; q < 32; q += 4) {
                    float v0 = __uint_as_float(r[q + 0]) * alpha;
                    float v1 = __uint_as_float(r[q + 1]) * alpha;
                    float v2 = __uint_as_float(r[q + 2]) * alpha;
                    float v3 = __uint_as_float(r[q + 3]) * alpha;
                    if (bp) { v0 += bp[q]; v1 += bp[q + 1]; v2 += bp[q + 2]; v3 += bp[q + 3]; }
                    if (do_relu) {
                        v0 = fmaxf(v0, 0.f); v1 = fmaxf(v1, 0.f);
                        v2 = fmaxf(v2, 0.f); v3 = fmaxf(v3, 0.f);
                    }
                    float4 o = {v0, v1, v2, v3};
                    *reinterpret_cast<float4*>(cp + q) = o;
                }
            }
        }
        TCGEN05_FENCE_BEFORE();
    }
    __syncthreads();
    if (tid == 0) { MBARRIER_INVAL(mb[0]); MBARRIER_INVAL(mb[1]); MBARRIER_INVAL(mb[2]); }
    __syncthreads();
    if (wid == 0) TCGEN05_DEALLOC(tmem, 128);

#else
    // =================== legacy HMMA fallback (compute_103) ===================
    extern __shared__ uint32_t sm[];
    const uint32_t smb = smem_u32(sm);
    const int tid = threadIdx.x;
    const int wid = tid >> 5, lane = tid & 31;
    const int g = lane >> 2, c4 = lane & 3;
    const int warp_m = wid >> 2;
    const int warp_n = wid & 3;
    const int m0 = blockIdx.x * GBM;
    const int n0 = blockIdx.y * GBN;

    const int srow = tid >> 1, spart = tid & 1;
    const __nv_bfloat16* aptr = A3 + (size_t)(m0 + srow) * K3 + spart * 32;
    const __nv_bfloat16* bptr = B3 + (size_t)(n0 + srow) * K3 + spart * 32;
    const uint32_t as_base = smb + (srow * RSTRIDE + spart * 16) * 4;
    const uint32_t bs_base = smb + (2 * ABUF + srow * RSTRIDE + spart * 16) * 4;

    const int NC = K3 / GBK;

    float acc[4][4][4];
    #pragma unroll
    for (int i = 0; i < 4; i++)
        #pragma unroll
        for (int j = 0; j < 4; j++)
            #pragma unroll
            for (int q = 0; q < 4; q++) acc[i][j][q] = 0.f;

    #pragma unroll
    for (int q = 0; q < 4; q++) cp16(as_base + q * 16, aptr + q * 8);
    #pragma unroll
    for (int q = 0; q < 4; q++) cp16(bs_base + q * 16, bptr + q * 8);
    cp_commit();

    for (int c = 0; c < NC; c++) {
        if (c + 1 < NC) {
            const int nb = (c + 1) & 1;
            const __nv_bfloat16* ap = aptr + (c + 1) * GBK;
            const __nv_bfloat16* bp = bptr + (c + 1) * GBK;
            #pragma unroll
            for (int q = 0; q < 4; q++)
                cp16(as_base + nb * ABUF * 4 + q * 16, ap + q * 8);
            #pragma unroll
            for (int q = 0; q < 4; q++)
                cp16(bs_base + nb * BBUF * 4 + q * 16, bp + q * 8);
            cp_commit();
            cp_wait<1>();
        } else {
            cp_wait<0>();
        }
        __syncthreads();

        const uint32_t* ab = sm + (c & 1) * ABUF;
        const uint32_t* bb = sm + 2 * ABUF + (c & 1) * BBUF;

        #pragma unroll
        for (int ks = 0; ks < 4; ks++) {
            const int kb = ks * 8;
            uint32_t af[4][4], bf[4][2];
            #pragma unroll
            for (int i = 0; i < 4; i++) {
                const uint32_t* p = ab + (warp_m * 64 + i * 16 + g) * RSTRIDE + kb + c4;
                af[i][0] = p[0];
                af[i][1] = p[8 * RSTRIDE];
                af[i][2] = p[4];
                af[i][3] = p[8 * RSTRIDE + 4];
            }
            #pragma unroll
            for (int j = 0; j < 4; j++) {
                const uint32_t* p = bb + (warp_n * 32 + j * 8 + g) * RSTRIDE + kb + c4;
                bf[j][0] = p[0];
                bf[j][1] = p[4];
            }
            #pragma unroll
            for (int i = 0; i < 4; i++)
                #pragma unroll
                for (int j = 0; j < 4; j++)
                    mma16(acc[i][j], af[i], bf[j]);
        }
        __syncthreads();
    }

    #pragma unroll
    for (int i = 0; i < 4; i++) {
        #pragma unroll
        for (int j = 0; j < 4; j++) {
            const int col = n0 + warp_n * 32 + j * 8 + c4 * 2;
            float b0v = 0.f, b1v = 0.f;
            if (bias) { b0v = bias[col]; b1v = bias[col + 1]; }
            float v0 = acc[i][j][0] * alpha + b0v;
            float v1 = acc[i][j][1] * alpha + b1v;
            float v2 = acc[i][j][2] * alpha + b0v;
            float v3 = acc[i][j][3] * alpha + b1v;
            if (do_relu) {
                v0 = fmaxf(v0, 0.f); v1 = fmaxf(v1, 0.f);
                v2 = fmaxf(v2, 0.f); v3 = fmaxf(v3, 0.f);
            }
            const int ra = m0 + warp_m * 64 + i * 16 + g;
            if (out3) {
                __nv_bfloat16 h0 = __float2bfloat16_rn(v0), h1 = __float2bfloat16_rn(v1);
                __nv_bfloat16 h2 = __float2bfloat16_rn(v2), h3 = __float2bfloat16_rn(v3);
                uint32_t hp0 = pack_raw(h0, h1), hp1 = pack_raw(h2, h3);
                uint32_t lp0 = pack_bf16x2(v0 - __bfloat162float(h0), v1 - __bfloat162float(h1));
                uint32_t lp1 = pack_bf16x2(v2 - __bfloat162float(h2), v3 - __bfloat162float(h3));
                __nv_bfloat16* o0 = out3 + (size_t)ra * 3 * N + col;
                __nv_bfloat16* o1 = out3 + (size_t)(ra + 8) * 3 * N + col;
                *reinterpret_cast<uint32_t*>(o0) = hp0;
                *reinterpret_cast<uint32_t*>(o0 + N) = lp0;
                *reinterpret_cast<uint32_t*>(o0 + 2 * N) = hp0;
                *reinterpret_cast<uint32_t*>(o1) = hp1;
                *reinterpret_cast<uint32_t*>(o1 + N) = lp1;
                *reinterpret_cast<uint32_t*>(o1 + 2 * N) = hp1;
            } else {
                float2 lo = {v0, v1}, hi = {v2, v3};
                *reinterpret_cast<float2*>(C + (size_t)ra * N + col) = lo;
                *reinterpret_cast<float2*>(C + (size_t)(ra + 8) * N + col) = hi;
            }
        }
    }
#endif
}

// ---------------------------------------------------------------------------
// Tensor-core split-bf16 causal flash attention.
// Block: 128 threads (4 warps), one 64-row q tile of one head. grid (16, 64).
// Writes split-bf16 conc3 directly ([hi|lo|hi], row stride 3H).
// ---------------------------------------------------------------------------
#define AT_STRIDE 136   // bf16 per smem row (128 data + 8 pad)
#define ATT_SMEM  (3 * 64 * AT_STRIDE * 2)   // 52224 B

__global__ __launch_bounds__(128, 3) void attn_mma_kernel(
    const float* __restrict__ Q, const float* __restrict__ Kg,
    const float* __restrict__ Vg, __nv_bfloat16* __restrict__ conc3)
{
    extern __shared__ __nv_bfloat16 sh[];
    __nv_bfloat16* Qs = sh;                    // [64][AT_STRIDE]: cols 0-63 hi, 64-127 lo
    __nv_bfloat16* Ks = sh + 64 * AT_STRIDE;   // same layout (key rows)
    __nv_bfloat16* Vs = sh + 128 * AT_STRIDE;  // transposed: row d, col token (hi), 64+token (lo)

    const int qt = blockIdx.x;
    const int bh = blockIdx.y;
    const int b = bh >> 4, n = bh & 15;
    const int tid = threadIdx.x;
    const int wid = tid >> 5, lane = tid & 31;
    const int g = lane >> 2, c4 = lane & 3;

    // stage Q once
    {
        const int r = tid >> 1;
        const int dbase = (tid & 1) * 32;
        const float* qp = Q + ((size_t)(b * S_ + qt * 64 + r)) * H_ + n * 64 + dbase;
        #pragma unroll
        for (int i = 0; i < 32; i += 4) {
            float4 f = *reinterpret_cast<const float4*>(qp + i);
            float vals[4] = {f.x, f.y, f.z, f.w};
            #pragma unroll
            for (int e = 0; e < 4; e++) {
                __nv_bfloat16 hi = __float2bfloat16_rn(vals[e]);
                Qs[r * AT_STRIDE + dbase + i + e] = hi;
                Qs[r * AT_STRIDE + 64 + dbase + i + e] =
                    __float2bfloat16_rn(vals[e] - __bfloat162float(hi));
            }
        }
    }

    const int row0 = wid * 16 + g;   // S-tile row for c0/c1 (c2/c3 -> row0+8)
    float m0 = -1e30f, m1 = -1e30f, l0 = 0.f, l1 = 0.f;
    float o[8][4];
    #pragma unroll
    for (int j = 0; j < 8; j++)
        #pragma unroll
        for (int q = 0; q < 4; q++) o[j][q] = 0.f;

    for (int kt = 0; kt <= qt; kt++) {
        __syncthreads();
        // stage K, V
        {
            const int r = tid >> 1;
            const int dbase = (tid & 1) * 32;
            const float* kp = Kg + ((size_t)(b * S_ + kt * 64 + r)) * H_ + n * 64 + dbase;
            const float* vp = Vg + ((size_t)(b * S_ + kt * 64 + r)) * H_ + n * 64 + dbase;
            #pragma unroll
            for (int i = 0; i < 32; i += 4) {
                float4 fk = *reinterpret_cast<const float4*>(kp + i);
                float4 fv = *reinterpret_cast<const float4*>(vp + i);
                float kv[4] = {fk.x, fk.y, fk.z, fk.w};
                float vv[4] = {fv.x, fv.y, fv.z, fv.w};
                #pragma unroll
                for (int e = 0; e < 4; e++) {
                    const int d = dbase + i + e;
                    __nv_bfloat16 kh = __float2bfloat16_rn(kv[e]);
                    Ks[r * AT_STRIDE + d] = kh;
                    Ks[r * AT_STRIDE + 64 + d] =
                        __float2bfloat16_rn(kv[e] - __bfloat162float(kh));
                    __nv_bfloat16 vh = __float2bfloat16_rn(vv[e]);
                    Vs[d * AT_STRIDE + r] = vh;
                    Vs[d * AT_STRIDE + 64 + r] =
                        __float2bfloat16_rn(vv[e] - __bfloat162float(vh));
                }
            }
        }
        __syncthreads();

        // S = Q·K^T, 3-term split: (Qhi,Khi), (Qlo,Khi), (Qhi,Klo)
        float s[8][4];
        #pragma unroll
        for (int j = 0; j < 8; j++)
            #pragma unroll
            for (int q = 0; q < 4; q++) s[j][q] = 0.f;

        #pragma unroll
        for (int phs = 0; phs < 3; phs++) {
            const int aoff = (phs == 1) ? 64 : 0;
            const int boff = (phs == 2) ? 64 : 0;
            #pragma unroll
            for (int ks = 0; ks < 4; ks++) {
                uint32_t a[4];
                const __nv_bfloat16* ap = Qs + row0 * AT_STRIDE + aoff + ks * 16 + c4 * 2;
                a[0] = *reinterpret_cast<const uint32_t*>(ap);
                a[1] = *reinterpret_cast<const uint32_t*>(ap + 8 * AT_STRIDE);
                a[2] = *reinterpret_cast<const uint32_t*>(ap + 8);
                a[3] = *reinterpret_cast<const uint32_t*>(ap + 8 * AT_STRIDE + 8);
                #pragma unroll
                for (int j = 0; j < 8; j++) {
                    uint32_t bf[2];
                    const __nv_bfloat16* bp =
                        Ks + (8 * j + g) * AT_STRIDE + boff + ks * 16 + c4 * 2;
                    bf[0] = *reinterpret_cast<const uint32_t*>(bp);
                    bf[1] = *reinterpret_cast<const uint32_t*>(bp + 8);
                    mma16(s[j], a, bf);
                }
            }
        }

        // causal mask on diagonal tile
        if (kt == qt) {
            #pragma unroll
            for (int j = 0; j < 8; j++) {
                const int colb = 8 * j + 2 * c4;
                if (colb     > row0)     s[j][0] = -1e30f;
                if (colb + 1 > row0)     s[j][1] = -1e30f;
                if (colb     > row0 + 8) s[j][2] = -1e30f;
                if (colb + 1 > row0 + 8) s[j][3] = -1e30f;
            }
        }

        // online softmax
        float rm0 = -1e30f, rm1 = -1e30f;
        #pragma unroll
        for (int j = 0; j < 8; j++) {
            rm0 = fmaxf(rm0, fmaxf(s[j][0], s[j][1]));
            rm1 = fmaxf(rm1, fmaxf(s[j][2], s[j][3]));
        }
        rm0 = fmaxf(rm0, __shfl_xor_sync(0xFFFFFFFFu, rm0, 1));
        rm0 = fmaxf(rm0, __shfl_xor_sync(0xFFFFFFFFu, rm0, 2));
        rm1 = fmaxf(rm1, __shfl_xor_sync(0xFFFFFFFFu, rm1, 1));
        rm1 = fmaxf(rm1, __shfl_xor_sync(0xFFFFFFFFu, rm1, 2));
        const float mn0 = fmaxf(m0, rm0), mn1 = fmaxf(m1, rm1);
        const float cr0 = __expf(m0 - mn0), cr1 = __expf(m1 - mn1);
        m0 = mn0; m1 = mn1;

        float ps0 = 0.f, ps1 = 0.f;
        uint32_t phi[8][2], plo[8][2];
        #pragma unroll
        for (int j = 0; j < 8; j++) {
            float p0 = __expf(s[j][0] - mn0);
            float p1 = __expf(s[j][1] - mn0);
            float p2 = __expf(s[j][2] - mn1);
            float p3 = __expf(s[j][3] - mn1);
            ps0 += p0 + p1; ps1 += p2 + p3;
            __nv_bfloat16 h0 = __float2bfloat16_rn(p0), h1 = __float2bfloat16_rn(p1);
            __nv_bfloat16 h2 = __float2bfloat16_rn(p2), h3 = __float2bfloat16_rn(p3);
            phi[j][0] = pack_raw(h0, h1);
            phi[j][1] = pack_raw(h2, h3);
            plo[j][0] = pack_bf16x2(p0 - __bfloat162float(h0), p1 - __bfloat162float(h1));
            plo[j][1] = pack_bf16x2(p2 - __bfloat162float(h2), p3 - __bfloat162float(h3));
        }
        ps0 += __shfl_xor_sync(0xFFFFFFFFu, ps0, 1);
        ps0 += __shfl_xor_sync(0xFFFFFFFFu, ps0, 2);
        ps1 += __shfl_xor_sync(0xFFFFFFFFu, ps1, 1);
        ps1 += __shfl_xor_sync(0xFFFFFFFFu, ps1, 2);
        l0 = l0 * cr0 + ps0;
        l1 = l1 * cr1 + ps1;
        #pragma unroll
        for (int j = 0; j < 8; j++) {
            o[j][0] *= cr0; o[j][1] *= cr0;
            o[j][2] *= cr1; o[j][3] *= cr1;
        }

        // O += P·V, 3-term split: (Phi,Vhi), (Plo,Vhi), (Phi,Vlo)
        #pragma unroll
        for (int phs = 0; phs < 3; phs++) {
            const int voff = (phs == 2) ? 64 : 0;
            #pragma unroll
            for (int ks = 0; ks < 4; ks++) {
                uint32_t a[4];
                if (phs == 1) {
                    a[0] = plo[2 * ks][0]; a[1] = plo[2 * ks][1];
                    a[2] = plo[2 * ks + 1][0]; a[3] = plo[2 * ks + 1][1];
                } else {
                    a[0] = phi[2 * ks][0]; a[1] = phi[2 * ks][1];
                    a[2] = phi[2 * ks + 1][0]; a[3] = phi[2 * ks + 1][1];
                }
                #pragma unroll
                for (int j = 0; j < 8; j++) {
                    uint32_t bf[2];
                    const __nv_bfloat16* bp =
                        Vs + (8 * j + g) * AT_STRIDE + voff + ks * 16 + c4 * 2;
                    bf[0] = *reinterpret_cast<const uint32_t*>(bp);
                    bf[1] = *reinterpret_cast<const uint32_t*>(bp + 8);
                    mma16(o[j], a, bf);
                }
            }
        }
    }

    // epilogue: normalize + split-bf16 store
    const float inv0 = 1.f / l0, inv1 = 1.f / l1;
    const size_t r0 = (size_t)(b * S_ + qt * 64 + row0);
    __nv_bfloat16* o0 = conc3 + r0 * 3 * H_;
    __nv_bfloat16* o1 = conc3 + (r0 + 8) * 3 * H_;
    #pragma unroll
    for (int j = 0; j < 8; j++) {
        const int col = n * 64 + 8 * j + 2 * c4;
        float v0 = o[j][0] * inv0, v1 = o[j][1] * inv0;
        float v2 = o[j][2] * inv1, v3 = o[j][3] * inv1;
        __nv_bfloat16 h0 = __float2bfloat16_rn(v0), h1 = __float2bfloat16_rn(v1);
        __nv_bfloat16 h2 = __float2bfloat16_rn(v2), h3 = __float2bfloat16_rn(v3);
        uint32_t hp0 = pack_raw(h0, h1), hp1 = pack_raw(h2, h3);
        uint32_t lp0 = pack_bf16x2(v0 - __bfloat162float(h0), v1 - __bfloat162float(h1));
        uint32_t lp1 = pack_bf16x2(v2 - __bfloat162float(h2), v3 - __bfloat162float(h3));
        *reinterpret_cast<uint32_t*>(o0 + col) = hp0;
        *reinterpret_cast<uint32_t*>(o0 + H_ + col) = lp0;
        *reinterpret_cast<uint32_t*>(o0 + 2 * H_ + col) = hp0;
        *reinterpret_cast<uint32_t*>(o1 + col) = hp1;
        *reinterpret_cast<uint32_t*>(o1 + H_ + col) = lp1;
        *reinterpret_cast<uint32_t*>(o1 + 2 * H_ + col) = hp1;
    }
}

// ---------------------------------------------------------------------------
// Split conversion: act[M,K] f32 -> A3[M,3K] bf16 = [hi | lo | hi]
// ---------------------------------------------------------------------------
__global__ void conv_act_kernel(const float* __restrict__ in,
                                __nv_bfloat16* __restrict__ out,
                                int M, int K)
{
    int idx = blockIdx.x * blockDim.x + threadIdx.x;
    if (idx >= M * K) return;
    int row = idx / K;
    int k = idx - row * K;
    float x = in[idx];
    __nv_bfloat16 hi = __float2bfloat16_rn(x);
    __nv_bfloat16 lo = __float2bfloat16_rn(x - __bfloat162float(hi));
    size_t base = (size_t)row * 3 * K;
    out[base + k] = hi;
    out[base + K + k] = lo;
    out[base + 2 * K + k] = hi;
}

// ---------------------------------------------------------------------------
// Split + transpose: W[K,N] f32 -> B3[N,3K] bf16 = [hi | hi | lo]
// ---------------------------------------------------------------------------
__global__ __launch_bounds__(256) void conv_wT_kernel(
    const float* __restrict__ W, __nv_bfloat16* __restrict__ out, int K, int N)
{
    __shared__ float tile[32][33];
    const int tx = threadIdx.x & 31;
    const int ty = threadIdx.x >> 5;
    const int n0 = blockIdx.x * 32;
    const int k0 = blockIdx.y * 32;
    #pragma unroll
    for (int i = 0; i < 4; i++)
        tile[ty + i * 8][tx] = W[(size_t)(k0 + ty + i * 8) * N + n0 + tx];
    __syncthreads();
    #pragma unroll
    for (int i = 0; i < 4; i++) {
        const int nn = n0 + ty + i * 8;
        const int k = k0 + tx;
        float x = tile[tx][ty + i * 8];
        __nv_bfloat16 hi = __float2bfloat16_rn(x);
        __nv_bfloat16 lo = __float2bfloat16_rn(x - __bfloat162float(hi));
        size_t base = (size_t)nn * 3 * K;
        out[base + k] = hi;
        out[base + K + k] = hi;
        out[base + 2 * K + k] = lo;
    }
}

// ---------------------------------------------------------------------------
// Elementwise / LN / gather (with optional fused split-bf16 output)
// ---------------------------------------------------------------------------
__global__ void gather_kernel(const int* __restrict__ x,
                              const float* __restrict__ emb,
                              float* __restrict__ out)
{
    int idx = blockIdx.x * blockDim.x + threadIdx.x;
    if (idx >= M4 * E_) return;
    int i = idx / E_;
    int e = idx - i * E_;
    out[idx] = emb[(size_t)x[i] * E_ + e];
}

__global__ void addpos_kernel(const float* __restrict__ xemb,
                              const float* __restrict__ pos11,
                              float* __restrict__ out,
                              __nv_bfloat16* __restrict__ out3)
{
    int idx = blockIdx.x * blockDim.x + threadIdx.x;
    if (idx >= M4 * H_) return;
    int i = idx / H_;
    int h = idx - i * H_;
    int s = i & (S_ - 1);
    float y = xemb[idx] + pos11[(size_t)s * H_ + h];
    out[idx] = y;
    __nv_bfloat16 hi = __float2bfloat16_rn(y);
    __nv_bfloat16 lo = __float2bfloat16_rn(y - __bfloat162float(hi));
    size_t base = (size_t)i * 3 * H_;
    out3[base + h] = hi;
    out3[base + H_ + h] = lo;
    out3[base + 2 * H_ + h] = hi;
}

__global__ __launch_bounds__(256) void ln_res_kernel(
    const float* __restrict__ res, const float* __restrict__ x,
    const float* __restrict__ bias, const float* __restrict__ scale,
    float* __restrict__ out, __nv_bfloat16* __restrict__ out3)
{
    __shared__ float red[256];
    const int row = blockIdx.x;
    const int t = threadIdx.x;
    const float* xr = x + (size_t)row * H_;

    float lsum = 0.f;
    for (int i = t; i < H_; i += 256) lsum += xr[i];
    red[t] = lsum; __syncthreads();
    for (int s = 128; s > 0; s >>= 1) { if (t < s) red[t] += red[t + s]; __syncthreads(); }
    const float mean = red[0] * (1.0f / H_);
    __syncthreads();

    float lvar = 0.f;
    for (int i = t; i < H_; i += 256) { float d = xr[i] - mean; lvar += d * d; }
    red[t] = lvar; __syncthreads();
    for (int s = 128; s > 0; s >>= 1) { if (t < s) red[t] += red[t + s]; __syncthreads(); }
    const float rstd = rsqrtf(red[0] * (1.0f / H_) + 1e-6f);

    for (int i = t; i < H_; i += 256) {
        float y = res[(size_t)row * H_ + i] + (xr[i] - mean) * rstd * scale[i] + bias[i];
        out[(size_t)row * H_ + i] = y;
        if (out3) {
            __nv_bfloat16 hi = __float2bfloat16_rn(y);
            __nv_bfloat16 lo = __float2bfloat16_rn(y - __bfloat162float(hi));
            size_t base = (size_t)row * 3 * H_;
            out3[base + i] = hi;
            out3[base + H_ + i] = lo;
            out3[base + 2 * H_ + i] = hi;
        }
    }
}

// ---------------------------------------------------------------------------
// Launch helpers
// ---------------------------------------------------------------------------
static inline void run_gemm(const __nv_bfloat16* A3, const __nv_bfloat16* B3,
                            const float* bias, float* C, __nv_bfloat16* out3,
                            int M, int N, int K3, float alpha, int relu)
{
    dim3 grid(M / GBM, N / GBN);
    gemm_bf16_kernel<<<grid, 256, GEMM_SMEM_BYTES>>>(A3, B3, bias, C, out3,
                                                     M, N, K3, alpha, relu);
}
static inline void run_conv_wT(const float* W, __nv_bfloat16* out, int K, int N)
{
    dim3 grid(N / 32, K / 32);
    conv_wT_kernel<<<grid, 256>>>(W, out, K, N);
}

extern "C" void kernel_launch(void* const* d_in, const int* in_sizes, int n_in,
                              void* d_out, int out_size)
{
    const int*   x            = (const int*)  d_in[0];
    const float* emb_decode   = (const float*)d_in[1];
    const float* W_dec_lin    = (const float*)d_in[2];
    const float* p_decoder    = (const float*)d_in[3];
    const float* x_emb_pos    = (const float*)d_in[4];
    const float* p_d_q        = (const float*)d_in[5];
    const float* p_d_k        = (const float*)d_in[6];
    const float* p_d_v        = (const float*)d_in[7];
    const float* p_d_c        = (const float*)d_in[8];
    const float* p_d_ff1      = (const float*)d_in[9];
    const float* p_d_ff2      = (const float*)d_in[10];
    const float* b_d_ff1      = (const float*)d_in[11];
    const float* b_d_ff2      = (const float*)d_in[12];
    const float* d_o_bias     = (const float*)d_in[13];
    const float* d_o_scale    = (const float*)d_in[14];
    const float* b_d_bias_1   = (const float*)d_in[15];
    const float* b_d_bias_2   = (const float*)d_in[16];
    const float* b_d_scale_1  = (const float*)d_in[17];
    const float* b_d_scale_2  = (const float*)d_in[18];
    float* out = (float*)d_out;

    const int m = L_ - 1;   // only the last layer's result is observable

    cudaFuncSetAttribute(gemm_bf16_kernel,
                         cudaFuncAttributeMaxDynamicSharedMemorySize, GEMM_SMEM_BYTES);
    cudaFuncSetAttribute(attn_mma_kernel,
                         cudaFuncAttributeMaxDynamicSharedMemorySize, ATT_SMEM);

    float *Aemb, *xemb, *layerin, *q, *k, *v, *xmulti, *xself,
          *ffw1, *ffw2, *xffw, *decout;
    __nv_bfloat16 *a3_emb, *a3_li, *a3_conc, *a3_self, *a3_ffw1, *a3_dec;
    __nv_bfloat16 *w3_dec, *w3_q, *w3_k, *w3_v, *w3_c, *w3_ff1, *w3_ff2, *w3_pdec;
    cudaGetSymbolAddress((void**)&Aemb,    g_Aemb);
    cudaGetSymbolAddress((void**)&xemb,    g_xemb);
    cudaGetSymbolAddress((void**)&layerin, g_layerin);
    cudaGetSymbolAddress((void**)&q,       g_q);
    cudaGetSymbolAddress((void**)&k,       g_k);
    cudaGetSymbolAddress((void**)&v,       g_v);
    cudaGetSymbolAddress((void**)&xmulti,  g_xmulti);
    cudaGetSymbolAddress((void**)&xself,   g_xself);
    cudaGetSymbolAddress((void**)&ffw1,    g_ffw1);
    cudaGetSymbolAddress((void**)&ffw2,    g_ffw2);
    cudaGetSymbolAddress((void**)&xffw,    g_xffw);
    cudaGetSymbolAddress((void**)&decout,  g_decout);
    cudaGetSymbolAddress((void**)&a3_emb,  g_a3_emb);
    cudaGetSymbolAddress((void**)&a3_li,   g_a3_li);
    cudaGetSymbolAddress((void**)&a3_conc, g_a3_conc);
    cudaGetSymbolAddress((void**)&a3_self, g_a3_self);
    cudaGetSymbolAddress((void**)&a3_ffw1, g_a3_ffw1);
    cudaGetSymbolAddress((void**)&a3_dec,  g_a3_dec);
    cudaGetSymbolAddress((void**)&w3_dec,  g_w3_dec);
    cudaGetSymbolAddress((void**)&w3_q,    g_w3_q);
    cudaGetSymbolAddress((void**)&w3_k,    g_w3_k);
    cudaGetSymbolAddress((void**)&w3_v,    g_w3_v);
    cudaGetSymbolAddress((void**)&w3_c,    g_w3_c);
    cudaGetSymbolAddress((void**)&w3_ff1,  g_w3_ff1);
    cudaGetSymbolAddress((void**)&w3_ff2,  g_w3_ff2);
    cudaGetSymbolAddress((void**)&w3_pdec, g_w3_pdec);

    const float inv_sqrt_head = 0.125f;

    // weight conversions (split + transpose)
    run_conv_wT(W_dec_lin, w3_dec, E_, H_);
    run_conv_wT(p_d_q + (size_t)m * H_ * H_, w3_q, H_, H_);
    run_conv_wT(p_d_k + (size_t)m * H_ * H_, w3_k, H_, H_);
    run_conv_wT(p_d_v + (size_t)m * H_ * H_, w3_v, H_, H_);
    run_conv_wT(p_d_c + (size_t)m * H_ * H_, w3_c, H_, H_);
    run_conv_wT(p_d_ff1 + (size_t)m * H_ * FF_, w3_ff1, H_, FF_);
    run_conv_wT(p_d_ff2 + (size_t)m * FF_ * H_, w3_ff2, FF_, H_);
    run_conv_wT(p_decoder, w3_pdec, H_, V_);

    // 1. gather embeddings + split
    gather_kernel<<<(M4 * E_ + 255) / 256, 256>>>(x, emb_decode, Aemb);
    conv_act_kernel<<<(M4 * E_ + 255) / 256, 256>>>(Aemb, a3_emb, M4, E_);

    // 2. x_dec_embed = A_emb @ W_dec_lin
    run_gemm(a3_emb, w3_dec, nullptr, xemb, nullptr, M4, H_, 3 * E_, 1.f, 0);

    // 3. layer_in = pos[11] + x_dec_embed  (+ fused split)
    addpos_kernel<<<(M4 * H_ + 255) / 256, 256>>>(
        xemb, x_emb_pos + (size_t)m * S_ * H_, layerin, a3_li);

    // 4. Q/K/V projections (Q pre-scaled)
    run_gemm(a3_li, w3_q, nullptr, q, nullptr, M4, H_, 3 * H_, inv_sqrt_head, 0);
    run_gemm(a3_li, w3_k, nullptr, k, nullptr, M4, H_, 3 * H_, 1.f, 0);
    run_gemm(a3_li, w3_v, nullptr, v, nullptr, M4, H_, 3 * H_, 1.f, 0);

    // 5. tensor-core causal attention -> a3_conc (split, fused)
    attn_mma_kernel<<<dim3(S_ / 64, B_ * NH_), 128, ATT_SMEM>>>(q, k, v, a3_conc);

    // 6. x_multi = conc @ p_d_c
    run_gemm(a3_conc, w3_c, nullptr, xmulti, nullptr, M4, H_, 3 * H_, 1.f, 0);

    // 7. x_self = layer_in + LN(x_multi)  (+ fused split)
    ln_res_kernel<<<M4, 256>>>(layerin, xmulti,
                               b_d_bias_1 + (size_t)m * H_,
                               b_d_scale_1 + (size_t)m * H_, xself, a3_self);

    // 8. FFN (ffw1 writes split directly)
    run_gemm(a3_self, w3_ff1, b_d_ff1 + (size_t)m * FF_, ffw1, a3_ffw1,
             M4, FF_, 3 * H_, 1.f, 1);
    run_gemm(a3_ffw1, w3_ff2, b_d_ff2 + (size_t)m * H_, ffw2, nullptr,
             M4, H_, 3 * FF_, 1.f, 0);

    // 9. x_ffw = x_self + LN(ffw2)
    ln_res_kernel<<<M4, 256>>>(xself, ffw2,
                               b_d_bias_2 + (size_t)m * H_,
                               b_d_scale_2 + (size_t)m * H_, xffw, nullptr);

    // 10. dec_outputs = x_dec_embed + LN(x_ffw)  (+ fused split)
    ln_res_kernel<<<M4, 256>>>(xemb, xffw, d_o_bias, d_o_scale, decout, a3_dec);

    // 11. logits = dec_outputs @ p_decoder
    run_gemm(a3_dec, w3_pdec, nullptr, out, nullptr, M4, V_, 3 * H_, 1.f, 0);
}

// round 8
// speedup vs baseline: 5.3220x; 1.0710x over previous
#include <cuda_runtime.h>
#include <cuda_bf16.h>
#include <cstdint>

// Problem constants
#define L_   12
#define NH_  16
#define H_   1024
#define FF_  4096
#define V_   32000
#define S_   1024
#define E_   128
#define B_   4
#define HEAD_ 64
#define M4   (B_ * S_)   // 4096 rows total
#define QKVS 3072        // fused qkv row stride (floats)

// Arch-feature dispatch: tcgen05 only legal in the sm_103a pass.
#if defined(__CUDA_ARCH__) && defined(__CUDA_ARCH_FEAT_SM103_ALL)
#define TC_PATH 1
#else
#define TC_PATH 0
#endif

// ---------------------------------------------------------------------------
// Scratch (device globals — allocation-free per harness rules)
// ---------------------------------------------------------------------------
__device__ float g_Aemb   [M4 * E_];
__device__ float g_xemb   [M4 * H_];
__device__ float g_layerin[M4 * H_];
__device__ float g_qkv    [M4 * QKVS];
__device__ float g_xmulti [M4 * H_];
__device__ float g_xself  [M4 * H_];
__device__ float g_ffw1   [M4 * FF_];
__device__ float g_ffw2   [M4 * H_];
__device__ float g_xffw   [M4 * H_];
__device__ float g_decout [M4 * H_];

// bf16 split-K3 operand buffers.  A' = [hi | lo | hi] (row-major, 3K cols),
// B' = [hi | hi | lo] as [N, 3K] (k-contiguous, i.e. transposed weight).
__device__ __align__(128) __nv_bfloat16 g_a3_emb [M4 * 3 * E_];
__device__ __align__(128) __nv_bfloat16 g_a3_li  [M4 * 3 * H_];
__device__ __align__(128) __nv_bfloat16 g_a3_conc[M4 * 3 * H_];
__device__ __align__(128) __nv_bfloat16 g_a3_self[M4 * 3 * H_];
__device__ __align__(128) __nv_bfloat16 g_a3_ffw1[(size_t)M4 * 3 * FF_];
__device__ __align__(128) __nv_bfloat16 g_a3_dec [M4 * 3 * H_];

__device__ __align__(128) __nv_bfloat16 g_w3_dec [H_ * 3 * E_];
__device__ __align__(128) __nv_bfloat16 g_w3_qkv [(size_t)QKVS * 3 * H_];
__device__ __align__(128) __nv_bfloat16 g_w3_c   [H_ * 3 * H_];
__device__ __align__(128) __nv_bfloat16 g_w3_ff1 [(size_t)FF_ * 3 * H_];
__device__ __align__(128) __nv_bfloat16 g_w3_ff2 [(size_t)H_ * 3 * FF_];
__device__ __align__(128) __nv_bfloat16 g_w3_pdec[(size_t)V_ * 3 * H_];

// ---------------------------------------------------------------------------
// PTX helpers — baseline-legal
// ---------------------------------------------------------------------------
__device__ __forceinline__ uint32_t smem_u32(const void* p) {
    uint32_t a;
    asm("{ .reg .u64 t; cvta.to.shared.u64 t, %1; cvt.u32.u64 %0, t; }"
        : "=r"(a) : "l"(p));
    return a;
}
__device__ __forceinline__ void cp16(uint32_t dst, const void* src) {
    asm volatile("cp.async.cg.shared.global [%0], [%1], 16;"
                 :: "r"(dst), "l"(src) : "memory");
}
__device__ __forceinline__ void cp_commit() {
    asm volatile("cp.async.commit_group;" ::: "memory");
}
template <int N>
__device__ __forceinline__ void cp_wait() {
    asm volatile("cp.async.wait_group %0;" :: "n"(N) : "memory");
}
__device__ __forceinline__ uint32_t elect_one_pred() {
    uint32_t pred;
    asm volatile(
        "{\n\t.reg .pred p;\n\telect.sync _|p, 0xFFFFFFFF;\n\t"
        "selp.b32 %0, 1, 0, p;\n\t}" : "=r"(pred));
    return pred;
}
// legacy m16n8k16 bf16 MMA, fp32 accumulate (sm_80+)
__device__ __forceinline__ void mma16(float* d, const uint32_t* a, const uint32_t* b) {
    asm volatile(
        "mma.sync.aligned.m16n8k16.row.col.f32.bf16.bf16.f32 "
        "{%0,%1,%2,%3}, {%4,%5,%6,%7}, {%8,%9}, {%0,%1,%2,%3};"
        : "+f"(d[0]), "+f"(d[1]), "+f"(d[2]), "+f"(d[3])
        : "r"(a[0]), "r"(a[1]), "r"(a[2]), "r"(a[3]),
          "r"(b[0]), "r"(b[1]));
}
__device__ __forceinline__ uint32_t pack_bf16x2(float lo_elem, float hi_elem) {
    uint32_t r;
    asm("cvt.rn.bf16x2.f32 %0, %1, %2;" : "=r"(r) : "f"(hi_elem), "f"(lo_elem));
    return r;
}
__device__ __forceinline__ uint32_t pack_raw(__nv_bfloat16 lo, __nv_bfloat16 hi) {
    return (uint32_t)__bfloat16_as_ushort(lo) | ((uint32_t)__bfloat16_as_ushort(hi) << 16);
}

#define SMEM_SWIZZLE_128B(o) ((o) ^ (((o) >> 3) & 0x70))

#if TC_PATH
// ---- tcgen05 helpers (only compiled in the sm_103a pass) ----
#define TCGEN05_ALLOC(smem_addr, nCols) \
    asm volatile("tcgen05.alloc.cta_group::1.sync.aligned.shared::cta.b32 [%0], %1;" \
                 :: "r"((uint32_t)(smem_addr)), "r"((uint32_t)(nCols)) : "memory")
#define TCGEN05_DEALLOC(tmem_addr, nCols) \
    asm volatile("tcgen05.dealloc.cta_group::1.sync.aligned.b32 %0, %1;" \
                 :: "r"(tmem_addr), "r"((uint32_t)(nCols)))
#define TCGEN05_RELINQUISH() \
    asm volatile("tcgen05.relinquish_alloc_permit.cta_group::1.sync.aligned;")
#define TCGEN05_COMMIT(mbar) \
    asm volatile("tcgen05.commit.cta_group::1.mbarrier::arrive::one.shared::cluster.b64 [%0];" \
                 :: "r"((uint32_t)(mbar)) : "memory")
#define TCGEN05_FENCE_AFTER() \
    asm volatile("tcgen05.fence::after_thread_sync;" ::: "memory")
#define TCGEN05_FENCE_BEFORE() \
    asm volatile("tcgen05.fence::before_thread_sync;" ::: "memory")
#define TCGEN05_WAIT_LD() \
    asm volatile("tcgen05.wait::ld.sync.aligned;" ::: "memory")
#define MBARRIER_INIT(mbar, cnt) \
    asm volatile("mbarrier.init.shared.b64 [%0], %1;" \
                 :: "r"((uint32_t)(mbar)), "r"((uint32_t)(cnt)) : "memory")
#define MBARRIER_INVAL(mbar) \
    asm volatile("mbarrier.inval.shared.b64 [%0];" :: "r"((uint32_t)(mbar)) : "memory")
#define FENCE_PROXY_ASYNC() \
    asm volatile("fence.proxy.async.shared::cta;" ::: "memory")

#define MBARRIER_WAIT_PARITY(mbar_smem_addr, phase_parity) do { \
    uint32_t _mbar = (uint32_t)(mbar_smem_addr); \
    uint32_t _parity = (uint32_t)(phase_parity); \
    uint32_t _done; \
    asm volatile("{\n\t.reg .pred p;\n\t" \
        "mbarrier.try_wait.parity.acquire.cta.shared::cta.b64 p, [%1], %2;\n\t" \
        "selp.b32 %0, 1, 0, p;\n\t}" \
        : "=r"(_done) : "r"(_mbar), "r"(_parity) : "memory"); \
    if (!_done) { \
        asm volatile("{\n\t.reg .pred P1;\n\t" \
            "WAIT_LOOP_%=:\n\t" \
            "mbarrier.try_wait.parity.acquire.cta.shared::cta.b64 P1, [%0], %1, 0x989680;\n\t" \
            "@P1 bra.uni WAIT_DONE_%=;\n\t" \
            "bra.uni WAIT_LOOP_%=;\n\t" \
            "WAIT_DONE_%=:\n\t}" \
            :: "r"(_mbar), "r"(_parity) : "memory"); \
    } \
} while(0)

#define TCGEN05_LD_32X32B_X32(r, tmem_addr) \
    asm volatile( \
        "tcgen05.ld.sync.aligned.32x32b.x32.b32 " \
        "{%0, %1, %2, %3, %4, %5, %6, %7, " \
        " %8, %9, %10, %11, %12, %13, %14, %15, " \
        " %16, %17, %18, %19, %20, %21, %22, %23, " \
        " %24, %25, %26, %27, %28, %29, %30, %31}, [%32];" \
        : "=r"((r)[0]),  "=r"((r)[1]),  "=r"((r)[2]),  "=r"((r)[3]), \
          "=r"((r)[4]),  "=r"((r)[5]),  "=r"((r)[6]),  "=r"((r)[7]), \
          "=r"((r)[8]),  "=r"((r)[9]),  "=r"((r)[10]), "=r"((r)[11]), \
          "=r"((r)[12]), "=r"((r)[13]), "=r"((r)[14]), "=r"((r)[15]), \
          "=r"((r)[16]), "=r"((r)[17]), "=r"((r)[18]), "=r"((r)[19]), \
          "=r"((r)[20]), "=r"((r)[21]), "=r"((r)[22]), "=r"((r)[23]), \
          "=r"((r)[24]), "=r"((r)[25]), "=r"((r)[26]), "=r"((r)[27]), \
          "=r"((r)[28]), "=r"((r)[29]), "=r"((r)[30]), "=r"((r)[31]) \
        : "r"(tmem_addr))

static constexpr uint64_t SMEM_DESC_BASE_SW128 =
    (uint64_t(2) << 61) | (uint64_t(1) << 46) | (uint64_t(64) << 32) | (uint64_t(1) << 16);
#define MAKE_SMEM_DESC(addr) (SMEM_DESC_BASE_SW128 | ((uint64_t)((addr) >> 4) & 0x3FFF))

__device__ __forceinline__ void mma_bf16_ss(uint32_t d_tmem, uint64_t a_desc,
                                            uint64_t b_desc, uint32_t idesc,
                                            uint32_t enable_d) {
    uint32_t z = 0;
    asm volatile(
        "{\n\t.reg .pred p;\n\tsetp.ne.u32 p, %5, 0;\n\t"
        "tcgen05.mma.cta_group::1.kind::f16 [%0], %1, %2, %3, {%4, %4, %4, %4}, p;\n\t}"
        :: "r"(d_tmem), "l"(a_desc), "l"(b_desc), "r"(idesc), "r"(z), "r"(enable_d)
        : "memory");
}
#endif // TC_PATH

// ---------------------------------------------------------------------------
// Shared epilogue value transform
// ---------------------------------------------------------------------------
__device__ __forceinline__ void store_split3(__nv_bfloat16* op, int N,
                                             float v0, float v1) {
    __nv_bfloat16 h0 = __float2bfloat16_rn(v0);
    __nv_bfloat16 h1 = __float2bfloat16_rn(v1);
    uint32_t hp = pack_raw(h0, h1);
    uint32_t lp = pack_bf16x2(v0 - __bfloat162float(h0), v1 - __bfloat162float(h1));
    *reinterpret_cast<uint32_t*>(op) = hp;
    *reinterpret_cast<uint32_t*>(op + N) = lp;
    *reinterpret_cast<uint32_t*>(op + 2 * N) = hp;
}

// ---------------------------------------------------------------------------
// Legacy HMMA 128x128 tile (compute_103 fallback only)
// ---------------------------------------------------------------------------
#define GBM 128
#define GBN 128
#define GBK 64
#define RSTRIDE 36
#define ABUF (128 * RSTRIDE)
#define BBUF (128 * RSTRIDE)
#define GEMM_SMEM_BYTES 99328   // 128-tile: 1024 + 6*16384 (tc); legacy 73728

#if !TC_PATH
__device__ void legacy_tile128(
    const __nv_bfloat16* __restrict__ A3, const __nv_bfloat16* __restrict__ B3,
    const float* __restrict__ bias, float* __restrict__ C,
    __nv_bfloat16* __restrict__ out3,
    int N, int K3, float alpha, int do_relu,
    int m0, int n0, uint32_t* sm, uint32_t smb)
{
    const int tid = threadIdx.x;
    const int wid = tid >> 5, lane = tid & 31;
    const int g = lane >> 2, c4 = lane & 3;
    const int warp_m = wid >> 2;
    const int warp_n = wid & 3;

    const int srow = tid >> 1, spart = tid & 1;
    const __nv_bfloat16* aptr = A3 + (size_t)(m0 + srow) * K3 + spart * 32;
    const __nv_bfloat16* bptr = B3 + (size_t)(n0 + srow) * K3 + spart * 32;
    const uint32_t as_base = smb + (srow * RSTRIDE + spart * 16) * 4;
    const uint32_t bs_base = smb + (2 * ABUF + srow * RSTRIDE + spart * 16) * 4;

    const int NC = K3 / GBK;

    float acc[4][4][4];
    #pragma unroll
    for (int i = 0; i < 4; i++)
        #pragma unroll
        for (int j = 0; j < 4; j++)
            #pragma unroll
            for (int q = 0; q < 4; q++) acc[i][j][q] = 0.f;

    #pragma unroll
    for (int q = 0; q < 4; q++) cp16(as_base + q * 16, aptr + q * 8);
    #pragma unroll
    for (int q = 0; q < 4; q++) cp16(bs_base + q * 16, bptr + q * 8);
    cp_commit();

    for (int c = 0; c < NC; c++) {
        if (c + 1 < NC) {
            const int nb = (c + 1) & 1;
            const __nv_bfloat16* ap = aptr + (c + 1) * GBK;
            const __nv_bfloat16* bp = bptr + (c + 1) * GBK;
            #pragma unroll
            for (int q = 0; q < 4; q++)
                cp16(as_base + nb * ABUF * 4 + q * 16, ap + q * 8);
            #pragma unroll
            for (int q = 0; q < 4; q++)
                cp16(bs_base + nb * BBUF * 4 + q * 16, bp + q * 8);
            cp_commit();
            cp_wait<1>();
        } else {
            cp_wait<0>();
        }
        __syncthreads();

        const uint32_t* ab = sm + (c & 1) * ABUF;
        const uint32_t* bb = sm + 2 * ABUF + (c & 1) * BBUF;

        #pragma unroll
        for (int ks = 0; ks < 4; ks++) {
            const int kb = ks * 8;
            uint32_t af[4][4], bf[4][2];
            #pragma unroll
            for (int i = 0; i < 4; i++) {
                const uint32_t* p = ab + (warp_m * 64 + i * 16 + g) * RSTRIDE + kb + c4;
                af[i][0] = p[0];
                af[i][1] = p[8 * RSTRIDE];
                af[i][2] = p[4];
                af[i][3] = p[8 * RSTRIDE + 4];
            }
            #pragma unroll
            for (int j = 0; j < 4; j++) {
                const uint32_t* p = bb + (warp_n * 32 + j * 8 + g) * RSTRIDE + kb + c4;
                bf[j][0] = p[0];
                bf[j][1] = p[4];
            }
            #pragma unroll
            for (int i = 0; i < 4; i++)
                #pragma unroll
                for (int j = 0; j < 4; j++)
                    mma16(acc[i][j], af[i], bf[j]);
        }
        __syncthreads();
    }

    #pragma unroll
    for (int i = 0; i < 4; i++) {
        #pragma unroll
        for (int j = 0; j < 4; j++) {
            const int col = n0 + warp_n * 32 + j * 8 + c4 * 2;
            float b0v = 0.f, b1v = 0.f;
            if (bias) { b0v = bias[col]; b1v = bias[col + 1]; }
            float v0 = acc[i][j][0] * alpha + b0v;
            float v1 = acc[i][j][1] * alpha + b1v;
            float v2 = acc[i][j][2] * alpha + b0v;
            float v3 = acc[i][j][3] * alpha + b1v;
            if (do_relu) {
                v0 = fmaxf(v0, 0.f); v1 = fmaxf(v1, 0.f);
                v2 = fmaxf(v2, 0.f); v3 = fmaxf(v3, 0.f);
            }
            const int ra = m0 + warp_m * 64 + i * 16 + g;
            if (out3) {
                store_split3(out3 + (size_t)ra * 3 * N + col, N, v0, v1);
                store_split3(out3 + (size_t)(ra + 8) * 3 * N + col, N, v2, v3);
            } else {
                float2 lo = {v0, v1}, hi = {v2, v3};
                *reinterpret_cast<float2*>(C + (size_t)ra * N + col) = lo;
                *reinterpret_cast<float2*>(C + (size_t)(ra + 8) * N + col) = hi;
            }
        }
    }
}
#endif // !TC_PATH

// ---------------------------------------------------------------------------
// 128x128 GEMM (N=1024 cases).  C = alpha*(A3 @ B3^T) + bias (+relu / +split)
// ---------------------------------------------------------------------------
__global__ __launch_bounds__(256, 2) void gemm_bf16_kernel(
    const __nv_bfloat16* __restrict__ A3, const __nv_bfloat16* __restrict__ B3,
    const float* __restrict__ bias, float* __restrict__ C,
    __nv_bfloat16* __restrict__ out3,
    int M, int N, int K3, float alpha, int do_relu)
{
#if TC_PATH
    extern __shared__ char smc[];
    const uint32_t smb = smem_u32(smc);
    const int tid = threadIdx.x;
    const int wid = tid >> 5, lane = tid & 31;
    const int m0 = blockIdx.x * GBM;
    const int n0 = blockIdx.y * GBN;

    const uint32_t sa[3] = {1024u, 1024u + 16384u, 1024u + 32768u};
    const uint32_t sb[3] = {1024u + 49152u, 1024u + 65536u, 1024u + 81920u};
    const uint32_t mb[3] = {smb + 8u, smb + 16u, smb + 24u};

    if (wid == 0) TCGEN05_ALLOC(smb, 128);
    if (tid == 0) { MBARRIER_INIT(mb[0], 1); MBARRIER_INIT(mb[1], 1); MBARRIER_INIT(mb[2], 1); }
    __syncthreads();
    uint32_t tmem;
    asm volatile("ld.shared.b32 %0, [%1];" : "=r"(tmem) : "r"(smb));
    if (wid == 0) TCGEN05_RELINQUISH();

    const uint32_t IDESC =
        (1u << 4) | (1u << 7) | (1u << 10) | ((GBN / 8) << 17) | ((GBM / 16) << 24);

    const int NC = K3 / GBK;
    const int r0s = tid >> 3;
    const int c8 = tid & 7;
    const __nv_bfloat16* abase = A3 + (size_t)(m0 + r0s) * K3 + c8 * 8;
    const __nv_bfloat16* bbase = B3 + (size_t)(n0 + r0s) * K3 + c8 * 8;
    const uint32_t swoff[4] = {
        SMEM_SWIZZLE_128B((uint32_t)((r0s +  0) * 128 + c8 * 16)),
        SMEM_SWIZZLE_128B((uint32_t)((r0s + 32) * 128 + c8 * 16)),
        SMEM_SWIZZLE_128B((uint32_t)((r0s + 64) * 128 + c8 * 16)),
        SMEM_SWIZZLE_128B((uint32_t)((r0s + 96) * 128 + c8 * 16))};

    auto stage_chunk = [&](int chunk, int buf) {
        #pragma unroll
        for (int it = 0; it < 4; it++) {
            cp16(smb + sa[buf] + swoff[it], abase + (size_t)it * 32 * K3 + chunk * GBK);
            cp16(smb + sb[buf] + swoff[it], bbase + (size_t)it * 32 * K3 + chunk * GBK);
        }
        cp_commit();
    };

    int ph[3] = {0, 0, 0};
    stage_chunk(0, 0);
    stage_chunk(1, 1);

    for (int c = 0; c < NC; c++) {
        const int b = c % 3;
        if (c + 2 < NC) {
            const int nb = (c + 2) % 3;
            if (c >= 1) { MBARRIER_WAIT_PARITY(mb[nb], ph[nb]); ph[nb] ^= 1; }
            stage_chunk(c + 2, nb);
            cp_wait<2>();
        } else if (c + 1 < NC) {
            cp_wait<1>();
        } else {
            cp_wait<0>();
        }
        __syncthreads();
        if (wid == 0 && elect_one_pred()) {
            FENCE_PROXY_ASYNC();
            const uint64_t ad = MAKE_SMEM_DESC(smb + sa[b]);
            const uint64_t bd = MAKE_SMEM_DESC(smb + sb[b]);
            #pragma unroll
            for (int ks = 0; ks < 4; ks++)
                mma_bf16_ss(tmem, ad + ks * 2, bd + ks * 2, IDESC,
                            (c > 0 || ks > 0) ? 1u : 0u);
            TCGEN05_COMMIT(mb[b]);
        }
    }
    MBARRIER_WAIT_PARITY(mb[(NC - 1) % 3], ph[(NC - 1) % 3]);
    TCGEN05_FENCE_AFTER();

    if (wid < 4) {
        const uint32_t lofs = (uint32_t)wid << 21;
        const int row = m0 + wid * 32 + lane;
        #pragma unroll
        for (int j = 0; j < 4; j++) {
            uint32_t r[32];
            TCGEN05_LD_32X32B_X32(r, tmem + j * 32 + lofs);
            TCGEN05_WAIT_LD();
            const float* bp = bias ? (bias + n0 + j * 32) : nullptr;
            if (out3) {
                __nv_bfloat16* op = out3 + (size_t)row * 3 * N + n0 + j * 32;
                #pragma unroll
                for (int q = 0; q < 32; q += 2) {
                    float v0 = __uint_as_float(r[q + 0]) * alpha;
                    float v1 = __uint_as_float(r[q + 1]) * alpha;
                    if (bp) { v0 += bp[q]; v1 += bp[q + 1]; }
                    if (do_relu) { v0 = fmaxf(v0, 0.f); v1 = fmaxf(v1, 0.f); }
                    store_split3(op + q, N, v0, v1);
                }
            } else {
                float* cp = C + (size_t)row * N + n0 + j * 32;
                #pragma unroll
                for (int q = 0; q < 32; q += 4) {
                    float v0 = __uint_as_float(r[q + 0]) * alpha;
                    float v1 = __uint_as_float(r[q + 1]) * alpha;
                    float v2 = __uint_as_float(r[q + 2]) * alpha;
                    float v3 = __uint_as_float(r[q + 3]) * alpha;
                    if (bp) { v0 += bp[q]; v1 += bp[q + 1]; v2 += bp[q + 2]; v3 += bp[q + 3]; }
                    if (do_relu) {
                        v0 = fmaxf(v0, 0.f); v1 = fmaxf(v1, 0.f);
                        v2 = fmaxf(v2, 0.f); v3 = fmaxf(v3, 0.f);
                    }
                    float4 o = {v0, v1, v2, v3};
                    *reinterpret_cast<float4*>(cp + q) = o;
                }
            }
        }
        TCGEN05_FENCE_BEFORE();
    }
    __syncthreads();
    if (tid == 0) { MBARRIER_INVAL(mb[0]); MBARRIER_INVAL(mb[1]); MBARRIER_INVAL(mb[2]); }
    __syncthreads();
    if (wid == 0) TCGEN05_DEALLOC(tmem, 128);
#else
    extern __shared__ uint32_t sm[];
    const uint32_t smb = smem_u32(sm);
    legacy_tile128(A3, B3, bias, C, out3, N, K3, alpha, do_relu,
                   blockIdx.x * GBM, blockIdx.y * GBN, sm, smb);
#endif
}

// ---------------------------------------------------------------------------
// 256x256 GEMM (big-N cases).  Full 512-col TMEM, 3-stage, 1 CTA/SM.
// ---------------------------------------------------------------------------
#define G2K 64
#define G2_SMEM (1024 + 3 * 65536)   // 197632 B

__global__ __launch_bounds__(256, 1) void gemm256_kernel(
    const __nv_bfloat16* __restrict__ A3, const __nv_bfloat16* __restrict__ B3,
    const float* __restrict__ bias, float* __restrict__ C,
    __nv_bfloat16* __restrict__ out3,
    int M, int N, int K3, float alpha, int do_relu)
{
#if TC_PATH
    extern __shared__ char smc[];
    const uint32_t smb = smem_u32(smc);
    const int tid = threadIdx.x;
    const int wid = tid >> 5, lane = tid & 31;
    const int m0 = blockIdx.x * 256;
    const int n0 = blockIdx.y * 256;

    const uint32_t mb[3] = {smb + 8u, smb + 16u, smb + 24u};

    if (wid == 0) TCGEN05_ALLOC(smb, 512);
    if (tid == 0) { MBARRIER_INIT(mb[0], 1); MBARRIER_INIT(mb[1], 1); MBARRIER_INIT(mb[2], 1); }
    __syncthreads();
    uint32_t tmem;
    asm volatile("ld.shared.b32 %0, [%1];" : "=r"(tmem) : "r"(smb));
    if (wid == 0) TCGEN05_RELINQUISH();

    // M=128, N=256 per dispatch
    const uint32_t IDESC2 =
        (1u << 4) | (1u << 7) | (1u << 10) | ((256 / 8) << 17) | ((128 / 16) << 24);

    const int NC = K3 / G2K;
    const int r0s = tid >> 3;        // 0..31
    const int c8 = tid & 7;
    const __nv_bfloat16* abase = A3 + (size_t)(m0 + r0s) * K3 + c8 * 8;
    const __nv_bfloat16* bbase = B3 + (size_t)(n0 + r0s) * K3 + c8 * 8;
    uint32_t swoff[8];
    #pragma unroll
    for (int it = 0; it < 8; it++)
        swoff[it] = SMEM_SWIZZLE_128B((uint32_t)((r0s + it * 32) * 128 + c8 * 16));

    auto stage_chunk = [&](int chunk, int buf) {
        const uint32_t sa = smb + 1024u + (uint32_t)buf * 65536u;
        const uint32_t sbo = sa + 32768u;
        #pragma unroll
        for (int it = 0; it < 8; it++) {
            cp16(sa + swoff[it], abase + (size_t)it * 32 * K3 + chunk * G2K);
            cp16(sbo + swoff[it], bbase + (size_t)it * 32 * K3 + chunk * G2K);
        }
        cp_commit();
    };

    int ph[3] = {0, 0, 0};
    stage_chunk(0, 0);
    stage_chunk(1, 1);

    for (int c = 0; c < NC; c++) {
        const int b = c % 3;
        if (c + 2 < NC) {
            const int nb = (c + 2) % 3;
            if (c >= 1) { MBARRIER_WAIT_PARITY(mb[nb], ph[nb]); ph[nb] ^= 1; }
            stage_chunk(c + 2, nb);
            cp_wait<2>();
        } else if (c + 1 < NC) {
            cp_wait<1>();
        } else {
            cp_wait<0>();
        }
        __syncthreads();
        if (wid == 0 && elect_one_pred()) {
            FENCE_PROXY_ASYNC();
            const uint32_t sa = smb + 1024u + (uint32_t)b * 65536u;
            const uint64_t ad = MAKE_SMEM_DESC(sa);
            const uint64_t bd = MAKE_SMEM_DESC(sa + 32768u);
            #pragma unroll
            for (int ks = 0; ks < 4; ks++) {
                const uint32_t en = (c > 0 || ks > 0) ? 1u : 0u;
                // m-half 0: A rows 0-127; m-half 1: rows 128-255 (+16KB = +1024 desc units)
                mma_bf16_ss(tmem,       ad + ks * 2,        bd + ks * 2, IDESC2, en);
                mma_bf16_ss(tmem + 256, ad + 1024 + ks * 2, bd + ks * 2, IDESC2, en);
            }
            TCGEN05_COMMIT(mb[b]);
        }
    }
    MBARRIER_WAIT_PARITY(mb[(NC - 1) % 3], ph[(NC - 1) % 3]);
    TCGEN05_FENCE_AFTER();

    // epilogue: all 8 warps. mh = wid>>2 selects D region (cols mh*256),
    // w4 = wid&3 selects 32-lane group.
    {
        const int mh = wid >> 2;
        const int w4 = wid & 3;
        const uint32_t lofs = (uint32_t)w4 << 21;
        const int row = m0 + mh * 128 + w4 * 32 + lane;
        #pragma unroll
        for (int j = 0; j < 8; j++) {
            uint32_t r[32];
            TCGEN05_LD_32X32B_X32(r, tmem + mh * 256 + j * 32 + lofs);
            TCGEN05_WAIT_LD();
            const float* bp = bias ? (bias + n0 + j * 32) : nullptr;
            if (out3) {
                __nv_bfloat16* op = out3 + (size_t)row * 3 * N + n0 + j * 32;
                #pragma unroll
                for (int q = 0; q < 32; q += 2) {
                    float v0 = __uint_as_float(r[q + 0]) * alpha;
                    float v1 = __uint_as_float(r[q + 1]) * alpha;
                    if (bp) { v0 += bp[q]; v1 += bp[q + 1]; }
                    if (do_relu) { v0 = fmaxf(v0, 0.f); v1 = fmaxf(v1, 0.f); }
                    store_split3(op + q, N, v0, v1);
                }
            } else {
                float* cp = C + (size_t)row * N + n0 + j * 32;
                #pragma unroll
                for (int q = 0; q < 32; q += 4) {
                    float v0 = __uint_as_float(r[q + 0]) * alpha;
                    float v1 = __uint_as_float(r[q + 1]) * alpha;
                    float v2 = __uint_as_float(r[q + 2]) * alpha;
                    float v3 = __uint_as_float(r[q + 3]) * alpha;
                    if (bp) { v0 += bp[q]; v1 += bp[q + 1]; v2 += bp[q + 2]; v3 += bp[q + 3]; }
                    if (do_relu) {
                        v0 = fmaxf(v0, 0.f); v1 = fmaxf(v1, 0.f);
                        v2 = fmaxf(v2, 0.f); v3 = fmaxf(v3, 0.f);
                    }
                    float4 o = {v0, v1, v2, v3};
                    *reinterpret_cast<float4*>(cp + q) = o;
                }
            }
        }
        TCGEN05_FENCE_BEFORE();
    }
    __syncthreads();
    if (tid == 0) { MBARRIER_INVAL(mb[0]); MBARRIER_INVAL(mb[1]); MBARRIER_INVAL(mb[2]); }
    __syncthreads();
    if (wid == 0) TCGEN05_DEALLOC(tmem, 512);
#else
    extern __shared__ uint32_t sm[];
    const uint32_t smb = smem_u32(sm);
    #pragma unroll
    for (int qm = 0; qm < 2; qm++)
        for (int qn = 0; qn < 2; qn++) {
            legacy_tile128(A3, B3, bias, C, out3, N, K3, alpha, do_relu,
                           blockIdx.x * 256 + qm * 128,
                           blockIdx.y * 256 + qn * 128, sm, smb);
            __syncthreads();
        }
#endif
}

// ---------------------------------------------------------------------------
// Tensor-core split-bf16 causal flash attention (fused-QKV input, stride QKVS)
// ---------------------------------------------------------------------------
#define AT_STRIDE 136
#define ATT_SMEM  (3 * 64 * AT_STRIDE * 2)   // 52224 B

__global__ __launch_bounds__(128, 3) void attn_mma_kernel(
    const float* __restrict__ Q, const float* __restrict__ Kg,
    const float* __restrict__ Vg, __nv_bfloat16* __restrict__ conc3)
{
    extern __shared__ __nv_bfloat16 sh[];
    __nv_bfloat16* Qs = sh;
    __nv_bfloat16* Ks = sh + 64 * AT_STRIDE;
    __nv_bfloat16* Vs = sh + 128 * AT_STRIDE;

    const int qt = blockIdx.x;
    const int bh = blockIdx.y;
    const int b = bh >> 4, n = bh & 15;
    const int tid = threadIdx.x;
    const int wid = tid >> 5, lane = tid & 31;
    const int g = lane >> 2, c4 = lane & 3;

    {
        const int r = tid >> 1;
        const int dbase = (tid & 1) * 32;
        const float* qp = Q + ((size_t)(b * S_ + qt * 64 + r)) * QKVS + n * 64 + dbase;
        #pragma unroll
        for (int i = 0; i < 32; i += 4) {
            float4 f = *reinterpret_cast<const float4*>(qp + i);
            float vals[4] = {f.x, f.y, f.z, f.w};
            #pragma unroll
            for (int e = 0; e < 4; e++) {
                __nv_bfloat16 hi = __float2bfloat16_rn(vals[e]);
                Qs[r * AT_STRIDE + dbase + i + e] = hi;
                Qs[r * AT_STRIDE + 64 + dbase + i + e] =
                    __float2bfloat16_rn(vals[e] - __bfloat162float(hi));
            }
        }
    }

    const int row0 = wid * 16 + g;
    float m0 = -1e30f, m1 = -1e30f, l0 = 0.f, l1 = 0.f;
    float o[8][4];
    #pragma unroll
    for (int j = 0; j < 8; j++)
        #pragma unroll
        for (int q = 0; q < 4; q++) o[j][q] = 0.f;

    for (int kt = 0; kt <= qt; kt++) {
        __syncthreads();
        {
            const int r = tid >> 1;
            const int dbase = (tid & 1) * 32;
            const float* kp = Kg + ((size_t)(b * S_ + kt * 64 + r)) * QKVS + n * 64 + dbase;
            const float* vp = Vg + ((size_t)(b * S_ + kt * 64 + r)) * QKVS + n * 64 + dbase;
            #pragma unroll
            for (int i = 0; i < 32; i += 4) {
                float4 fk = *reinterpret_cast<const float4*>(kp + i);
                float4 fv = *reinterpret_cast<const float4*>(vp + i);
                float kv[4] = {fk.x, fk.y, fk.z, fk.w};
                float vv[4] = {fv.x, fv.y, fv.z, fv.w};
                #pragma unroll
                for (int e = 0; e < 4; e++) {
                    const int d = dbase + i + e;
                    __nv_bfloat16 kh = __float2bfloat16_rn(kv[e]);
                    Ks[r * AT_STRIDE + d] = kh;
                    Ks[r * AT_STRIDE + 64 + d] =
                        __float2bfloat16_rn(kv[e] - __bfloat162float(kh));
                    __nv_bfloat16 vh = __float2bfloat16_rn(vv[e]);
                    Vs[d * AT_STRIDE + r] = vh;
                    Vs[d * AT_STRIDE + 64 + r] =
                        __float2bfloat16_rn(vv[e] - __bfloat162float(vh));
                }
            }
        }
        __syncthreads();

        float s[8][4];
        #pragma unroll
        for (int j = 0; j < 8; j++)
            #pragma unroll
            for (int q = 0; q < 4; q++) s[j][q] = 0.f;

        #pragma unroll
        for (int phs = 0; phs < 3; phs++) {
            const int aoff = (phs == 1) ? 64 : 0;
            const int boff = (phs == 2) ? 64 : 0;
            #pragma unroll
            for (int ks = 0; ks < 4; ks++) {
                uint32_t a[4];
                const __nv_bfloat16* ap = Qs + row0 * AT_STRIDE + aoff + ks * 16 + c4 * 2;
                a[0] = *reinterpret_cast<const uint32_t*>(ap);
                a[1] = *reinterpret_cast<const uint32_t*>(ap + 8 * AT_STRIDE);
                a[2] = *reinterpret_cast<const uint32_t*>(ap + 8);
                a[3] = *reinterpret_cast<const uint32_t*>(ap + 8 * AT_STRIDE + 8);
                #pragma unroll
                for (int j = 0; j < 8; j++) {
                    uint32_t bf[2];
                    const __nv_bfloat16* bp =
                        Ks + (8 * j + g) * AT_STRIDE + boff + ks * 16 + c4 * 2;
                    bf[0] = *reinterpret_cast<const uint32_t*>(bp);
                    bf[1] = *reinterpret_cast<const uint32_t*>(bp + 8);
                    mma16(s[j], a, bf);
                }
            }
        }

        if (kt == qt) {
            #pragma unroll
            for (int j = 0; j < 8; j++) {
                const int colb = 8 * j + 2 * c4;
                if (colb     > row0)     s[j][0] = -1e30f;
                if (colb + 1 > row0)     s[j][1] = -1e30f;
                if (colb     > row0 + 8) s[j][2] = -1e30f;
                if (colb + 1 > row0 + 8) s[j][3] = -1e30f;
            }
        }

        float rm0 = -1e30f, rm1 = -1e30f;
        #pragma unroll
        for (int j = 0; j < 8; j++) {
            rm0 = fmaxf(rm0, fmaxf(s[j][0], s[j][1]));
            rm1 = fmaxf(rm1, fmaxf(s[j][2], s[j][3]));
        }
        rm0 = fmaxf(rm0, __shfl_xor_sync(0xFFFFFFFFu, rm0, 1));
        rm0 = fmaxf(rm0, __shfl_xor_sync(0xFFFFFFFFu, rm0, 2));
        rm1 = fmaxf(rm1, __shfl_xor_sync(0xFFFFFFFFu, rm1, 1));
        rm1 = fmaxf(rm1, __shfl_xor_sync(0xFFFFFFFFu, rm1, 2));
        const float mn0 = fmaxf(m0, rm0), mn1 = fmaxf(m1, rm1);
        const float cr0 = __expf(m0 - mn0), cr1 = __expf(m1 - mn1);
        m0 = mn0; m1 = mn1;

        float ps0 = 0.f, ps1 = 0.f;
        uint32_t phi[8][2], plo[8][2];
        #pragma unroll
        for (int j = 0; j < 8; j++) {
            float p0 = __expf(s[j][0] - mn0);
            float p1 = __expf(s[j][1] - mn0);
            float p2 = __expf(s[j][2] - mn1);
            float p3 = __expf(s[j][3] - mn1);
            ps0 += p0 + p1; ps1 += p2 + p3;
            __nv_bfloat16 h0 = __float2bfloat16_rn(p0), h1 = __float2bfloat16_rn(p1);
            __nv_bfloat16 h2 = __float2bfloat16_rn(p2), h3 = __float2bfloat16_rn(p3);
            phi[j][0] = pack_raw(h0, h1);
            phi[j][1] = pack_raw(h2, h3);
            plo[j][0] = pack_bf16x2(p0 - __bfloat162float(h0), p1 - __bfloat162float(h1));
            plo[j][1] = pack_bf16x2(p2 - __bfloat162float(h2), p3 - __bfloat162float(h3));
        }
        ps0 += __shfl_xor_sync(0xFFFFFFFFu, ps0, 1);
        ps0 += __shfl_xor_sync(0xFFFFFFFFu, ps0, 2);
        ps1 += __shfl_xor_sync(0xFFFFFFFFu, ps1, 1);
        ps1 += __shfl_xor_sync(0xFFFFFFFFu, ps1, 2);
        l0 = l0 * cr0 + ps0;
        l1 = l1 * cr1 + ps1;
        #pragma unroll
        for (int j = 0; j < 8; j++) {
            o[j][0] *= cr0; o[j][1] *= cr0;
            o[j][2] *= cr1; o[j][3] *= cr1;
        }

        #pragma unroll
        for (int phs = 0; phs < 3; phs++) {
            const int voff = (phs == 2) ? 64 : 0;
            #pragma unroll
            for (int ks = 0; ks < 4; ks++) {
                uint32_t a[4];
                if (phs == 1) {
                    a[0] = plo[2 * ks][0]; a[1] = plo[2 * ks][1];
                    a[2] = plo[2 * ks + 1][0]; a[3] = plo[2 * ks + 1][1];
                } else {
                    a[0] = phi[2 * ks][0]; a[1] = phi[2 * ks][1];
                    a[2] = phi[2 * ks + 1][0]; a[3] = phi[2 * ks + 1][1];
                }
                #pragma unroll
                for (int j = 0; j < 8; j++) {
                    uint32_t bf[2];
                    const __nv_bfloat16* bp =
                        Vs + (8 * j + g) * AT_STRIDE + voff + ks * 16 + c4 * 2;
                    bf[0] = *reinterpret_cast<const uint32_t*>(bp);
                    bf[1] = *reinterpret_cast<const uint32_t*>(bp + 8);
                    mma16(o[j], a, bf);
                }
            }
        }
    }

    const float inv0 = 1.f / l0, inv1 = 1.f / l1;
    const size_t r0 = (size_t)(b * S_ + qt * 64 + row0);
    __nv_bfloat16* o0 = conc3 + r0 * 3 * H_;
    __nv_bfloat16* o1 = conc3 + (r0 + 8) * 3 * H_;
    #pragma unroll
    for (int j = 0; j < 8; j++) {
        const int col = n * 64 + 8 * j + 2 * c4;
        store_split3(o0 + col, H_, o[j][0] * inv0, o[j][1] * inv0);
        store_split3(o1 + col, H_, o[j][2] * inv1, o[j][3] * inv1);
    }
}

// ---------------------------------------------------------------------------
// Split conversion / transpose / elementwise kernels
// ---------------------------------------------------------------------------
__global__ void conv_act_kernel(const float* __restrict__ in,
                                __nv_bfloat16* __restrict__ out,
                                int M, int K)
{
    int idx = blockIdx.x * blockDim.x + threadIdx.x;
    if (idx >= M * K) return;
    int row = idx / K;
    int k = idx - row * K;
    float x = in[idx];
    __nv_bfloat16 hi = __float2bfloat16_rn(x);
    __nv_bfloat16 lo = __float2bfloat16_rn(x - __bfloat162float(hi));
    size_t base = (size_t)row * 3 * K;
    out[base + k] = hi;
    out[base + K + k] = lo;
    out[base + 2 * K + k] = hi;
}

__global__ __launch_bounds__(256) void conv_wT_kernel(
    const float* __restrict__ W, __nv_bfloat16* __restrict__ out,
    int K, int N, float wscale)
{
    __shared__ float tile[32][33];
    const int tx = threadIdx.x & 31;
    const int ty = threadIdx.x >> 5;
    const int n0 = blockIdx.x * 32;
    const int k0 = blockIdx.y * 32;
    #pragma unroll
    for (int i = 0; i < 4; i++)
        tile[ty + i * 8][tx] = W[(size_t)(k0 + ty + i * 8) * N + n0 + tx];
    __syncthreads();
    #pragma unroll
    for (int i = 0; i < 4; i++) {
        const int nn = n0 + ty + i * 8;
        const int k = k0 + tx;
        float x = tile[tx][ty + i * 8] * wscale;
        __nv_bfloat16 hi = __float2bfloat16_rn(x);
        __nv_bfloat16 lo = __float2bfloat16_rn(x - __bfloat162float(hi));
        size_t base = (size_t)nn * 3 * K;
        out[base + k] = hi;
        out[base + K + k] = hi;
        out[base + 2 * K + k] = lo;
    }
}

__global__ void gather_kernel(const int* __restrict__ x,
                              const float* __restrict__ emb,
                              float* __restrict__ out)
{
    int idx = blockIdx.x * blockDim.x + threadIdx.x;
    if (idx >= M4 * E_) return;
    int i = idx / E_;
    int e = idx - i * E_;
    out[idx] = emb[(size_t)x[i] * E_ + e];
}

__global__ void addpos_kernel(const float* __restrict__ xemb,
                              const float* __restrict__ pos11,
                              float* __restrict__ out,
                              __nv_bfloat16* __restrict__ out3)
{
    int idx = blockIdx.x * blockDim.x + threadIdx.x;
    if (idx >= M4 * H_) return;
    int i = idx / H_;
    int h = idx - i * H_;
    int s = i & (S_ - 1);
    float y = xemb[idx] + pos11[(size_t)s * H_ + h];
    out[idx] = y;
    __nv_bfloat16 hi = __float2bfloat16_rn(y);
    __nv_bfloat16 lo = __float2bfloat16_rn(y - __bfloat162float(hi));
    size_t base = (size_t)i * 3 * H_;
    out3[base + h] = hi;
    out3[base + H_ + h] = lo;
    out3[base + 2 * H_ + h] = hi;
}

__global__ __launch_bounds__(256) void ln_res_kernel(
    const float* __restrict__ res, const float* __restrict__ x,
    const float* __restrict__ bias, const float* __restrict__ scale,
    float* __restrict__ out, __nv_bfloat16* __restrict__ out3)
{
    __shared__ float red[256];
    const int row = blockIdx.x;
    const int t = threadIdx.x;
    const float* xr = x + (size_t)row * H_;

    float lsum = 0.f;
    for (int i = t; i < H_; i += 256) lsum += xr[i];
    red[t] = lsum; __syncthreads();
    for (int s = 128; s > 0; s >>= 1) { if (t < s) red[t] += red[t + s]; __syncthreads(); }
    const float mean = red[0] * (1.0f / H_);
    __syncthreads();

    float lvar = 0.f;
    for (int i = t; i < H_; i += 256) { float d = xr[i] - mean; lvar += d * d; }
    red[t] = lvar; __syncthreads();
    for (int s = 128; s > 0; s >>= 1) { if (t < s) red[t] += red[t + s]; __syncthreads(); }
    const float rstd = rsqrtf(red[0] * (1.0f / H_) + 1e-6f);

    for (int i = t; i < H_; i += 256) {
        float y = res[(size_t)row * H_ + i] + (xr[i] - mean) * rstd * scale[i] + bias[i];
        out[(size_t)row * H_ + i] = y;
        if (out3) {
            __nv_bfloat16 hi = __float2bfloat16_rn(y);
            __nv_bfloat16 lo = __float2bfloat16_rn(y - __bfloat162float(hi));
            size_t base = (size_t)row * 3 * H_;
            out3[base + i] = hi;
            out3[base + H_ + i] = lo;
            out3[base + 2 * H_ + i] = hi;
        }
    }
}

// ---------------------------------------------------------------------------
// Launch helpers
// ---------------------------------------------------------------------------
static inline void run_gemm(const __nv_bfloat16* A3, const __nv_bfloat16* B3,
                            const float* bias, float* C, __nv_bfloat16* out3,
                            int M, int N, int K3, float alpha, int relu)
{
    dim3 grid(M / GBM, N / GBN);
    gemm_bf16_kernel<<<grid, 256, GEMM_SMEM_BYTES>>>(A3, B3, bias, C, out3,
                                                     M, N, K3, alpha, relu);
}
static inline void run_gemm256(const __nv_bfloat16* A3, const __nv_bfloat16* B3,
                               const float* bias, float* C, __nv_bfloat16* out3,
                               int M, int N, int K3, float alpha, int relu)
{
    dim3 grid(M / 256, N / 256);
    gemm256_kernel<<<grid, 256, G2_SMEM>>>(A3, B3, bias, C, out3,
                                           M, N, K3, alpha, relu);
}
static inline void run_conv_wT(const float* W, __nv_bfloat16* out,
                               int K, int N, float wscale)
{
    dim3 grid(N / 32, K / 32);
    conv_wT_kernel<<<grid, 256>>>(W, out, K, N, wscale);
}

extern "C" void kernel_launch(void* const* d_in, const int* in_sizes, int n_in,
                              void* d_out, int out_size)
{
    const int*   x            = (const int*)  d_in[0];
    const float* emb_decode   = (const float*)d_in[1];
    const float* W_dec_lin    = (const float*)d_in[2];
    const float* p_decoder    = (const float*)d_in[3];
    const float* x_emb_pos    = (const float*)d_in[4];
    const float* p_d_q        = (const float*)d_in[5];
    const float* p_d_k        = (const float*)d_in[6];
    const float* p_d_v        = (const float*)d_in[7];
    const float* p_d_c        = (const float*)d_in[8];
    const float* p_d_ff1      = (const float*)d_in[9];
    const float* p_d_ff2      = (const float*)d_in[10];
    const float* b_d_ff1      = (const float*)d_in[11];
    const float* b_d_ff2      = (const float*)d_in[12];
    const float* d_o_bias     = (const float*)d_in[13];
    const float* d_o_scale    = (const float*)d_in[14];
    const float* b_d_bias_1   = (const float*)d_in[15];
    const float* b_d_bias_2   = (const float*)d_in[16];
    const float* b_d_scale_1  = (const float*)d_in[17];
    const float* b_d_scale_2  = (const float*)d_in[18];
    float* out = (float*)d_out;

    const int m = L_ - 1;   // only the last layer's result is observable

    cudaFuncSetAttribute(gemm_bf16_kernel,
                         cudaFuncAttributeMaxDynamicSharedMemorySize, GEMM_SMEM_BYTES);
    cudaFuncSetAttribute(gemm256_kernel,
                         cudaFuncAttributeMaxDynamicSharedMemorySize, G2_SMEM);
    cudaFuncSetAttribute(attn_mma_kernel,
                         cudaFuncAttributeMaxDynamicSharedMemorySize, ATT_SMEM);

    float *Aemb, *xemb, *layerin, *qkv, *xmulti, *xself,
          *ffw1, *ffw2, *xffw, *decout;
    __nv_bfloat16 *a3_emb, *a3_li, *a3_conc, *a3_self, *a3_ffw1, *a3_dec;
    __nv_bfloat16 *w3_dec, *w3_qkv, *w3_c, *w3_ff1, *w3_ff2, *w3_pdec;
    cudaGetSymbolAddress((void**)&Aemb,    g_Aemb);
    cudaGetSymbolAddress((void**)&xemb,    g_xemb);
    cudaGetSymbolAddress((void**)&layerin, g_layerin);
    cudaGetSymbolAddress((void**)&qkv,     g_qkv);
    cudaGetSymbolAddress((void**)&xmulti,  g_xmulti);
    cudaGetSymbolAddress((void**)&xself,   g_xself);
    cudaGetSymbolAddress((void**)&ffw1,    g_ffw1);
    cudaGetSymbolAddress((void**)&ffw2,    g_ffw2);
    cudaGetSymbolAddress((void**)&xffw,    g_xffw);
    cudaGetSymbolAddress((void**)&decout,  g_decout);
    cudaGetSymbolAddress((void**)&a3_emb,  g_a3_emb);
    cudaGetSymbolAddress((void**)&a3_li,   g_a3_li);
    cudaGetSymbolAddress((void**)&a3_conc, g_a3_conc);
    cudaGetSymbolAddress((void**)&a3_self, g_a3_self);
    cudaGetSymbolAddress((void**)&a3_ffw1, g_a3_ffw1);
    cudaGetSymbolAddress((void**)&a3_dec,  g_a3_dec);
    cudaGetSymbolAddress((void**)&w3_dec,  g_w3_dec);
    cudaGetSymbolAddress((void**)&w3_qkv,  g_w3_qkv);
    cudaGetSymbolAddress((void**)&w3_c,    g_w3_c);
    cudaGetSymbolAddress((void**)&w3_ff1,  g_w3_ff1);
    cudaGetSymbolAddress((void**)&w3_ff2,  g_w3_ff2);
    cudaGetSymbolAddress((void**)&w3_pdec, g_w3_pdec);

    // weight conversions (split + transpose); Q weights pre-scaled by 1/sqrt(head)
    run_conv_wT(W_dec_lin, w3_dec, E_, H_, 1.f);
    run_conv_wT(p_d_q + (size_t)m * H_ * H_, w3_qkv, H_, H_, 0.125f);
    run_conv_wT(p_d_k + (size_t)m * H_ * H_, w3_qkv + (size_t)1024 * 3 * H_, H_, H_, 1.f);
    run_conv_wT(p_d_v + (size_t)m * H_ * H_, w3_qkv + (size_t)2048 * 3 * H_, H_, H_, 1.f);
    run_conv_wT(p_d_c + (size_t)m * H_ * H_, w3_c, H_, H_, 1.f);
    run_conv_wT(p_d_ff1 + (size_t)m * H_ * FF_, w3_ff1, H_, FF_, 1.f);
    run_conv_wT(p_d_ff2 + (size_t)m * FF_ * H_, w3_ff2, FF_, H_, 1.f);
    run_conv_wT(p_decoder, w3_pdec, H_, V_, 1.f);

    // 1. gather embeddings + split
    gather_kernel<<<(M4 * E_ + 255) / 256, 256>>>(x, emb_decode, Aemb);
    conv_act_kernel<<<(M4 * E_ + 255) / 256, 256>>>(Aemb, a3_emb, M4, E_);

    // 2. x_dec_embed = A_emb @ W_dec_lin
    run_gemm(a3_emb, w3_dec, nullptr, xemb, nullptr, M4, H_, 3 * E_, 1.f, 0);

    // 3. layer_in = pos[11] + x_dec_embed  (+ fused split)
    addpos_kernel<<<(M4 * H_ + 255) / 256, 256>>>(
        xemb, x_emb_pos + (size_t)m * S_ * H_, layerin, a3_li);

    // 4. fused Q/K/V projection (one N=3072 GEMM; Q scaling folded into weights)
    run_gemm256(a3_li, w3_qkv, nullptr, qkv, nullptr, M4, QKVS, 3 * H_, 1.f, 0);

    // 5. tensor-core causal attention -> a3_conc (split, fused)
    attn_mma_kernel<<<dim3(S_ / 64, B_ * NH_), 128, ATT_SMEM>>>(
        qkv, qkv + 1024, qkv + 2048, a3_conc);

    // 6. x_multi = conc @ p_d_c
    run_gemm(a3_conc, w3_c, nullptr, xmulti, nullptr, M4, H_, 3 * H_, 1.f, 0);

    // 7. x_self = layer_in + LN(x_multi)  (+ fused split)
    ln_res_kernel<<<M4, 256>>>(layerin, xmulti,
                               b_d_bias_1 + (size_t)m * H_,
                               b_d_scale_1 + (size_t)m * H_, xself, a3_self);

    // 8. FFN (ffw1 via 256-tile kernel, split output fused)
    run_gemm256(a3_self, w3_ff1, b_d_ff1 + (size_t)m * FF_, ffw1, a3_ffw1,
                M4, FF_, 3 * H_, 1.f, 1);
    run_gemm(a3_ffw1, w3_ff2, b_d_ff2 + (size_t)m * H_, ffw2, nullptr,
             M4, H_, 3 * FF_, 1.f, 0);

    // 9. x_ffw = x_self + LN(ffw2)
    ln_res_kernel<<<M4, 256>>>(xself, ffw2,
                               b_d_bias_2 + (size_t)m * H_,
                               b_d_scale_2 + (size_t)m * H_, xffw, nullptr);

    // 10. dec_outputs = x_dec_embed + LN(x_ffw)  (+ fused split)
    ln_res_kernel<<<M4, 256>>>(xemb, xffw, d_o_bias, d_o_scale, decout, a3_dec);

    // 11. logits = dec_outputs @ p_decoder  (256-tile, halved L2 traffic)
    run_gemm256(a3_dec, w3_pdec, nullptr, out, nullptr, M4, V_, 3 * H_, 1.f, 0);
}

// round 9
// speedup vs baseline: 5.8107x; 1.0918x over previous
#include <cuda_runtime.h>
#include <cuda_bf16.h>
#include <cstdint>

// Problem constants
#define L_   12
#define NH_  16
#define H_   1024
#define FF_  4096
#define V_   32000
#define S_   1024
#define E_   128
#define B_   4
#define HEAD_ 64
#define M4   (B_ * S_)   // 4096 rows total
#define QKVS 3072        // fused qkv row stride (floats)

// Arch-feature dispatch: tcgen05 only legal in the sm_103a pass.
#if defined(__CUDA_ARCH__) && defined(__CUDA_ARCH_FEAT_SM103_ALL)
#define TC_PATH 1
#else
#define TC_PATH 0
#endif

// ---------------------------------------------------------------------------
// Scratch (device globals — allocation-free per harness rules)
// ---------------------------------------------------------------------------
__device__ float g_Aemb   [M4 * E_];
__device__ float g_xemb   [M4 * H_];
__device__ float g_layerin[M4 * H_];
__device__ float g_qkv    [M4 * QKVS];
__device__ float g_xmulti [M4 * H_];
__device__ float g_xself  [M4 * H_];
__device__ float g_ffw1   [M4 * FF_];
__device__ float g_ffw2   [M4 * H_];
__device__ float g_xffw   [M4 * H_];
__device__ float g_decout [M4 * H_];   // RNA-tf32-rounded fp32 (feeds logits GEMM)

// bf16 split-K3 operand buffers.  A' = [hi | lo | hi] (row-major, 3K cols),
// B' = [hi | hi | lo] as [N, 3K] (k-contiguous, i.e. transposed weight).
__device__ __align__(128) __nv_bfloat16 g_a3_emb [M4 * 3 * E_];
__device__ __align__(128) __nv_bfloat16 g_a3_li  [M4 * 3 * H_];
__device__ __align__(128) __nv_bfloat16 g_a3_conc[M4 * 3 * H_];
__device__ __align__(128) __nv_bfloat16 g_a3_self[M4 * 3 * H_];
__device__ __align__(128) __nv_bfloat16 g_a3_ffw1[(size_t)M4 * 3 * FF_];

__device__ __align__(128) __nv_bfloat16 g_w3_dec [H_ * 3 * E_];
__device__ __align__(128) __nv_bfloat16 g_w3_qkv [(size_t)QKVS * 3 * H_];
__device__ __align__(128) __nv_bfloat16 g_w3_c   [H_ * 3 * H_];
__device__ __align__(128) __nv_bfloat16 g_w3_ff1 [(size_t)FF_ * 3 * H_];
__device__ __align__(128) __nv_bfloat16 g_w3_ff2 [(size_t)H_ * 3 * FF_];
// p_decoder transposed, RNA-tf32-rounded fp32  [V, H]
__device__ __align__(128) float g_wtp [(size_t)V_ * H_];

// ---------------------------------------------------------------------------
// PTX helpers — baseline-legal
// ---------------------------------------------------------------------------
__device__ __forceinline__ uint32_t smem_u32(const void* p) {
    uint32_t a;
    asm("{ .reg .u64 t; cvta.to.shared.u64 t, %1; cvt.u32.u64 %0, t; }"
        : "=r"(a) : "l"(p));
    return a;
}
__device__ __forceinline__ void cp16(uint32_t dst, const void* src) {
    asm volatile("cp.async.cg.shared.global [%0], [%1], 16;"
                 :: "r"(dst), "l"(src) : "memory");
}
__device__ __forceinline__ void cp_commit() {
    asm volatile("cp.async.commit_group;" ::: "memory");
}
template <int N>
__device__ __forceinline__ void cp_wait() {
    asm volatile("cp.async.wait_group %0;" :: "n"(N) : "memory");
}
__device__ __forceinline__ uint32_t elect_one_pred() {
    uint32_t pred;
    asm volatile(
        "{\n\t.reg .pred p;\n\telect.sync _|p, 0xFFFFFFFF;\n\t"
        "selp.b32 %0, 1, 0, p;\n\t}" : "=r"(pred));
    return pred;
}
// legacy m16n8k16 bf16 MMA, fp32 accumulate (sm_80+)
__device__ __forceinline__ void mma16(float* d, const uint32_t* a, const uint32_t* b) {
    asm volatile(
        "mma.sync.aligned.m16n8k16.row.col.f32.bf16.bf16.f32 "
        "{%0,%1,%2,%3}, {%4,%5,%6,%7}, {%8,%9}, {%0,%1,%2,%3};"
        : "+f"(d[0]), "+f"(d[1]), "+f"(d[2]), "+f"(d[3])
        : "r"(a[0]), "r"(a[1]), "r"(a[2]), "r"(a[3]),
          "r"(b[0]), "r"(b[1]));
}
__device__ __forceinline__ uint32_t pack_bf16x2(float lo_elem, float hi_elem) {
    uint32_t r;
    asm("cvt.rn.bf16x2.f32 %0, %1, %2;" : "=r"(r) : "f"(hi_elem), "f"(lo_elem));
    return r;
}
__device__ __forceinline__ uint32_t pack_raw(__nv_bfloat16 lo, __nv_bfloat16 hi) {
    return (uint32_t)__bfloat16_as_ushort(lo) | ((uint32_t)__bfloat16_as_ushort(hi) << 16);
}
// RNA round fp32 -> tf32 (bit pattern stays a valid fp32)
__device__ __forceinline__ float rna_tf32(float v) {
    uint32_t r;
    asm("cvt.rna.tf32.f32 %0, %1;" : "=r"(r) : "f"(v));
    return __uint_as_float(r);
}

#define SMEM_SWIZZLE_128B(o) ((o) ^ (((o) >> 3) & 0x70))

#if TC_PATH
// ---- tcgen05 helpers (only compiled in the sm_103a pass) ----
#define TCGEN05_ALLOC(smem_addr, nCols) \
    asm volatile("tcgen05.alloc.cta_group::1.sync.aligned.shared::cta.b32 [%0], %1;" \
                 :: "r"((uint32_t)(smem_addr)), "r"((uint32_t)(nCols)) : "memory")
#define TCGEN05_DEALLOC(tmem_addr, nCols) \
    asm volatile("tcgen05.dealloc.cta_group::1.sync.aligned.b32 %0, %1;" \
                 :: "r"(tmem_addr), "r"((uint32_t)(nCols)))
#define TCGEN05_RELINQUISH() \
    asm volatile("tcgen05.relinquish_alloc_permit.cta_group::1.sync.aligned;")
#define TCGEN05_COMMIT(mbar) \
    asm volatile("tcgen05.commit.cta_group::1.mbarrier::arrive::one.shared::cluster.b64 [%0];" \
                 :: "r"((uint32_t)(mbar)) : "memory")
#define TCGEN05_FENCE_AFTER() \
    asm volatile("tcgen05.fence::after_thread_sync;" ::: "memory")
#define TCGEN05_FENCE_BEFORE() \
    asm volatile("tcgen05.fence::before_thread_sync;" ::: "memory")
#define TCGEN05_WAIT_LD() \
    asm volatile("tcgen05.wait::ld.sync.aligned;" ::: "memory")
#define MBARRIER_INIT(mbar, cnt) \
    asm volatile("mbarrier.init.shared.b64 [%0], %1;" \
                 :: "r"((uint32_t)(mbar)), "r"((uint32_t)(cnt)) : "memory")
#define MBARRIER_INVAL(mbar) \
    asm volatile("mbarrier.inval.shared.b64 [%0];" :: "r"((uint32_t)(mbar)) : "memory")
#define FENCE_PROXY_ASYNC() \
    asm volatile("fence.proxy.async.shared::cta;" ::: "memory")

#define MBARRIER_WAIT_PARITY(mbar_smem_addr, phase_parity) do { \
    uint32_t _mbar = (uint32_t)(mbar_smem_addr); \
    uint32_t _parity = (uint32_t)(phase_parity); \
    uint32_t _done; \
    asm volatile("{\n\t.reg .pred p;\n\t" \
        "mbarrier.try_wait.parity.acquire.cta.shared::cta.b64 p, [%1], %2;\n\t" \
        "selp.b32 %0, 1, 0, p;\n\t}" \
        : "=r"(_done) : "r"(_mbar), "r"(_parity) : "memory"); \
    if (!_done) { \
        asm volatile("{\n\t.reg .pred P1;\n\t" \
            "WAIT_LOOP_%=:\n\t" \
            "mbarrier.try_wait.parity.acquire.cta.shared::cta.b64 P1, [%0], %1, 0x989680;\n\t" \
            "@P1 bra.uni WAIT_DONE_%=;\n\t" \
            "bra.uni WAIT_LOOP_%=;\n\t" \
            "WAIT_DONE_%=:\n\t}" \
            :: "r"(_mbar), "r"(_parity) : "memory"); \
    } \
} while(0)

#define TCGEN05_LD_32X32B_X32(r, tmem_addr) \
    asm volatile( \
        "tcgen05.ld.sync.aligned.32x32b.x32.b32 " \
        "{%0, %1, %2, %3, %4, %5, %6, %7, " \
        " %8, %9, %10, %11, %12, %13, %14, %15, " \
        " %16, %17, %18, %19, %20, %21, %22, %23, " \
        " %24, %25, %26, %27, %28, %29, %30, %31}, [%32];" \
        : "=r"((r)[0]),  "=r"((r)[1]),  "=r"((r)[2]),  "=r"((r)[3]), \
          "=r"((r)[4]),  "=r"((r)[5]),  "=r"((r)[6]),  "=r"((r)[7]), \
          "=r"((r)[8]),  "=r"((r)[9]),  "=r"((r)[10]), "=r"((r)[11]), \
          "=r"((r)[12]), "=r"((r)[13]), "=r"((r)[14]), "=r"((r)[15]), \
          "=r"((r)[16]), "=r"((r)[17]), "=r"((r)[18]), "=r"((r)[19]), \
          "=r"((r)[20]), "=r"((r)[21]), "=r"((r)[22]), "=r"((r)[23]), \
          "=r"((r)[24]), "=r"((r)[25]), "=r"((r)[26]), "=r"((r)[27]), \
          "=r"((r)[28]), "=r"((r)[29]), "=r"((r)[30]), "=r"((r)[31]) \
        : "r"(tmem_addr))

static constexpr uint64_t SMEM_DESC_BASE_SW128 =
    (uint64_t(2) << 61) | (uint64_t(1) << 46) | (uint64_t(64) << 32) | (uint64_t(1) << 16);
#define MAKE_SMEM_DESC(addr) (SMEM_DESC_BASE_SW128 | ((uint64_t)((addr) >> 4) & 0x3FFF))

__device__ __forceinline__ void mma_bf16_ss(uint32_t d_tmem, uint64_t a_desc,
                                            uint64_t b_desc, uint32_t idesc,
                                            uint32_t enable_d) {
    uint32_t z = 0;
    asm volatile(
        "{\n\t.reg .pred p;\n\tsetp.ne.u32 p, %5, 0;\n\t"
        "tcgen05.mma.cta_group::1.kind::f16 [%0], %1, %2, %3, {%4, %4, %4, %4}, p;\n\t}"
        :: "r"(d_tmem), "l"(a_desc), "l"(b_desc), "r"(idesc), "r"(z), "r"(enable_d)
        : "memory");
}
__device__ __forceinline__ void mma_tf32_ss(uint32_t d_tmem, uint64_t a_desc,
                                            uint64_t b_desc, uint32_t idesc,
                                            uint32_t enable_d) {
    uint32_t z = 0;
    asm volatile(
        "{\n\t.reg .pred p;\n\tsetp.ne.u32 p, %5, 0;\n\t"
        "tcgen05.mma.cta_group::1.kind::tf32 [%0], %1, %2, %3, {%4, %4, %4, %4}, p;\n\t}"
        :: "r"(d_tmem), "l"(a_desc), "l"(b_desc), "r"(idesc), "r"(z), "r"(enable_d)
        : "memory");
}
#endif // TC_PATH

// ---------------------------------------------------------------------------
// Shared epilogue value transform
// ---------------------------------------------------------------------------
__device__ __forceinline__ void store_split3(__nv_bfloat16* op, int N,
                                             float v0, float v1) {
    __nv_bfloat16 h0 = __float2bfloat16_rn(v0);
    __nv_bfloat16 h1 = __float2bfloat16_rn(v1);
    uint32_t hp = pack_raw(h0, h1);
    uint32_t lp = pack_bf16x2(v0 - __bfloat162float(h0), v1 - __bfloat162float(h1));
    *reinterpret_cast<uint32_t*>(op) = hp;
    *reinterpret_cast<uint32_t*>(op + N) = lp;
    *reinterpret_cast<uint32_t*>(op + 2 * N) = hp;
}

// ---------------------------------------------------------------------------
// Legacy HMMA 128x128 tile (compute_103 fallback only)
// ---------------------------------------------------------------------------
#define GBM 128
#define GBN 128
#define GBK 64
#define RSTRIDE 36
#define ABUF (128 * RSTRIDE)
#define BBUF (128 * RSTRIDE)
#define GEMM_SMEM_BYTES 99328

#if !TC_PATH
__device__ void legacy_tile128(
    const __nv_bfloat16* __restrict__ A3, const __nv_bfloat16* __restrict__ B3,
    const float* __restrict__ bias, float* __restrict__ C,
    __nv_bfloat16* __restrict__ out3,
    int N, int K3, float alpha, int do_relu,
    int m0, int n0, uint32_t* sm, uint32_t smb)
{
    const int tid = threadIdx.x;
    const int wid = tid >> 5, lane = tid & 31;
    const int g = lane >> 2, c4 = lane & 3;
    const int warp_m = wid >> 2;
    const int warp_n = wid & 3;

    const int srow = tid >> 1, spart = tid & 1;
    const __nv_bfloat16* aptr = A3 + (size_t)(m0 + srow) * K3 + spart * 32;
    const __nv_bfloat16* bptr = B3 + (size_t)(n0 + srow) * K3 + spart * 32;
    const uint32_t as_base = smb + (srow * RSTRIDE + spart * 16) * 4;
    const uint32_t bs_base = smb + (2 * ABUF + srow * RSTRIDE + spart * 16) * 4;

    const int NC = K3 / GBK;

    float acc[4][4][4];
    #pragma unroll
    for (int i = 0; i < 4; i++)
        #pragma unroll
        for (int j = 0; j < 4; j++)
            #pragma unroll
            for (int q = 0; q < 4; q++) acc[i][j][q] = 0.f;

    #pragma unroll
    for (int q = 0; q < 4; q++) cp16(as_base + q * 16, aptr + q * 8);
    #pragma unroll
    for (int q = 0; q < 4; q++) cp16(bs_base + q * 16, bptr + q * 8);
    cp_commit();

    for (int c = 0; c < NC; c++) {
        if (c + 1 < NC) {
            const int nb = (c + 1) & 1;
            const __nv_bfloat16* ap = aptr + (c + 1) * GBK;
            const __nv_bfloat16* bp = bptr + (c + 1) * GBK;
            #pragma unroll
            for (int q = 0; q < 4; q++)
                cp16(as_base + nb * ABUF * 4 + q * 16, ap + q * 8);
            #pragma unroll
            for (int q = 0; q < 4; q++)
                cp16(bs_base + nb * BBUF * 4 + q * 16, bp + q * 8);
            cp_commit();
            cp_wait<1>();
        } else {
            cp_wait<0>();
        }
        __syncthreads();

        const uint32_t* ab = sm + (c & 1) * ABUF;
        const uint32_t* bb = sm + 2 * ABUF + (c & 1) * BBUF;

        #pragma unroll
        for (int ks = 0; ks < 4; ks++) {
            const int kb = ks * 8;
            uint32_t af[4][4], bf[4][2];
            #pragma unroll
            for (int i = 0; i < 4; i++) {
                const uint32_t* p = ab + (warp_m * 64 + i * 16 + g) * RSTRIDE + kb + c4;
                af[i][0] = p[0];
                af[i][1] = p[8 * RSTRIDE];
                af[i][2] = p[4];
                af[i][3] = p[8 * RSTRIDE + 4];
            }
            #pragma unroll
            for (int j = 0; j < 4; j++) {
                const uint32_t* p = bb + (warp_n * 32 + j * 8 + g) * RSTRIDE + kb + c4;
                bf[j][0] = p[0];
                bf[j][1] = p[4];
            }
            #pragma unroll
            for (int i = 0; i < 4; i++)
                #pragma unroll
                for (int j = 0; j < 4; j++)
                    mma16(acc[i][j], af[i], bf[j]);
        }
        __syncthreads();
    }

    #pragma unroll
    for (int i = 0; i < 4; i++) {
        #pragma unroll
        for (int j = 0; j < 4; j++) {
            const int col = n0 + warp_n * 32 + j * 8 + c4 * 2;
            float b0v = 0.f, b1v = 0.f;
            if (bias) { b0v = bias[col]; b1v = bias[col + 1]; }
            float v0 = acc[i][j][0] * alpha + b0v;
            float v1 = acc[i][j][1] * alpha + b1v;
            float v2 = acc[i][j][2] * alpha + b0v;
            float v3 = acc[i][j][3] * alpha + b1v;
            if (do_relu) {
                v0 = fmaxf(v0, 0.f); v1 = fmaxf(v1, 0.f);
                v2 = fmaxf(v2, 0.f); v3 = fmaxf(v3, 0.f);
            }
            const int ra = m0 + warp_m * 64 + i * 16 + g;
            if (out3) {
                store_split3(out3 + (size_t)ra * 3 * N + col, N, v0, v1);
                store_split3(out3 + (size_t)(ra + 8) * 3 * N + col, N, v2, v3);
            } else {
                float2 lo = {v0, v1}, hi = {v2, v3};
                *reinterpret_cast<float2*>(C + (size_t)ra * N + col) = lo;
                *reinterpret_cast<float2*>(C + (size_t)(ra + 8) * N + col) = hi;
            }
        }
    }
}
#endif // !TC_PATH

// ---------------------------------------------------------------------------
// 128x128 bf16-split GEMM (N=1024 cases)
// ---------------------------------------------------------------------------
__global__ __launch_bounds__(256, 2) void gemm_bf16_kernel(
    const __nv_bfloat16* __restrict__ A3, const __nv_bfloat16* __restrict__ B3,
    const float* __restrict__ bias, float* __restrict__ C,
    __nv_bfloat16* __restrict__ out3,
    int M, int N, int K3, float alpha, int do_relu)
{
#if TC_PATH
    extern __shared__ char smc[];
    const uint32_t smb = smem_u32(smc);
    const int tid = threadIdx.x;
    const int wid = tid >> 5, lane = tid & 31;
    const int m0 = blockIdx.x * GBM;
    const int n0 = blockIdx.y * GBN;

    const uint32_t sa[3] = {1024u, 1024u + 16384u, 1024u + 32768u};
    const uint32_t sb[3] = {1024u + 49152u, 1024u + 65536u, 1024u + 81920u};
    const uint32_t mb[3] = {smb + 8u, smb + 16u, smb + 24u};

    if (wid == 0) TCGEN05_ALLOC(smb, 128);
    if (tid == 0) { MBARRIER_INIT(mb[0], 1); MBARRIER_INIT(mb[1], 1); MBARRIER_INIT(mb[2], 1); }
    __syncthreads();
    uint32_t tmem;
    asm volatile("ld.shared.b32 %0, [%1];" : "=r"(tmem) : "r"(smb));
    if (wid == 0) TCGEN05_RELINQUISH();

    const uint32_t IDESC =
        (1u << 4) | (1u << 7) | (1u << 10) | ((GBN / 8) << 17) | ((GBM / 16) << 24);

    const int NC = K3 / GBK;
    const int r0s = tid >> 3;
    const int c8 = tid & 7;
    const __nv_bfloat16* abase = A3 + (size_t)(m0 + r0s) * K3 + c8 * 8;
    const __nv_bfloat16* bbase = B3 + (size_t)(n0 + r0s) * K3 + c8 * 8;
    const uint32_t swoff[4] = {
        SMEM_SWIZZLE_128B((uint32_t)((r0s +  0) * 128 + c8 * 16)),
        SMEM_SWIZZLE_128B((uint32_t)((r0s + 32) * 128 + c8 * 16)),
        SMEM_SWIZZLE_128B((uint32_t)((r0s + 64) * 128 + c8 * 16)),
        SMEM_SWIZZLE_128B((uint32_t)((r0s + 96) * 128 + c8 * 16))};

    auto stage_chunk = [&](int chunk, int buf) {
        #pragma unroll
        for (int it = 0; it < 4; it++) {
            cp16(smb + sa[buf] + swoff[it], abase + (size_t)it * 32 * K3 + chunk * GBK);
            cp16(smb + sb[buf] + swoff[it], bbase + (size_t)it * 32 * K3 + chunk * GBK);
        }
        cp_commit();
    };

    int ph[3] = {0, 0, 0};
    stage_chunk(0, 0);
    stage_chunk(1, 1);

    for (int c = 0; c < NC; c++) {
        const int b = c % 3;
        if (c + 2 < NC) {
            const int nb = (c + 2) % 3;
            if (c >= 1) { MBARRIER_WAIT_PARITY(mb[nb], ph[nb]); ph[nb] ^= 1; }
            stage_chunk(c + 2, nb);
            cp_wait<2>();
        } else if (c + 1 < NC) {
            cp_wait<1>();
        } else {
            cp_wait<0>();
        }
        __syncthreads();
        if (wid == 0 && elect_one_pred()) {
            FENCE_PROXY_ASYNC();
            const uint64_t ad = MAKE_SMEM_DESC(smb + sa[b]);
            const uint64_t bd = MAKE_SMEM_DESC(smb + sb[b]);
            #pragma unroll
            for (int ks = 0; ks < 4; ks++)
                mma_bf16_ss(tmem, ad + ks * 2, bd + ks * 2, IDESC,
                            (c > 0 || ks > 0) ? 1u : 0u);
            TCGEN05_COMMIT(mb[b]);
        }
    }
    MBARRIER_WAIT_PARITY(mb[(NC - 1) % 3], ph[(NC - 1) % 3]);
    TCGEN05_FENCE_AFTER();

    if (wid < 4) {
        const uint32_t lofs = (uint32_t)wid << 21;
        const int row = m0 + wid * 32 + lane;
        #pragma unroll
        for (int j = 0; j < 4; j++) {
            uint32_t r[32];
            TCGEN05_LD_32X32B_X32(r, tmem + j * 32 + lofs);
            TCGEN05_WAIT_LD();
            const float* bp = bias ? (bias + n0 + j * 32) : nullptr;
            if (out3) {
                __nv_bfloat16* op = out3 + (size_t)row * 3 * N + n0 + j * 32;
                #pragma unroll
                for (int q = 0; q < 32; q += 2) {
                    float v0 = __uint_as_float(r[q + 0]) * alpha;
                    float v1 = __uint_as_float(r[q + 1]) * alpha;
                    if (bp) { v0 += bp[q]; v1 += bp[q + 1]; }
                    if (do_relu) { v0 = fmaxf(v0, 0.f); v1 = fmaxf(v1, 0.f); }
                    store_split3(op + q, N, v0, v1);
                }
            } else {
                float* cp = C + (size_t)row * N + n0 + j * 32;
                #pragma unroll
                for (int q = 0; q < 32; q += 4) {
                    float v0 = __uint_as_float(r[q + 0]) * alpha;
                    float v1 = __uint_as_float(r[q + 1]) * alpha;
                    float v2 = __uint_as_float(r[q + 2]) * alpha;
                    float v3 = __uint_as_float(r[q + 3]) * alpha;
                    if (bp) { v0 += bp[q]; v1 += bp[q + 1]; v2 += bp[q + 2]; v3 += bp[q + 3]; }
                    if (do_relu) {
                        v0 = fmaxf(v0, 0.f); v1 = fmaxf(v1, 0.f);
                        v2 = fmaxf(v2, 0.f); v3 = fmaxf(v3, 0.f);
                    }
                    float4 o = {v0, v1, v2, v3};
                    *reinterpret_cast<float4*>(cp + q) = o;
                }
            }
        }
        TCGEN05_FENCE_BEFORE();
    }
    __syncthreads();
    if (tid == 0) { MBARRIER_INVAL(mb[0]); MBARRIER_INVAL(mb[1]); MBARRIER_INVAL(mb[2]); }
    __syncthreads();
    if (wid == 0) TCGEN05_DEALLOC(tmem, 128);
#else
    extern __shared__ uint32_t sm[];
    const uint32_t smb = smem_u32(sm);
    legacy_tile128(A3, B3, bias, C, out3, N, K3, alpha, do_relu,
                   blockIdx.x * GBM, blockIdx.y * GBN, sm, smb);
#endif
}

// ---------------------------------------------------------------------------
// 256x256 bf16-split GEMM (big-N chained cases)
// ---------------------------------------------------------------------------
#define G2K 64
#define G2_SMEM (1024 + 3 * 65536)   // 197632 B

__global__ __launch_bounds__(256, 1) void gemm256_kernel(
    const __nv_bfloat16* __restrict__ A3, const __nv_bfloat16* __restrict__ B3,
    const float* __restrict__ bias, float* __restrict__ C,
    __nv_bfloat16* __restrict__ out3,
    int M, int N, int K3, float alpha, int do_relu)
{
#if TC_PATH
    extern __shared__ char smc[];
    const uint32_t smb = smem_u32(smc);
    const int tid = threadIdx.x;
    const int wid = tid >> 5, lane = tid & 31;
    const int m0 = blockIdx.x * 256;
    const int n0 = blockIdx.y * 256;

    const uint32_t mb[3] = {smb + 8u, smb + 16u, smb + 24u};

    if (wid == 0) TCGEN05_ALLOC(smb, 512);
    if (tid == 0) { MBARRIER_INIT(mb[0], 1); MBARRIER_INIT(mb[1], 1); MBARRIER_INIT(mb[2], 1); }
    __syncthreads();
    uint32_t tmem;
    asm volatile("ld.shared.b32 %0, [%1];" : "=r"(tmem) : "r"(smb));
    if (wid == 0) TCGEN05_RELINQUISH();

    const uint32_t IDESC2 =
        (1u << 4) | (1u << 7) | (1u << 10) | ((256 / 8) << 17) | ((128 / 16) << 24);

    const int NC = K3 / G2K;
    const int r0s = tid >> 3;
    const int c8 = tid & 7;
    const __nv_bfloat16* abase = A3 + (size_t)(m0 + r0s) * K3 + c8 * 8;
    const __nv_bfloat16* bbase = B3 + (size_t)(n0 + r0s) * K3 + c8 * 8;
    uint32_t swoff[8];
    #pragma unroll
    for (int it = 0; it < 8; it++)
        swoff[it] = SMEM_SWIZZLE_128B((uint32_t)((r0s + it * 32) * 128 + c8 * 16));

    auto stage_chunk = [&](int chunk, int buf) {
        const uint32_t sa = smb + 1024u + (uint32_t)buf * 65536u;
        const uint32_t sbo = sa + 32768u;
        #pragma unroll
        for (int it = 0; it < 8; it++) {
            cp16(sa + swoff[it], abase + (size_t)it * 32 * K3 + chunk * G2K);
            cp16(sbo + swoff[it], bbase + (size_t)it * 32 * K3 + chunk * G2K);
        }
        cp_commit();
    };

    int ph[3] = {0, 0, 0};
    stage_chunk(0, 0);
    stage_chunk(1, 1);

    for (int c = 0; c < NC; c++) {
        const int b = c % 3;
        if (c + 2 < NC) {
            const int nb = (c + 2) % 3;
            if (c >= 1) { MBARRIER_WAIT_PARITY(mb[nb], ph[nb]); ph[nb] ^= 1; }
            stage_chunk(c + 2, nb);
            cp_wait<2>();
        } else if (c + 1 < NC) {
            cp_wait<1>();
        } else {
            cp_wait<0>();
        }
        __syncthreads();
        if (wid == 0 && elect_one_pred()) {
            FENCE_PROXY_ASYNC();
            const uint32_t sa = smb + 1024u + (uint32_t)b * 65536u;
            const uint64_t ad = MAKE_SMEM_DESC(sa);
            const uint64_t bd = MAKE_SMEM_DESC(sa + 32768u);
            #pragma unroll
            for (int ks = 0; ks < 4; ks++) {
                const uint32_t en = (c > 0 || ks > 0) ? 1u : 0u;
                mma_bf16_ss(tmem,       ad + ks * 2,        bd + ks * 2, IDESC2, en);
                mma_bf16_ss(tmem + 256, ad + 1024 + ks * 2, bd + ks * 2, IDESC2, en);
            }
            TCGEN05_COMMIT(mb[b]);
        }
    }
    MBARRIER_WAIT_PARITY(mb[(NC - 1) % 3], ph[(NC - 1) % 3]);
    TCGEN05_FENCE_AFTER();

    {
        const int mh = wid >> 2;
        const int w4 = wid & 3;
        const uint32_t lofs = (uint32_t)w4 << 21;
        const int row = m0 + mh * 128 + w4 * 32 + lane;
        #pragma unroll
        for (int j = 0; j < 8; j++) {
            uint32_t r[32];
            TCGEN05_LD_32X32B_X32(r, tmem + mh * 256 + j * 32 + lofs);
            TCGEN05_WAIT_LD();
            const float* bp = bias ? (bias + n0 + j * 32) : nullptr;
            if (out3) {
                __nv_bfloat16* op = out3 + (size_t)row * 3 * N + n0 + j * 32;
                #pragma unroll
                for (int q = 0; q < 32; q += 2) {
                    float v0 = __uint_as_float(r[q + 0]) * alpha;
                    float v1 = __uint_as_float(r[q + 1]) * alpha;
                    if (bp) { v0 += bp[q]; v1 += bp[q + 1]; }
                    if (do_relu) { v0 = fmaxf(v0, 0.f); v1 = fmaxf(v1, 0.f); }
                    store_split3(op + q, N, v0, v1);
                }
            } else {
                float* cp = C + (size_t)row * N + n0 + j * 32;
                #pragma unroll
                for (int q = 0; q < 32; q += 4) {
                    float v0 = __uint_as_float(r[q + 0]) * alpha;
                    float v1 = __uint_as_float(r[q + 1]) * alpha;
                    float v2 = __uint_as_float(r[q + 2]) * alpha;
                    float v3 = __uint_as_float(r[q + 3]) * alpha;
                    if (bp) { v0 += bp[q]; v1 += bp[q + 1]; v2 += bp[q + 2]; v3 += bp[q + 3]; }
                    if (do_relu) {
                        v0 = fmaxf(v0, 0.f); v1 = fmaxf(v1, 0.f);
                        v2 = fmaxf(v2, 0.f); v3 = fmaxf(v3, 0.f);
                    }
                    float4 o = {v0, v1, v2, v3};
                    *reinterpret_cast<float4*>(cp + q) = o;
                }
            }
        }
        TCGEN05_FENCE_BEFORE();
    }
    __syncthreads();
    if (tid == 0) { MBARRIER_INVAL(mb[0]); MBARRIER_INVAL(mb[1]); MBARRIER_INVAL(mb[2]); }
    __syncthreads();
    if (wid == 0) TCGEN05_DEALLOC(tmem, 512);
#else
    extern __shared__ uint32_t sm[];
    const uint32_t smb = smem_u32(sm);
    #pragma unroll
    for (int qm = 0; qm < 2; qm++)
        for (int qn = 0; qn < 2; qn++) {
            legacy_tile128(A3, B3, bias, C, out3, N, K3, alpha, do_relu,
                           blockIdx.x * 256 + qm * 128,
                           blockIdx.y * 256 + qn * 128, sm, smb);
            __syncthreads();
        }
#endif
}

// ---------------------------------------------------------------------------
// 256x256 tf32 GEMM (logits only). A, B are RNA-tf32-rounded fp32.
// C = A[M,K] @ B[N,K]^T.  Same staging geometry as gemm256 (128B rows, SW128),
// chunk = 32 fp32, K_per_mma = 8.
// ---------------------------------------------------------------------------
__global__ __launch_bounds__(256, 1) void gemm256tf_kernel(
    const float* __restrict__ A, const float* __restrict__ Bm,
    float* __restrict__ C, int M, int N, int K)
{
#if TC_PATH
    extern __shared__ char smc[];
    const uint32_t smb = smem_u32(smc);
    const int tid = threadIdx.x;
    const int wid = tid >> 5, lane = tid & 31;
    const int m0 = blockIdx.x * 256;
    const int n0 = blockIdx.y * 256;

    const uint32_t mb[3] = {smb + 8u, smb + 16u, smb + 24u};

    if (wid == 0) TCGEN05_ALLOC(smb, 512);
    if (tid == 0) { MBARRIER_INIT(mb[0], 1); MBARRIER_INIT(mb[1], 1); MBARRIER_INIT(mb[2], 1); }
    __syncthreads();
    uint32_t tmem;
    asm volatile("ld.shared.b32 %0, [%1];" : "=r"(tmem) : "r"(smb));
    if (wid == 0) TCGEN05_RELINQUISH();

    // kind::tf32 idesc: d=F32(1), a=b=TF32(2), N=256, M=128
    const uint32_t IDESCT =
        (1u << 4) | (2u << 7) | (2u << 10) | ((256 / 8) << 17) | ((128 / 16) << 24);

    const int NC = K / 32;              // 32 fp32 per 128B row chunk
    const int r0s = tid >> 3;
    const int c8 = tid & 7;
    const float* abase = A + (size_t)(m0 + r0s) * K + c8 * 4;
    const float* bbase = Bm + (size_t)(n0 + r0s) * K + c8 * 4;
    uint32_t swoff[8];
    #pragma unroll
    for (int it = 0; it < 8; it++)
        swoff[it] = SMEM_SWIZZLE_128B((uint32_t)((r0s + it * 32) * 128 + c8 * 16));

    auto stage_chunk = [&](int chunk, int buf) {
        const uint32_t sa = smb + 1024u + (uint32_t)buf * 65536u;
        const uint32_t sbo = sa + 32768u;
        #pragma unroll
        for (int it = 0; it < 8; it++) {
            cp16(sa + swoff[it], abase + (size_t)it * 32 * K + chunk * 32);
            cp16(sbo + swoff[it], bbase + (size_t)it * 32 * K + chunk * 32);
        }
        cp_commit();
    };

    int ph[3] = {0, 0, 0};
    stage_chunk(0, 0);
    stage_chunk(1, 1);

    for (int c = 0; c < NC; c++) {
        const int b = c % 3;
        if (c + 2 < NC) {
            const int nb = (c + 2) % 3;
            if (c >= 1) { MBARRIER_WAIT_PARITY(mb[nb], ph[nb]); ph[nb] ^= 1; }
            stage_chunk(c + 2, nb);
            cp_wait<2>();
        } else if (c + 1 < NC) {
            cp_wait<1>();
        } else {
            cp_wait<0>();
        }
        __syncthreads();
        if (wid == 0 && elect_one_pred()) {
            FENCE_PROXY_ASYNC();
            const uint32_t sa = smb + 1024u + (uint32_t)b * 65536u;
            const uint64_t ad = MAKE_SMEM_DESC(sa);
            const uint64_t bd = MAKE_SMEM_DESC(sa + 32768u);
            #pragma unroll
            for (int ks = 0; ks < 4; ks++) {      // 4 x K8 = 32 elems
                const uint32_t en = (c > 0 || ks > 0) ? 1u : 0u;
                mma_tf32_ss(tmem,       ad + ks * 2,        bd + ks * 2, IDESCT, en);
                mma_tf32_ss(tmem + 256, ad + 1024 + ks * 2, bd + ks * 2, IDESCT, en);
            }
            TCGEN05_COMMIT(mb[b]);
        }
    }
    MBARRIER_WAIT_PARITY(mb[(NC - 1) % 3], ph[(NC - 1) % 3]);
    TCGEN05_FENCE_AFTER();

    {
        const int mh = wid >> 2;
        const int w4 = wid & 3;
        const uint32_t lofs = (uint32_t)w4 << 21;
        const int row = m0 + mh * 128 + w4 * 32 + lane;
        #pragma unroll
        for (int j = 0; j < 8; j++) {
            uint32_t r[32];
            TCGEN05_LD_32X32B_X32(r, tmem + mh * 256 + j * 32 + lofs);
            TCGEN05_WAIT_LD();
            float* cp = C + (size_t)row * N + n0 + j * 32;
            #pragma unroll
            for (int q = 0; q < 32; q += 4) {
                float4 o;
                o.x = __uint_as_float(r[q + 0]);
                o.y = __uint_as_float(r[q + 1]);
                o.z = __uint_as_float(r[q + 2]);
                o.w = __uint_as_float(r[q + 3]);
                *reinterpret_cast<float4*>(cp + q) = o;
            }
        }
        TCGEN05_FENCE_BEFORE();
    }
    __syncthreads();
    if (tid == 0) { MBARRIER_INVAL(mb[0]); MBARRIER_INVAL(mb[1]); MBARRIER_INVAL(mb[2]); }
    __syncthreads();
    if (wid == 0) TCGEN05_DEALLOC(tmem, 512);
#else
    // correctness-only fallback (never executes on sm_103a; operands pre-rounded)
    const int m0 = blockIdx.x * 256;
    const int n0 = blockIdx.y * 256;
    for (int idx = threadIdx.x; idx < 256 * 256; idx += 256) {
        const int i = idx >> 8, j = idx & 255;
        const float* a = A + (size_t)(m0 + i) * K;
        const float* b = Bm + (size_t)(n0 + j) * K;
        float s = 0.f;
        for (int k = 0; k < K; k++) s += a[k] * b[k];
        C[(size_t)(m0 + i) * N + n0 + j] = s;
    }
#endif
}

// ---------------------------------------------------------------------------
// Tensor-core split-bf16 causal flash attention (fused-QKV input, stride QKVS)
// ---------------------------------------------------------------------------
#define AT_STRIDE 136
#define ATT_SMEM  (3 * 64 * AT_STRIDE * 2)   // 52224 B

__global__ __launch_bounds__(128, 3) void attn_mma_kernel(
    const float* __restrict__ Q, const float* __restrict__ Kg,
    const float* __restrict__ Vg, __nv_bfloat16* __restrict__ conc3)
{
    extern __shared__ __nv_bfloat16 sh[];
    __nv_bfloat16* Qs = sh;
    __nv_bfloat16* Ks = sh + 64 * AT_STRIDE;
    __nv_bfloat16* Vs = sh + 128 * AT_STRIDE;

    const int qt = blockIdx.x;
    const int bh = blockIdx.y;
    const int b = bh >> 4, n = bh & 15;
    const int tid = threadIdx.x;
    const int wid = tid >> 5, lane = tid & 31;
    const int g = lane >> 2, c4 = lane & 3;

    {
        const int r = tid >> 1;
        const int dbase = (tid & 1) * 32;
        const float* qp = Q + ((size_t)(b * S_ + qt * 64 + r)) * QKVS + n * 64 + dbase;
        #pragma unroll
        for (int i = 0; i < 32; i += 4) {
            float4 f = *reinterpret_cast<const float4*>(qp + i);
            float vals[4] = {f.x, f.y, f.z, f.w};
            #pragma unroll
            for (int e = 0; e < 4; e++) {
                __nv_bfloat16 hi = __float2bfloat16_rn(vals[e]);
                Qs[r * AT_STRIDE + dbase + i + e] = hi;
                Qs[r * AT_STRIDE + 64 + dbase + i + e] =
                    __float2bfloat16_rn(vals[e] - __bfloat162float(hi));
            }
        }
    }

    const int row0 = wid * 16 + g;
    float m0 = -1e30f, m1 = -1e30f, l0 = 0.f, l1 = 0.f;
    float o[8][4];
    #pragma unroll
    for (int j = 0; j < 8; j++)
        #pragma unroll
        for (int q = 0; q < 4; q++) o[j][q] = 0.f;

    for (int kt = 0; kt <= qt; kt++) {
        __syncthreads();
        {
            const int r = tid >> 1;
            const int dbase = (tid & 1) * 32;
            const float* kp = Kg + ((size_t)(b * S_ + kt * 64 + r)) * QKVS + n * 64 + dbase;
            const float* vp = Vg + ((size_t)(b * S_ + kt * 64 + r)) * QKVS + n * 64 + dbase;
            #pragma unroll
            for (int i = 0; i < 32; i += 4) {
                float4 fk = *reinterpret_cast<const float4*>(kp + i);
                float4 fv = *reinterpret_cast<const float4*>(vp + i);
                float kv[4] = {fk.x, fk.y, fk.z, fk.w};
                float vv[4] = {fv.x, fv.y, fv.z, fv.w};
                #pragma unroll
                for (int e = 0; e < 4; e++) {
                    const int d = dbase + i + e;
                    __nv_bfloat16 kh = __float2bfloat16_rn(kv[e]);
                    Ks[r * AT_STRIDE + d] = kh;
                    Ks[r * AT_STRIDE + 64 + d] =
                        __float2bfloat16_rn(kv[e] - __bfloat162float(kh));
                    __nv_bfloat16 vh = __float2bfloat16_rn(vv[e]);
                    Vs[d * AT_STRIDE + r] = vh;
                    Vs[d * AT_STRIDE + 64 + r] =
                        __float2bfloat16_rn(vv[e] - __bfloat162float(vh));
                }
            }
        }
        __syncthreads();

        float s[8][4];
        #pragma unroll
        for (int j = 0; j < 8; j++)
            #pragma unroll
            for (int q = 0; q < 4; q++) s[j][q] = 0.f;

        #pragma unroll
        for (int phs = 0; phs < 3; phs++) {
            const int aoff = (phs == 1) ? 64 : 0;
            const int boff = (phs == 2) ? 64 : 0;
            #pragma unroll
            for (int ks = 0; ks < 4; ks++) {
                uint32_t a[4];
                const __nv_bfloat16* ap = Qs + row0 * AT_STRIDE + aoff + ks * 16 + c4 * 2;
                a[0] = *reinterpret_cast<const uint32_t*>(ap);
                a[1] = *reinterpret_cast<const uint32_t*>(ap + 8 * AT_STRIDE);
                a[2] = *reinterpret_cast<const uint32_t*>(ap + 8);
                a[3] = *reinterpret_cast<const uint32_t*>(ap + 8 * AT_STRIDE + 8);
                #pragma unroll
                for (int j = 0; j < 8; j++) {
                    uint32_t bf[2];
                    const __nv_bfloat16* bp =
                        Ks + (8 * j + g) * AT_STRIDE + boff + ks * 16 + c4 * 2;
                    bf[0] = *reinterpret_cast<const uint32_t*>(bp);
                    bf[1] = *reinterpret_cast<const uint32_t*>(bp + 8);
                    mma16(s[j], a, bf);
                }
            }
        }

        if (kt == qt) {
            #pragma unroll
            for (int j = 0; j < 8; j++) {
                const int colb = 8 * j + 2 * c4;
                if (colb     > row0)     s[j][0] = -1e30f;
                if (colb + 1 > row0)     s[j][1] = -1e30f;
                if (colb     > row0 + 8) s[j][2] = -1e30f;
                if (colb + 1 > row0 + 8) s[j][3] = -1e30f;
            }
        }

        float rm0 = -1e30f, rm1 = -1e30f;
        #pragma unroll
        for (int j = 0; j < 8; j++) {
            rm0 = fmaxf(rm0, fmaxf(s[j][0], s[j][1]));
            rm1 = fmaxf(rm1, fmaxf(s[j][2], s[j][3]));
        }
        rm0 = fmaxf(rm0, __shfl_xor_sync(0xFFFFFFFFu, rm0, 1));
        rm0 = fmaxf(rm0, __shfl_xor_sync(0xFFFFFFFFu, rm0, 2));
        rm1 = fmaxf(rm1, __shfl_xor_sync(0xFFFFFFFFu, rm1, 1));
        rm1 = fmaxf(rm1, __shfl_xor_sync(0xFFFFFFFFu, rm1, 2));
        const float mn0 = fmaxf(m0, rm0), mn1 = fmaxf(m1, rm1);
        const float cr0 = __expf(m0 - mn0), cr1 = __expf(m1 - mn1);
        m0 = mn0; m1 = mn1;

        float ps0 = 0.f, ps1 = 0.f;
        uint32_t phi[8][2], plo[8][2];
        #pragma unroll
        for (int j = 0; j < 8; j++) {
            float p0 = __expf(s[j][0] - mn0);
            float p1 = __expf(s[j][1] - mn0);
            float p2 = __expf(s[j][2] - mn1);
            float p3 = __expf(s[j][3] - mn1);
            ps0 += p0 + p1; ps1 += p2 + p3;
            __nv_bfloat16 h0 = __float2bfloat16_rn(p0), h1 = __float2bfloat16_rn(p1);
            __nv_bfloat16 h2 = __float2bfloat16_rn(p2), h3 = __float2bfloat16_rn(p3);
            phi[j][0] = pack_raw(h0, h1);
            phi[j][1] = pack_raw(h2, h3);
            plo[j][0] = pack_bf16x2(p0 - __bfloat162float(h0), p1 - __bfloat162float(h1));
            plo[j][1] = pack_bf16x2(p2 - __bfloat162float(h2), p3 - __bfloat162float(h3));
        }
        ps0 += __shfl_xor_sync(0xFFFFFFFFu, ps0, 1);
        ps0 += __shfl_xor_sync(0xFFFFFFFFu, ps0, 2);
        ps1 += __shfl_xor_sync(0xFFFFFFFFu, ps1, 1);
        ps1 += __shfl_xor_sync(0xFFFFFFFFu, ps1, 2);
        l0 = l0 * cr0 + ps0;
        l1 = l1 * cr1 + ps1;
        #pragma unroll
        for (int j = 0; j < 8; j++) {
            o[j][0] *= cr0; o[j][1] *= cr0;
            o[j][2] *= cr1; o[j][3] *= cr1;
        }

        #pragma unroll
        for (int phs = 0; phs < 3; phs++) {
            const int voff = (phs == 2) ? 64 : 0;
            #pragma unroll
            for (int ks = 0; ks < 4; ks++) {
                uint32_t a[4];
                if (phs == 1) {
                    a[0] = plo[2 * ks][0]; a[1] = plo[2 * ks][1];
                    a[2] = plo[2 * ks + 1][0]; a[3] = plo[2 * ks + 1][1];
                } else {
                    a[0] = phi[2 * ks][0]; a[1] = phi[2 * ks][1];
                    a[2] = phi[2 * ks + 1][0]; a[3] = phi[2 * ks + 1][1];
                }
                #pragma unroll
                for (int j = 0; j < 8; j++) {
                    uint32_t bf[2];
                    const __nv_bfloat16* bp =
                        Vs + (8 * j + g) * AT_STRIDE + voff + ks * 16 + c4 * 2;
                    bf[0] = *reinterpret_cast<const uint32_t*>(bp);
                    bf[1] = *reinterpret_cast<const uint32_t*>(bp + 8);
                    mma16(o[j], a, bf);
                }
            }
        }
    }

    const float inv0 = 1.f / l0, inv1 = 1.f / l1;
    const size_t r0 = (size_t)(b * S_ + qt * 64 + row0);
    __nv_bfloat16* o0 = conc3 + r0 * 3 * H_;
    __nv_bfloat16* o1 = conc3 + (r0 + 8) * 3 * H_;
    #pragma unroll
    for (int j = 0; j < 8; j++) {
        const int col = n * 64 + 8 * j + 2 * c4;
        store_split3(o0 + col, H_, o[j][0] * inv0, o[j][1] * inv0);
        store_split3(o1 + col, H_, o[j][2] * inv1, o[j][3] * inv1);
    }
}

// ---------------------------------------------------------------------------
// Split conversion / transpose / elementwise kernels
// ---------------------------------------------------------------------------
__global__ void conv_act_kernel(const float* __restrict__ in,
                                __nv_bfloat16* __restrict__ out,
                                int M, int K)
{
    int idx = blockIdx.x * blockDim.x + threadIdx.x;
    if (idx >= M * K) return;
    int row = idx / K;
    int k = idx - row * K;
    float x = in[idx];
    __nv_bfloat16 hi = __float2bfloat16_rn(x);
    __nv_bfloat16 lo = __float2bfloat16_rn(x - __bfloat162float(hi));
    size_t base = (size_t)row * 3 * K;
    out[base + k] = hi;
    out[base + K + k] = lo;
    out[base + 2 * K + k] = hi;
}

__global__ __launch_bounds__(256) void conv_wT_kernel(
    const float* __restrict__ W, __nv_bfloat16* __restrict__ out,
    int K, int N, float wscale)
{
    __shared__ float tile[32][33];
    const int tx = threadIdx.x & 31;
    const int ty = threadIdx.x >> 5;
    const int n0 = blockIdx.x * 32;
    const int k0 = blockIdx.y * 32;
    #pragma unroll
    for (int i = 0; i < 4; i++)
        tile[ty + i * 8][tx] = W[(size_t)(k0 + ty + i * 8) * N + n0 + tx];
    __syncthreads();
    #pragma unroll
    for (int i = 0; i < 4; i++) {
        const int nn = n0 + ty + i * 8;
        const int k = k0 + tx;
        float x = tile[tx][ty + i * 8] * wscale;
        __nv_bfloat16 hi = __float2bfloat16_rn(x);
        __nv_bfloat16 lo = __float2bfloat16_rn(x - __bfloat162float(hi));
        size_t base = (size_t)nn * 3 * K;
        out[base + k] = hi;
        out[base + K + k] = hi;
        out[base + 2 * K + k] = lo;
    }
}

// transpose + RNA-tf32-round to fp32 (for p_decoder)
__global__ __launch_bounds__(256) void conv_wTf32_kernel(
    const float* __restrict__ W, float* __restrict__ out, int K, int N)
{
    __shared__ float tile[32][33];
    const int tx = threadIdx.x & 31;
    const int ty = threadIdx.x >> 5;
    const int n0 = blockIdx.x * 32;
    const int k0 = blockIdx.y * 32;
    #pragma unroll
    for (int i = 0; i < 4; i++)
        tile[ty + i * 8][tx] = W[(size_t)(k0 + ty + i * 8) * N + n0 + tx];
    __syncthreads();
    #pragma unroll
    for (int i = 0; i < 4; i++) {
        const int nn = n0 + ty + i * 8;
        out[(size_t)nn * K + k0 + tx] = rna_tf32(tile[tx][ty + i * 8]);
    }
}

__global__ void gather_kernel(const int* __restrict__ x,
                              const float* __restrict__ emb,
                              float* __restrict__ out)
{
    int idx = blockIdx.x * blockDim.x + threadIdx.x;
    if (idx >= M4 * E_) return;
    int i = idx / E_;
    int e = idx - i * E_;
    out[idx] = emb[(size_t)x[i] * E_ + e];
}

__global__ void addpos_kernel(const float* __restrict__ xemb,
                              const float* __restrict__ pos11,
                              float* __restrict__ out,
                              __nv_bfloat16* __restrict__ out3)
{
    int idx = blockIdx.x * blockDim.x + threadIdx.x;
    if (idx >= M4 * H_) return;
    int i = idx / H_;
    int h = idx - i * H_;
    int s = i & (S_ - 1);
    float y = xemb[idx] + pos11[(size_t)s * H_ + h];
    out[idx] = y;
    __nv_bfloat16 hi = __float2bfloat16_rn(y);
    __nv_bfloat16 lo = __float2bfloat16_rn(y - __bfloat162float(hi));
    size_t base = (size_t)i * 3 * H_;
    out3[base + h] = hi;
    out3[base + H_ + h] = lo;
    out3[base + 2 * H_ + h] = hi;
}

__global__ __launch_bounds__(256) void ln_res_kernel(
    const float* __restrict__ res, const float* __restrict__ x,
    const float* __restrict__ bias, const float* __restrict__ scale,
    float* __restrict__ out, __nv_bfloat16* __restrict__ out3,
    int round_out)
{
    __shared__ float red[256];
    const int row = blockIdx.x;
    const int t = threadIdx.x;
    const float* xr = x + (size_t)row * H_;

    float lsum = 0.f;
    for (int i = t; i < H_; i += 256) lsum += xr[i];
    red[t] = lsum; __syncthreads();
    for (int s = 128; s > 0; s >>= 1) { if (t < s) red[t] += red[t + s]; __syncthreads(); }
    const float mean = red[0] * (1.0f / H_);
    __syncthreads();

    float lvar = 0.f;
    for (int i = t; i < H_; i += 256) { float d = xr[i] - mean; lvar += d * d; }
    red[t] = lvar; __syncthreads();
    for (int s = 128; s > 0; s >>= 1) { if (t < s) red[t] += red[t + s]; __syncthreads(); }
    const float rstd = rsqrtf(red[0] * (1.0f / H_) + 1e-6f);

    for (int i = t; i < H_; i += 256) {
        float y = res[(size_t)row * H_ + i] + (xr[i] - mean) * rstd * scale[i] + bias[i];
        out[(size_t)row * H_ + i] = round_out ? rna_tf32(y) : y;
        if (out3) {
            __nv_bfloat16 hi = __float2bfloat16_rn(y);
            __nv_bfloat16 lo = __float2bfloat16_rn(y - __bfloat162float(hi));
            size_t base = (size_t)row * 3 * H_;
            out3[base + i] = hi;
            out3[base + H_ + i] = lo;
            out3[base + 2 * H_ + i] = hi;
        }
    }
}

// ---------------------------------------------------------------------------
// Launch helpers
// ---------------------------------------------------------------------------
static inline void run_gemm(const __nv_bfloat16* A3, const __nv_bfloat16* B3,
                            const float* bias, float* C, __nv_bfloat16* out3,
                            int M, int N, int K3, float alpha, int relu)
{
    dim3 grid(M / GBM, N / GBN);
    gemm_bf16_kernel<<<grid, 256, GEMM_SMEM_BYTES>>>(A3, B3, bias, C, out3,
                                                     M, N, K3, alpha, relu);
}
static inline void run_gemm256(const __nv_bfloat16* A3, const __nv_bfloat16* B3,
                               const float* bias, float* C, __nv_bfloat16* out3,
                               int M, int N, int K3, float alpha, int relu)
{
    dim3 grid(M / 256, N / 256);
    gemm256_kernel<<<grid, 256, G2_SMEM>>>(A3, B3, bias, C, out3,
                                           M, N, K3, alpha, relu);
}
static inline void run_gemm256tf(const float* A, const float* Bm, float* C,
                                 int M, int N, int K)
{
    dim3 grid(M / 256, N / 256);
    gemm256tf_kernel<<<grid, 256, G2_SMEM>>>(A, Bm, C, M, N, K);
}
static inline void run_conv_wT(const float* W, __nv_bfloat16* out,
                               int K, int N, float wscale)
{
    dim3 grid(N / 32, K / 32);
    conv_wT_kernel<<<grid, 256>>>(W, out, K, N, wscale);
}

extern "C" void kernel_launch(void* const* d_in, const int* in_sizes, int n_in,
                              void* d_out, int out_size)
{
    const int*   x            = (const int*)  d_in[0];
    const float* emb_decode   = (const float*)d_in[1];
    const float* W_dec_lin    = (const float*)d_in[2];
    const float* p_decoder    = (const float*)d_in[3];
    const float* x_emb_pos    = (const float*)d_in[4];
    const float* p_d_q        = (const float*)d_in[5];
    const float* p_d_k        = (const float*)d_in[6];
    const float* p_d_v        = (const float*)d_in[7];
    const float* p_d_c        = (const float*)d_in[8];
    const float* p_d_ff1      = (const float*)d_in[9];
    const float* p_d_ff2      = (const float*)d_in[10];
    const float* b_d_ff1      = (const float*)d_in[11];
    const float* b_d_ff2      = (const float*)d_in[12];
    const float* d_o_bias     = (const float*)d_in[13];
    const float* d_o_scale    = (const float*)d_in[14];
    const float* b_d_bias_1   = (const float*)d_in[15];
    const float* b_d_bias_2   = (const float*)d_in[16];
    const float* b_d_scale_1  = (const float*)d_in[17];
    const float* b_d_scale_2  = (const float*)d_in[18];
    float* out = (float*)d_out;

    const int m = L_ - 1;   // only the last layer's result is observable

    cudaFuncSetAttribute(gemm_bf16_kernel,
                         cudaFuncAttributeMaxDynamicSharedMemorySize, GEMM_SMEM_BYTES);
    cudaFuncSetAttribute(gemm256_kernel,
                         cudaFuncAttributeMaxDynamicSharedMemorySize, G2_SMEM);
    cudaFuncSetAttribute(gemm256tf_kernel,
                         cudaFuncAttributeMaxDynamicSharedMemorySize, G2_SMEM);
    cudaFuncSetAttribute(attn_mma_kernel,
                         cudaFuncAttributeMaxDynamicSharedMemorySize, ATT_SMEM);

    float *Aemb, *xemb, *layerin, *qkv, *xmulti, *xself,
          *ffw1, *ffw2, *xffw, *decout, *wtp;
    __nv_bfloat16 *a3_emb, *a3_li, *a3_conc, *a3_self, *a3_ffw1;
    __nv_bfloat16 *w3_dec, *w3_qkv, *w3_c, *w3_ff1, *w3_ff2;
    cudaGetSymbolAddress((void**)&Aemb,    g_Aemb);
    cudaGetSymbolAddress((void**)&xemb,    g_xemb);
    cudaGetSymbolAddress((void**)&layerin, g_layerin);
    cudaGetSymbolAddress((void**)&qkv,     g_qkv);
    cudaGetSymbolAddress((void**)&xmulti,  g_xmulti);
    cudaGetSymbolAddress((void**)&xself,   g_xself);
    cudaGetSymbolAddress((void**)&ffw1,    g_ffw1);
    cudaGetSymbolAddress((void**)&ffw2,    g_ffw2);
    cudaGetSymbolAddress((void**)&xffw,    g_xffw);
    cudaGetSymbolAddress((void**)&decout,  g_decout);
    cudaGetSymbolAddress((void**)&wtp,     g_wtp);
    cudaGetSymbolAddress((void**)&a3_emb,  g_a3_emb);
    cudaGetSymbolAddress((void**)&a3_li,   g_a3_li);
    cudaGetSymbolAddress((void**)&a3_conc, g_a3_conc);
    cudaGetSymbolAddress((void**)&a3_self, g_a3_self);
    cudaGetSymbolAddress((void**)&a3_ffw1, g_a3_ffw1);
    cudaGetSymbolAddress((void**)&w3_dec,  g_w3_dec);
    cudaGetSymbolAddress((void**)&w3_qkv,  g_w3_qkv);
    cudaGetSymbolAddress((void**)&w3_c,    g_w3_c);
    cudaGetSymbolAddress((void**)&w3_ff1,  g_w3_ff1);
    cudaGetSymbolAddress((void**)&w3_ff2,  g_w3_ff2);

    // weight conversions; Q weights pre-scaled by 1/sqrt(head)
    run_conv_wT(W_dec_lin, w3_dec, E_, H_, 1.f);
    run_conv_wT(p_d_q + (size_t)m * H_ * H_, w3_qkv, H_, H_, 0.125f);
    run_conv_wT(p_d_k + (size_t)m * H_ * H_, w3_qkv + (size_t)1024 * 3 * H_, H_, H_, 1.f);
    run_conv_wT(p_d_v + (size_t)m * H_ * H_, w3_qkv + (size_t)2048 * 3 * H_, H_, H_, 1.f);
    run_conv_wT(p_d_c + (size_t)m * H_ * H_, w3_c, H_, H_, 1.f);
    run_conv_wT(p_d_ff1 + (size_t)m * H_ * FF_, w3_ff1, H_, FF_, 1.f);
    run_conv_wT(p_d_ff2 + (size_t)m * FF_ * H_, w3_ff2, FF_, H_, 1.f);
    {   // p_decoder -> transposed RNA-rounded fp32
        dim3 grid(V_ / 32, H_ / 32);
        conv_wTf32_kernel<<<grid, 256>>>(p_decoder, wtp, H_, V_);
    }

    // 1. gather embeddings + split
    gather_kernel<<<(M4 * E_ + 255) / 256, 256>>>(x, emb_decode, Aemb);
    conv_act_kernel<<<(M4 * E_ + 255) / 256, 256>>>(Aemb, a3_emb, M4, E_);

    // 2. x_dec_embed = A_emb @ W_dec_lin
    run_gemm(a3_emb, w3_dec, nullptr, xemb, nullptr, M4, H_, 3 * E_, 1.f, 0);

    // 3. layer_in = pos[11] + x_dec_embed  (+ fused split)
    addpos_kernel<<<(M4 * H_ + 255) / 256, 256>>>(
        xemb, x_emb_pos + (size_t)m * S_ * H_, layerin, a3_li);

    // 4. fused Q/K/V projection
    run_gemm256(a3_li, w3_qkv, nullptr, qkv, nullptr, M4, QKVS, 3 * H_, 1.f, 0);

    // 5. tensor-core causal attention -> a3_conc
    attn_mma_kernel<<<dim3(S_ / 64, B_ * NH_), 128, ATT_SMEM>>>(
        qkv, qkv + 1024, qkv + 2048, a3_conc);

    // 6. x_multi = conc @ p_d_c
    run_gemm(a3_conc, w3_c, nullptr, xmulti, nullptr, M4, H_, 3 * H_, 1.f, 0);

    // 7. x_self = layer_in + LN(x_multi)  (+ fused split)
    ln_res_kernel<<<M4, 256>>>(layerin, xmulti,
                               b_d_bias_1 + (size_t)m * H_,
                               b_d_scale_1 + (size_t)m * H_, xself, a3_self, 0);

    // 8. FFN
    run_gemm256(a3_self, w3_ff1, b_d_ff1 + (size_t)m * FF_, ffw1, a3_ffw1,
                M4, FF_, 3 * H_, 1.f, 1);
    run_gemm(a3_ffw1, w3_ff2, b_d_ff2 + (size_t)m * H_, ffw2, nullptr,
             M4, H_, 3 * FF_, 1.f, 0);

    // 9. x_ffw = x_self + LN(ffw2)
    ln_res_kernel<<<M4, 256>>>(xself, ffw2,
                               b_d_bias_2 + (size_t)m * H_,
                               b_d_scale_2 + (size_t)m * H_, xffw, nullptr, 0);

    // 10. dec_outputs = x_dec_embed + LN(x_ffw), RNA-tf32-rounded fp32
    ln_res_kernel<<<M4, 256>>>(xemb, xffw, d_o_bias, d_o_scale, decout, nullptr, 1);

    // 11. logits = dec_outputs @ p_decoder  (tf32 tcgen05, 4 B/elem traffic)
    run_gemm256tf(decout, wtp, out, M4, V_, H_);
}